// round 4
// baseline (speedup 1.0000x reference)
#include <cuda_runtime.h>
#include <math.h>

// Problem constants
#define NB 32
#define NS 2048
#define NE 300
#define NH 256
#define NT 24
#define NROWS (NB * NS)        // 65536
#define XN 1024                 // 4 gate cols per hidden unit j (i,o,u,f)
#define UN 1280                 // 5 gate cols per hidden unit j (i,o,u,fl,fr)
#define UK 512                  // K = [h_l | h_r]
#define HCNT 16777216           // NROWS * NH

// ---------------- device scratch (static; no runtime alloc) ----------------
__device__ float g_x[(size_t)NROWS * XN];   // 256 MiB  packed x-gates
__device__ float g_W[NE * XN];              // packed input weights
__device__ float g_bias[XN];
__device__ float g_U[UK * UN];              // packed recurrence weights
__device__ float g_h[2 * HCNT];             // ping-pong h state (fp32)
__device__ float g_c[2 * HCNT];             // ping-pong c state
__device__ int   g_winner[NROWS];           // per (b,d): step*2048+s of last writer
__device__ int   g_work[NROWS];             // compacted winner row list
__device__ int   g_cnt[32];                 // per-step winner counts

__device__ __forceinline__ float sigm(float x) { return 1.0f / (1.0f + __expf(-x)); }

// ---------------- init: zero state, reset winner/counts --------------------
__global__ void k_init() {
    size_t i = (size_t)blockIdx.x * blockDim.x + threadIdx.x;
    size_t stride = (size_t)gridDim.x * blockDim.x;
    for (size_t p = i; p < (size_t)HCNT; p += stride) { g_h[p] = 0.0f; g_c[p] = 0.0f; }
    for (size_t p = i; p < (size_t)NROWS; p += stride) g_winner[p] = -1;
    if (i < 32) g_cnt[i] = 0;
}

// ---------------- pack input weights: g_W[k][j*4+g] ------------------------
__global__ void k_pack_w(const float* __restrict__ W_iou, const float* __restrict__ b_iou,
                         const float* __restrict__ W_f,   const float* __restrict__ b_f) {
    int idx = blockIdx.x * blockDim.x + threadIdx.x;
    if (idx < NE * XN) {
        int k = idx >> 10, n = idx & 1023, j = n >> 2, g = n & 3;
        g_W[idx] = (g < 3) ? W_iou[k * 768 + g * 256 + j] : W_f[k * 256 + j];
    }
    if (idx < XN) {
        int j = idx >> 2, g = idx & 3;
        g_bias[idx] = (g < 3) ? b_iou[g * 256 + j] : b_f[j];
    }
}

// ---------------- pack recurrence weights: g_U[k][j*5+g] -------------------
__global__ void k_pack_u(const float* __restrict__ Ul, const float* __restrict__ Ur,
                         const float* __restrict__ Fll, const float* __restrict__ Flr,
                         const float* __restrict__ Frl, const float* __restrict__ Frr) {
    int idx = blockIdx.x * blockDim.x + threadIdx.x;
    if (idx >= UK * UN) return;
    int k = idx / UN, n = idx % UN, j = n / 5, g = n - 5 * j;
    float v;
    if (k < 256) {
        v = (g == 0) ? Ul[k * 768 + j]
          : (g == 1) ? Ul[k * 768 + 256 + j]
          : (g == 2) ? Ul[k * 768 + 512 + j]
          : (g == 3) ? Fll[k * 256 + j]
                     : Frl[k * 256 + j];
    } else {
        int kk = k - 256;
        v = (g == 0) ? Ur[kk * 768 + j]
          : (g == 1) ? Ur[kk * 768 + 256 + j]
          : (g == 2) ? Ur[kk * 768 + 512 + j]
          : (g == 3) ? Flr[kk * 256 + j]
                     : Frr[kk * 256 + j];
    }
    g_U[idx] = v;
}

// ---------------- input-projection GEMM: g_x = X @ g_W + bias --------------
// BM=32 rows, BN=128 cols (32 j * 4 gates), K=300 in chunks of 32.
__global__ __launch_bounds__(256) void k_xgemm(const float* __restrict__ X) {
    __shared__ float As[32][32];
    __shared__ __align__(16) float Bs[32][128];
    int tid = threadIdx.x;
    int m0 = blockIdx.x * 32;
    int j0 = blockIdx.y * 32;
    int w = tid >> 5, lane = tid & 31;

    float acc[4][4];
#pragma unroll
    for (int i = 0; i < 4; i++)
#pragma unroll
        for (int g = 0; g < 4; g++) acc[i][g] = 0.0f;

    for (int kc = 0; kc < 10; kc++) {
        int bk = kc * 32;
#pragma unroll
        for (int i = 0; i < 4; i++) {
            int r = w + i * 8;
            int k = bk + lane;
            As[r][lane] = (k < NE) ? X[(size_t)(m0 + r) * NE + k] : 0.0f;
        }
        {
            int kk = tid >> 3, grp = tid & 7;
            int k = bk + kk;
            float4* dst = (float4*)&Bs[kk][grp * 16];
            if (k < NE) {
                const float4* src = (const float4*)&g_W[(size_t)k * XN + j0 * 4 + grp * 16];
#pragma unroll
                for (int i = 0; i < 4; i++) dst[i] = src[i];
            } else {
                float4 z = make_float4(0.f, 0.f, 0.f, 0.f);
#pragma unroll
                for (int i = 0; i < 4; i++) dst[i] = z;
            }
        }
        __syncthreads();
#pragma unroll
        for (int kk = 0; kk < 32; kk++) {
            float4 b4 = *(const float4*)&Bs[kk][lane * 4];
#pragma unroll
            for (int i = 0; i < 4; i++) {
                float a = As[w + i * 8][kk];
                acc[i][0] += a * b4.x; acc[i][1] += a * b4.y;
                acc[i][2] += a * b4.z; acc[i][3] += a * b4.w;
            }
        }
        __syncthreads();
    }
    float4 bb = *(const float4*)&g_bias[(j0 + lane) * 4];
#pragma unroll
    for (int i = 0; i < 4; i++) {
        int row = m0 + w + i * 8;
        float4 o = make_float4(acc[i][0] + bb.x, acc[i][1] + bb.y,
                               acc[i][2] + bb.z, acc[i][3] + bb.w);
        *(float4*)&g_x[(size_t)row * XN + (j0 + lane) * 4] = o;
    }
}

// ---------------- winner pass: last (highest s) writer per destination -----
__global__ void k_winner(int t, const int* __restrict__ td) {
    int idx = blockIdx.x * blockDim.x + threadIdx.x;
    if (idx >= NROWS) return;
    int b = idx >> 11, s = idx & 2047;
    int d = td[b * (NT * NS) + t * NS + s];
    atomicMax(&g_winner[(b << 11) + d], t * 2048 + s);
}

__global__ void k_compact(int t, const int* __restrict__ td) {
    int idx = blockIdx.x * blockDim.x + threadIdx.x;
    if (idx >= NROWS) return;
    int b = idx >> 11, s = idx & 2047;
    int d = td[b * (NT * NS) + t * NS + s];
    if (d != 0 && g_winner[(b << 11) + d] == t * 2048 + s) {
        int p = atomicAdd(&g_cnt[t], 1);
        g_work[p] = idx;
    }
}

// ---------------- fused step: gather + GEMM + activations + scatter --------
// BM=32 winner rows, BN=160 cols (32 j * 5 gates), K=512 in chunks of 32.
__global__ __launch_bounds__(256) void k_step(
    int t, const int* __restrict__ td, const int* __restrict__ tl, const int* __restrict__ tr,
    const float* __restrict__ hcur, const float* __restrict__ ccur,
    float* __restrict__ hn, float* __restrict__ cn)
{
    __shared__ float As[32][32];
    __shared__ __align__(16) float Bs[32][160];
    __shared__ int s_offL[32], s_offR[32], s_offD[32], s_row[32];

    int count = g_cnt[t];
    int m0 = blockIdx.x * 32;
    if (m0 >= count) return;
    int tid = threadIdx.x;
    int j0 = blockIdx.y * 32;

    if (tid < 32) {
        int m = m0 + tid;
        if (m < count) {
            int idx = g_work[m];
            int b = idx >> 11, s = idx & 2047;
            int tb = b * (NT * NS) + t * NS + s;
            int d = td[tb], il = tl[tb], ir = tr[tb];
            int brow = b << 11;
            s_offL[tid] = (brow + il) << 8;
            s_offR[tid] = (brow + ir) << 8;
            s_offD[tid] = (brow + d) << 8;
            s_row[tid] = idx;
        } else {
            s_offL[tid] = 0; s_offR[tid] = 0; s_offD[tid] = -1; s_row[tid] = 0;
        }
    }
    __syncthreads();

    int w = tid >> 5, lane = tid & 31;
    float acc[4][5];
#pragma unroll
    for (int i = 0; i < 4; i++)
#pragma unroll
        for (int g = 0; g < 5; g++) acc[i][g] = 0.0f;

    for (int kc = 0; kc < 16; kc++) {
        int bk = kc * 32;
#pragma unroll
        for (int i = 0; i < 4; i++) {
            int r = w + i * 8;
            int k = bk + lane;
            int off = (k < 256) ? (s_offL[r] + k) : (s_offR[r] + k - 256);
            As[r][lane] = hcur[off];
        }
        {
            int kk = tid >> 3, grp = tid & 7;
            const float4* src = (const float4*)&g_U[(size_t)(bk + kk) * UN + j0 * 5 + grp * 20];
            float4* dst = (float4*)&Bs[kk][grp * 20];
#pragma unroll
            for (int i = 0; i < 5; i++) dst[i] = src[i];
        }
        __syncthreads();
#pragma unroll
        for (int kk = 0; kk < 32; kk++) {
            float b0 = Bs[kk][lane * 5 + 0];
            float b1 = Bs[kk][lane * 5 + 1];
            float b2 = Bs[kk][lane * 5 + 2];
            float b3 = Bs[kk][lane * 5 + 3];
            float b4 = Bs[kk][lane * 5 + 4];
#pragma unroll
            for (int i = 0; i < 4; i++) {
                float a = As[w + i * 8][kk];
                acc[i][0] += a * b0; acc[i][1] += a * b1; acc[i][2] += a * b2;
                acc[i][3] += a * b3; acc[i][4] += a * b4;
            }
        }
        __syncthreads();
    }

    int j = j0 + lane;
#pragma unroll
    for (int i = 0; i < 4; i++) {
        int r = w + i * 8;
        int offD = s_offD[r];
        if (offD < 0) continue;
        float4 xv = *(const float4*)&g_x[(size_t)s_row[r] * XN + j * 4];
        float gi = sigm(acc[i][0] + xv.x);
        float go = sigm(acc[i][1] + xv.y);
        float gu = tanhf(acc[i][2] + xv.z);
        float fl = sigm(acc[i][3] + xv.w);
        float fr = sigm(acc[i][4] + xv.w);
        float cl = ccur[s_offL[r] + j];
        float cr = ccur[s_offR[r] + j];
        float cnew = gi * gu + fl * cl + fr * cr;
        float hnew = go * tanhf(cnew);
        hn[offD + j] = hnew;
        cn[offD + j] = cnew;
    }
}

// ---------------- copy non-winner rows to next buffers; zero slot 0 --------
__global__ void k_copy(int t, const float* __restrict__ hcur, const float* __restrict__ ccur,
                       float* __restrict__ hn, float* __restrict__ cn) {
    int row = blockIdx.x;
    int j = threadIdx.x;
    int d = row & 2047;
    size_t o = ((size_t)row << 8) + j;
    if (d == 0) { hn[o] = 0.0f; cn[o] = 0.0f; return; }
    if (g_winner[row] >= t * 2048) return;   // winner wrote it in k_step
    hn[o] = hcur[o];
    cn[o] = ccur[o];
}

// ---------------- h_root: root = max(tree_ids[:, -1, :]) -------------------
__global__ void k_root(const int* __restrict__ td, const float* __restrict__ out_h,
                       float* __restrict__ out_root) {
    __shared__ int red[256];
    int b = blockIdx.x, tid = threadIdx.x;
    int v = 0;
    for (int s = tid; s < NS; s += 256) v = max(v, td[b * (NT * NS) + (NT - 1) * NS + s]);
    red[tid] = v;
    __syncthreads();
    for (int off = 128; off > 0; off >>= 1) {
        if (tid < off) red[tid] = max(red[tid], red[tid + off]);
        __syncthreads();
    }
    int root = red[0];
    out_root[b * NH + tid] = out_h[(((size_t)(b << 11)) + root) * NH + tid];
}

// ---------------- host launcher (graph-capturable) -------------------------
extern "C" void kernel_launch(void* const* d_in, const int* in_sizes, int n_in,
                              void* d_out, int out_size) {
    const float* X     = (const float*)d_in[0];
    const int*   td    = (const int*)d_in[1];   // tree_ids (destinations)
    const int*   tr    = (const int*)d_in[2];   // tree_ids_r
    const int*   tl    = (const int*)d_in[3];   // tree_ids_l
    const float* W_iou = (const float*)d_in[4];
    const float* b_iou = (const float*)d_in[5];
    const float* U_l   = (const float*)d_in[6];
    const float* U_r   = (const float*)d_in[7];
    const float* W_f   = (const float*)d_in[8];
    const float* b_f   = (const float*)d_in[9];
    const float* F_ll  = (const float*)d_in[10];
    const float* F_lr  = (const float*)d_in[11];
    const float* F_rl  = (const float*)d_in[12];
    const float* F_rr  = (const float*)d_in[13];

    float* out      = (float*)d_out;
    float* out_h    = out;                       // [B,S,H]
    float* out_c    = out + (size_t)HCNT;        // [B,S,H]
    float* out_root = out + 2 * (size_t)HCNT;    // [B,H]

    float *hb = nullptr, *cb = nullptr;
    cudaGetSymbolAddress((void**)&hb, g_h);
    cudaGetSymbolAddress((void**)&cb, g_c);

    k_init<<<4096, 256>>>();
    k_pack_w<<<(NE * XN + 255) / 256, 256>>>(W_iou, b_iou, W_f, b_f);
    k_pack_u<<<(UK * UN + 255) / 256, 256>>>(U_l, U_r, F_ll, F_lr, F_rl, F_rr);
    k_xgemm<<<dim3(NROWS / 32, 8), 256>>>(X);

    int cur = 0;
    for (int t = 0; t < NT; t++) {
        k_winner<<<NROWS / 256, 256>>>(t, td);
        k_compact<<<NROWS / 256, 256>>>(t, td);
        float* hc = hb + (size_t)cur * HCNT;
        float* cc = cb + (size_t)cur * HCNT;
        float* hn = (t == NT - 1) ? out_h : hb + (size_t)(1 - cur) * HCNT;
        float* cn = (t == NT - 1) ? out_c : cb + (size_t)(1 - cur) * HCNT;
        k_step<<<dim3(NROWS / 32, 8), 256>>>(t, td, tl, tr, hc, cc, hn, cn);
        k_copy<<<NROWS, 256>>>(t, hc, cc, hn, cn);
        cur ^= 1;
    }
    k_root<<<NB, 256>>>(td, out_h, out_root);
}

// round 7
// speedup vs baseline: 1.9411x; 1.9411x over previous
#include <cuda_runtime.h>
#include <cuda_bf16.h>
#include <math.h>
#include <stdint.h>

// ---------------- problem constants ----------------
#define NB 32
#define NS 2048
#define NE 300
#define NH 256
#define NT 24
#define NROWS 65536            // NB*NS
#define XN 1024                 // x-gates per row: j*4 + {i,o,u,f}
#define HCNT 16777216           // NROWS*NH

// ---------------- step-GEMM tiling ----------------
#define BM 128                  // rows per CTA
#define BN 80                   // 16 units * 5 gates per CTA
#define NTL 16                  // 1280 / 80 n-tiles
#define UB_CHUNK 5120           // bf16 elems per (ntile, kchunk): 4s*80n*4c*4e
#define UB_NT_STRIDE 40960      // 8 chunks
#define UB_TOTAL (NTL * UB_NT_STRIDE)   // 655360

// ---------------- dynamic smem layout (bytes) ------
#define OFF_IDX   0             // sL/sR/sD/sRow: 4 * 512
#define OFF_AH    2048          // 128 x 64 bf16 = 16384
#define OFF_AL    18432         // 16384
#define OFF_STAGE 2048          // 128 x 84 f32 = 43008 (reuses AH/AL region)
#define SMEM_DYN  45056

// ---------------- device scratch -------------------
__device__ float g_x[(size_t)NROWS * XN];     // 256 MiB packed x-gates
__device__ float g_W[NE * XN];
__device__ float g_bias[XN];
__device__ __nv_bfloat16 g_UBH[UB_TOTAL];     // U hi, fragment-native layout
__device__ __nv_bfloat16 g_UBL[UB_TOTAL];     // U lo
__device__ float g_h[2 * (size_t)HCNT];
__device__ float g_c[2 * (size_t)HCNT];
__device__ int   g_winner[NROWS];
__device__ int   g_work[NROWS];
__device__ int   g_cnt[32];

__device__ __forceinline__ float sigm(float x) { return 1.0f / (1.0f + __expf(-x)); }

__device__ __forceinline__ uint32_t smem_u32(const void* p) {
    uint32_t r;
    asm("{ .reg .u64 t; cvta.to.shared.u64 t, %1; cvt.u32.u64 %0, t; }" : "=r"(r) : "l"(p));
    return r;
}
__device__ __forceinline__ void ldsm4(uint32_t* r, uint32_t addr) {
    asm volatile("ldmatrix.sync.aligned.m8n8.x4.shared.b16 {%0,%1,%2,%3}, [%4];"
                 : "=r"(r[0]), "=r"(r[1]), "=r"(r[2]), "=r"(r[3]) : "r"(addr));
}
#define MMA(d, a, bx, by) asm volatile( \
    "mma.sync.aligned.m16n8k16.row.col.f32.bf16.bf16.f32 " \
    "{%0,%1,%2,%3},{%4,%5,%6,%7},{%8,%9},{%0,%1,%2,%3};" \
    : "+f"((d)[0]), "+f"((d)[1]), "+f"((d)[2]), "+f"((d)[3]) \
    : "r"((a)[0]), "r"((a)[1]), "r"((a)[2]), "r"((a)[3]), "r"(bx), "r"(by))

__device__ __forceinline__ uint32_t pack_hi2(float a, float b) {
    __nv_bfloat162 v = __floats2bfloat162_rn(a, b);
    return *(uint32_t*)&v;
}

// ---------------- init ----------------
__global__ void k_init() {
    size_t i = (size_t)blockIdx.x * blockDim.x + threadIdx.x;
    size_t stride = (size_t)gridDim.x * blockDim.x;
    for (size_t p = i; p < (size_t)HCNT; p += stride) { g_h[p] = 0.0f; g_c[p] = 0.0f; }
    for (size_t p = i; p < (size_t)NROWS; p += stride) g_winner[p] = -1;
    if (i < 32) g_cnt[i] = 0;
}

// ---------------- pack input weights: g_W[k][j*4+g] ----------------
__global__ void k_pack_w(const float* __restrict__ W_iou, const float* __restrict__ b_iou,
                         const float* __restrict__ W_f,   const float* __restrict__ b_f) {
    int idx = blockIdx.x * blockDim.x + threadIdx.x;
    if (idx < NE * XN) {
        int k = idx >> 10, n = idx & 1023, j = n >> 2, g = n & 3;
        g_W[idx] = (g < 3) ? W_iou[k * 768 + g * 256 + j] : W_f[k * 256 + j];
    }
    if (idx < XN) {
        int j = idx >> 2, g = idx & 3;
        g_bias[idx] = (g < 3) ? b_iou[g * 256 + j] : b_f[j];
    }
}

// ---- pack U hi/lo bf16, mma-fragment-native layout ----
// elem = ntl*40960 + ((kc*4+s)*80 + n)*16 + c*4 + e
// holds U[k][ncol] with k = kc*64 + s*16 + (e<2 ? 2c+e : 8+2c+e-2), ncol = ntl*80+n
__global__ void k_pack_ub(const float* __restrict__ Ul, const float* __restrict__ Ur,
                          const float* __restrict__ Fll, const float* __restrict__ Flr,
                          const float* __restrict__ Frl, const float* __restrict__ Frr) {
    int idx = blockIdx.x * blockDim.x + threadIdx.x;
    if (idx >= UB_TOTAL) return;
    int e = idx & 3, c = (idx >> 2) & 3;
    int n = (idx >> 4) % 80;
    int q = (idx >> 4) / 80;           // ntl*32 + kc*4 + s
    int s = q & 3, kc = (q >> 2) & 7, ntl = q >> 5;
    int kin = (e < 2) ? (2 * c + e) : (8 + 2 * c + (e - 2));
    int k = kc * 64 + s * 16 + kin;
    int ncol = ntl * 80 + n;
    int j = ncol / 5, g = ncol - 5 * j;
    float v;
    if (k < 256) {
        v = (g == 0) ? Ul[k * 768 + j]
          : (g == 1) ? Ul[k * 768 + 256 + j]
          : (g == 2) ? Ul[k * 768 + 512 + j]
          : (g == 3) ? Fll[k * 256 + j]
                     : Frl[k * 256 + j];
    } else {
        int kr = k - 256;
        v = (g == 0) ? Ur[kr * 768 + j]
          : (g == 1) ? Ur[kr * 768 + 256 + j]
          : (g == 2) ? Ur[kr * 768 + 512 + j]
          : (g == 3) ? Flr[kr * 256 + j]
                     : Frr[kr * 256 + j];
    }
    __nv_bfloat16 hi = __float2bfloat16(v);
    float lo = v - __bfloat162float(hi);
    g_UBH[idx] = hi;
    g_UBL[idx] = __float2bfloat16(lo);
}

// ---------------- input-projection GEMM (SIMT fp32, once) ----------------
__global__ __launch_bounds__(256) void k_xgemm(const float* __restrict__ X) {
    __shared__ float As[32][32];
    __shared__ __align__(16) float Bs[32][128];
    int tid = threadIdx.x;
    int m0 = blockIdx.x * 32;
    int j0 = blockIdx.y * 32;
    int w = tid >> 5, lane = tid & 31;

    float acc[4][4];
#pragma unroll
    for (int i = 0; i < 4; i++)
#pragma unroll
        for (int g = 0; g < 4; g++) acc[i][g] = 0.0f;

    for (int kc = 0; kc < 10; kc++) {
        int bk = kc * 32;
#pragma unroll
        for (int i = 0; i < 4; i++) {
            int r = w + i * 8;
            int k = bk + lane;
            As[r][lane] = (k < NE) ? X[(size_t)(m0 + r) * NE + k] : 0.0f;
        }
        {
            int kk = tid >> 3, grp = tid & 7;
            int k = bk + kk;
            float4* dst = (float4*)&Bs[kk][grp * 16];
            if (k < NE) {
                const float4* src = (const float4*)&g_W[(size_t)k * XN + j0 * 4 + grp * 16];
#pragma unroll
                for (int i = 0; i < 4; i++) dst[i] = src[i];
            } else {
                float4 z = make_float4(0.f, 0.f, 0.f, 0.f);
#pragma unroll
                for (int i = 0; i < 4; i++) dst[i] = z;
            }
        }
        __syncthreads();
#pragma unroll
        for (int kk = 0; kk < 32; kk++) {
            float4 b4 = *(const float4*)&Bs[kk][lane * 4];
#pragma unroll
            for (int i = 0; i < 4; i++) {
                float a = As[w + i * 8][kk];
                acc[i][0] += a * b4.x; acc[i][1] += a * b4.y;
                acc[i][2] += a * b4.z; acc[i][3] += a * b4.w;
            }
        }
        __syncthreads();
    }
    float4 bb = *(const float4*)&g_bias[(j0 + lane) * 4];
#pragma unroll
    for (int i = 0; i < 4; i++) {
        int row = m0 + w + i * 8;
        float4 o = make_float4(acc[i][0] + bb.x, acc[i][1] + bb.y,
                               acc[i][2] + bb.z, acc[i][3] + bb.w);
        *(float4*)&g_x[(size_t)row * XN + (j0 + lane) * 4] = o;
    }
}

// ---------------- winner / compact ----------------
__global__ void k_winner(int t, const int* __restrict__ td) {
    int idx = blockIdx.x * blockDim.x + threadIdx.x;
    if (idx >= NROWS) return;
    int b = idx >> 11, s = idx & 2047;
    int d = td[b * (NT * NS) + t * NS + s];
    atomicMax(&g_winner[(b << 11) + d], t * 2048 + s);
}

__global__ void k_compact(int t, const int* __restrict__ td) {
    int idx = blockIdx.x * blockDim.x + threadIdx.x;
    if (idx >= NROWS) return;
    int b = idx >> 11, s = idx & 2047;
    int d = td[b * (NT * NS) + t * NS + s];
    if (d != 0 && g_winner[(b << 11) + d] == t * 2048 + s) {
        int p = atomicAdd(&g_cnt[t], 1);
        g_work[p] = idx;
    }
}

// ---------------- mma.sync split-bf16 fused step kernel ----------------
// grid = (16 ntiles, 512 mtiles), 256 threads
__global__ __launch_bounds__(256, 2) void k_step_mma(
    int t, const int* __restrict__ td, const int* __restrict__ tl, const int* __restrict__ tr,
    const float* __restrict__ hcur, const float* __restrict__ ccur,
    float* __restrict__ hn, float* __restrict__ cn)
{
    extern __shared__ char smem[];
    int count = g_cnt[t];
    int mt = blockIdx.y;
    if (mt * BM >= count) return;
    int nt = blockIdx.x;
    int tid = threadIdx.x;

    int* sL = (int*)(smem + OFF_IDX);
    int* sR = (int*)(smem + OFF_IDX + 512);
    int* sD = (int*)(smem + OFF_IDX + 1024);
    int* sRow = (int*)(smem + OFF_IDX + 1536);

    if (tid < BM) {
        int m = mt * BM + tid;
        if (m < count) {
            int idx = g_work[m];
            int b = idx >> 11, s = idx & 2047;
            int tb = b * (NT * NS) + t * NS + s;
            int brow = b << 11;
            sL[tid] = (brow + tl[tb]) << 8;
            sR[tid] = (brow + tr[tb]) << 8;
            sD[tid] = (brow + td[tb]) << 8;
            sRow[tid] = idx;
        } else {
            sL[tid] = 0; sR[tid] = 0; sD[tid] = -1; sRow[tid] = 0;
        }
    }
    __syncthreads();

    uint32_t sb = smem_u32(smem);
    int warp = tid >> 5, lane = tid & 31;
    int warpM = warp & 3, warpN = warp >> 2;      // 4 m-warps x 2 n-warps

    float acc[2][5][4];
#pragma unroll
    for (int m = 0; m < 2; m++)
#pragma unroll
        for (int f = 0; f < 5; f++)
#pragma unroll
            for (int i = 0; i < 4; i++) acc[m][f][i] = 0.0f;

    // ldmatrix lane address components
    int r0 = warpM * 32 + (lane & 15);
    int r1 = r0 + 16;
    int segb = ((lane >> 4) & 1) * 16;
    uint32_t abh = sb + OFF_AH, abl = sb + OFF_AL;

    const __nv_bfloat16* pbh = g_UBH + (size_t)nt * UB_NT_STRIDE;
    const __nv_bfloat16* pbl = g_UBL + (size_t)nt * UB_NT_STRIDE;
    int lanepart = (lane >> 2) * 16 + (lane & 3) * 4;
    int warppart = warpN * 640;                    // warpN*40 cols * 16

    int arow = tid >> 1, ahalf = tid & 1;          // staging role

    for (int kc = 0; kc < 8; kc++) {
        __syncthreads();   // previous mma consumers done with A buffers
        // ---- stage A chunk: gather 64 fp32 per row, split hi/lo bf16, swizzle ----
        {
            const float* src = hcur + ((kc < 4) ? sL[arow] : sR[arow]) + (kc & 3) * 64 + ahalf * 32;
#pragma unroll
            for (int gi = 0; gi < 4; gi++) {
                float4 v0 = *(const float4*)(src + gi * 8);
                float4 v1 = *(const float4*)(src + gi * 8 + 4);
                float h0 = __bfloat162float(__float2bfloat16(v0.x));
                float h1 = __bfloat162float(__float2bfloat16(v0.y));
                float h2 = __bfloat162float(__float2bfloat16(v0.z));
                float h3 = __bfloat162float(__float2bfloat16(v0.w));
                float h4 = __bfloat162float(__float2bfloat16(v1.x));
                float h5 = __bfloat162float(__float2bfloat16(v1.y));
                float h6 = __bfloat162float(__float2bfloat16(v1.z));
                float h7 = __bfloat162float(__float2bfloat16(v1.w));
                uint4 ph, pl;
                ph.x = pack_hi2(v0.x, v0.y); ph.y = pack_hi2(v0.z, v0.w);
                ph.z = pack_hi2(v1.x, v1.y); ph.w = pack_hi2(v1.z, v1.w);
                pl.x = pack_hi2(v0.x - h0, v0.y - h1); pl.y = pack_hi2(v0.z - h2, v0.w - h3);
                pl.z = pack_hi2(v1.x - h4, v1.y - h5); pl.w = pack_hi2(v1.z - h6, v1.w - h7);
                int byte = arow * 128 + ahalf * 64 + gi * 16;
                int sw = byte ^ ((byte >> 3) & 0x70);
                *(uint4*)(smem + OFF_AH + sw) = ph;
                *(uint4*)(smem + OFF_AL + sw) = pl;
            }
        }
        __syncthreads();

        // ---- 4 k16 steps: 3-pass split-bf16 mma ----
#pragma unroll
        for (int s = 0; s < 4; s++) {
            uint32_t ah0[4], ah1[4], al0[4], al1[4];
            {
                int o = r0 * 128 + s * 32 + segb; o ^= ((o >> 3) & 0x70);
                ldsm4(ah0, abh + o); ldsm4(al0, abl + o);
            }
            {
                int o = r1 * 128 + s * 32 + segb; o ^= ((o >> 3) & 0x70);
                ldsm4(ah1, abh + o); ldsm4(al1, abl + o);
            }
            int be = (kc * 4 + s) * 1280 + warppart + lanepart;
#pragma unroll
            for (int f = 0; f < 5; f++) {
                uint2 bh = *(const uint2*)(pbh + be + f * 128);
                uint2 bl = *(const uint2*)(pbl + be + f * 128);
                MMA(acc[0][f], ah0, bh.x, bh.y);
                MMA(acc[1][f], ah1, bh.x, bh.y);
                MMA(acc[0][f], al0, bh.x, bh.y);
                MMA(acc[1][f], al1, bh.x, bh.y);
                MMA(acc[0][f], ah0, bl.x, bl.y);
                MMA(acc[1][f], ah1, bl.x, bl.y);
            }
        }
    }

    // ---- epilogue: transpose acc through smem, fuse activations ----
    __syncthreads();
    float* stg = (float*)(smem + OFF_STAGE);
    {
        int rg = lane >> 2, cc = 2 * (lane & 3);
#pragma unroll
        for (int m = 0; m < 2; m++) {
#pragma unroll
            for (int f = 0; f < 5; f++) {
                int row = warpM * 32 + m * 16 + rg;
                int col = warpN * 40 + f * 8 + cc;
                *(float2*)&stg[row * 84 + col] = make_float2(acc[m][f][0], acc[m][f][1]);
                *(float2*)&stg[(row + 8) * 84 + col] = make_float2(acc[m][f][2], acc[m][f][3]);
            }
        }
    }
    __syncthreads();

    {
        int row = tid >> 1, ug = tid & 1;
        int j0 = nt * 16;
        int od = sD[row];
        const float* xp = g_x + (size_t)sRow[row] * XN + (size_t)(j0 + ug * 8) * 4;
        const float* clp = ccur + sL[row] + j0 + ug * 8;
        const float* crp = ccur + sR[row] + j0 + ug * 8;
        float clv[8], crv[8], ho[8], co[8];
        *(float4*)&clv[0] = *(const float4*)clp;
        *(float4*)&clv[4] = *(const float4*)(clp + 4);
        *(float4*)&crv[0] = *(const float4*)crp;
        *(float4*)&crv[4] = *(const float4*)(crp + 4);
#pragma unroll
        for (int u = 0; u < 8; u++) {
            int jl = ug * 8 + u;
            float a_i = stg[row * 84 + jl * 5 + 0];
            float a_o = stg[row * 84 + jl * 5 + 1];
            float a_u = stg[row * 84 + jl * 5 + 2];
            float a_fl = stg[row * 84 + jl * 5 + 3];
            float a_fr = stg[row * 84 + jl * 5 + 4];
            float4 xv = *(const float4*)(xp + u * 4);
            float gi = sigm(a_i + xv.x);
            float go = sigm(a_o + xv.y);
            float gu = tanhf(a_u + xv.z);
            float fl = sigm(a_fl + xv.w);
            float fr = sigm(a_fr + xv.w);
            float cnew = gi * gu + fl * clv[u] + fr * crv[u];
            ho[u] = go * tanhf(cnew);
            co[u] = cnew;
        }
        if (od >= 0) {
            float* hp = hn + od + j0 + ug * 8;
            float* cp = cn + od + j0 + ug * 8;
            *(float4*)hp = *(float4*)&ho[0];
            *(float4*)(hp + 4) = *(float4*)&ho[4];
            *(float4*)cp = *(float4*)&co[0];
            *(float4*)(cp + 4) = *(float4*)&co[4];
        }
    }
}

// ---------------- copy non-winner rows; zero slot 0 ----------------
__global__ void k_copy(int t, const float* __restrict__ hcur, const float* __restrict__ ccur,
                       float* __restrict__ hn, float* __restrict__ cn) {
    int row = blockIdx.x;
    int j = threadIdx.x;
    int d = row & 2047;
    size_t o = ((size_t)row << 8) + j;
    if (d == 0) { hn[o] = 0.0f; cn[o] = 0.0f; return; }
    if (g_winner[row] >= t * 2048) return;
    hn[o] = hcur[o];
    cn[o] = ccur[o];
}

// ---------------- h_root ----------------
__global__ void k_root(const int* __restrict__ td, const float* __restrict__ out_h,
                       float* __restrict__ out_root) {
    __shared__ int red[256];
    int b = blockIdx.x, tid = threadIdx.x;
    int v = 0;
    for (int s = tid; s < NS; s += 256) v = max(v, td[b * (NT * NS) + (NT - 1) * NS + s]);
    red[tid] = v;
    __syncthreads();
    for (int off = 128; off > 0; off >>= 1) {
        if (tid < off) red[tid] = max(red[tid], red[tid + off]);
        __syncthreads();
    }
    int root = red[0];
    out_root[b * NH + tid] = out_h[(((size_t)(b << 11)) + root) * NH + tid];
}

// ---------------- host launcher (graph-capturable) ----------------
extern "C" void kernel_launch(void* const* d_in, const int* in_sizes, int n_in,
                              void* d_out, int out_size) {
    const float* X     = (const float*)d_in[0];
    const int*   td    = (const int*)d_in[1];
    const int*   tr    = (const int*)d_in[2];
    const int*   tl    = (const int*)d_in[3];
    const float* W_iou = (const float*)d_in[4];
    const float* b_iou = (const float*)d_in[5];
    const float* U_l   = (const float*)d_in[6];
    const float* U_r   = (const float*)d_in[7];
    const float* W_f   = (const float*)d_in[8];
    const float* b_f   = (const float*)d_in[9];
    const float* F_ll  = (const float*)d_in[10];
    const float* F_lr  = (const float*)d_in[11];
    const float* F_rl  = (const float*)d_in[12];
    const float* F_rr  = (const float*)d_in[13];

    float* out      = (float*)d_out;
    float* out_h    = out;
    float* out_c    = out + (size_t)HCNT;
    float* out_root = out + 2 * (size_t)HCNT;

    float *hb = nullptr, *cb = nullptr;
    cudaGetSymbolAddress((void**)&hb, g_h);
    cudaGetSymbolAddress((void**)&cb, g_c);

    k_init<<<4096, 256>>>();
    k_pack_w<<<(NE * XN + 255) / 256, 256>>>(W_iou, b_iou, W_f, b_f);
    k_pack_ub<<<(UB_TOTAL + 255) / 256, 256>>>(U_l, U_r, F_ll, F_lr, F_rl, F_rr);
    k_xgemm<<<dim3(NROWS / 32, 8), 256>>>(X);

    int cur = 0;
    for (int t = 0; t < NT; t++) {
        k_winner<<<NROWS / 256, 256>>>(t, td);
        k_compact<<<NROWS / 256, 256>>>(t, td);
        float* hc = hb + (size_t)cur * HCNT;
        float* cc = cb + (size_t)cur * HCNT;
        float* hnp = (t == NT - 1) ? out_h : hb + (size_t)(1 - cur) * HCNT;
        float* cnp = (t == NT - 1) ? out_c : cb + (size_t)(1 - cur) * HCNT;
        k_step_mma<<<dim3(NTL, 512), 256, SMEM_DYN>>>(t, td, tl, tr, hc, cc, hnp, cnp);
        k_copy<<<NROWS, 256>>>(t, hc, cc, hnp, cnp);
        cur ^= 1;
    }
    k_root<<<NB, 256>>>(td, out_h, out_root);
}

// round 8
// speedup vs baseline: 2.4691x; 1.2720x over previous
#include <cuda_runtime.h>
#include <cuda_bf16.h>
#include <math.h>
#include <stdint.h>

// ---------------- problem constants ----------------
#define NB 32
#define NS 2048
#define NE 300
#define NH 256
#define NT 24
#define NROWS 65536            // NB*NS
#define XN 1024                 // x-gates per row: j*4 + {i,o,u,f}
#define HCNT 16777216           // NROWS*NH

// ---------------- step-GEMM tiling ----------------
#define BM 128                  // rows per CTA
#define BN 160                  // 32 units * 5 gates per CTA
#define NTL 8                   // 1280 / 160 n-tiles
#define UB_NT_STRIDE 40960      // bf16 elems per 80-col packed tile (8 kchunks)
#define UB_TOTAL (16 * UB_NT_STRIDE)

// ---------------- dynamic smem layout (bytes) ------
#define OFF_IDX   0             // sL/sR/sD/sRow: 4 * 512
#define OFF_AH0   2048          // 128 x 64 bf16 = 16384
#define OFF_AL0   18432
#define OFF_AH1   34816
#define OFF_AL1   51200
#define OFF_STAGE 2048          // 128 x 164 f32 = 83968 (reuses A buffers)
#define SMEM_DYN  86016

// ---------------- device scratch -------------------
__device__ float g_x[(size_t)NROWS * XN];     // 256 MiB packed x-gates
__device__ float g_W[NE * XN];
__device__ float g_bias[XN];
__device__ __nv_bfloat16 g_UBH[UB_TOTAL];     // U hi, fragment-native layout
__device__ __nv_bfloat16 g_UBL[UB_TOTAL];     // U lo
__device__ __nv_bfloat16 g_hh[2 * (size_t)HCNT];  // h hi state (ping-pong)
__device__ __nv_bfloat16 g_hl[2 * (size_t)HCNT];  // h lo state
__device__ float g_c[2 * (size_t)HCNT];           // c state fp32
__device__ int   g_winner[NROWS];
__device__ int   g_work[NROWS];
__device__ int   g_cnt[32];

__device__ __forceinline__ float sigm(float x) { return 1.0f / (1.0f + __expf(-x)); }

__device__ __forceinline__ uint32_t smem_u32(const void* p) {
    uint32_t r;
    asm("{ .reg .u64 t; cvta.to.shared.u64 t, %1; cvt.u32.u64 %0, t; }" : "=r"(r) : "l"(p));
    return r;
}
__device__ __forceinline__ void ldsm4(uint32_t* r, uint32_t addr) {
    asm volatile("ldmatrix.sync.aligned.m8n8.x4.shared.b16 {%0,%1,%2,%3}, [%4];"
                 : "=r"(r[0]), "=r"(r[1]), "=r"(r[2]), "=r"(r[3]) : "r"(addr));
}
#define MMA(d, a, bx, by) asm volatile( \
    "mma.sync.aligned.m16n8k16.row.col.f32.bf16.bf16.f32 " \
    "{%0,%1,%2,%3},{%4,%5,%6,%7},{%8,%9},{%0,%1,%2,%3};" \
    : "+f"((d)[0]), "+f"((d)[1]), "+f"((d)[2]), "+f"((d)[3]) \
    : "r"((a)[0]), "r"((a)[1]), "r"((a)[2]), "r"((a)[3]), "r"(bx), "r"(by))

__device__ __forceinline__ void cp16(uint32_t dst, const void* src) {
    asm volatile("{\n\t.reg .u64 g;\n\tcvta.to.global.u64 g, %1;\n\t"
                 "cp.async.cg.shared.global [%0], [g], 16;\n\t}"
                 :: "r"(dst), "l"(src) : "memory");
}
#define CP_COMMIT asm volatile("cp.async.commit_group;" ::: "memory")
#define CP_WAIT1  asm volatile("cp.async.wait_group 1;" ::: "memory")
#define CP_WAIT0  asm volatile("cp.async.wait_group 0;" ::: "memory")

__device__ __forceinline__ uint32_t pack_bf2(float a, float b) {
    __nv_bfloat162 v = __floats2bfloat162_rn(a, b);
    return *(uint32_t*)&v;
}

// ---------------- init: zero buf0 state, reset winner/counts ----------------
__global__ void k_init() {
    size_t i = (size_t)blockIdx.x * blockDim.x + threadIdx.x;
    size_t stride = (size_t)gridDim.x * blockDim.x;
    uint32_t* ph = (uint32_t*)g_hh;
    uint32_t* pl = (uint32_t*)g_hl;
    for (size_t p = i; p < (size_t)(HCNT / 2); p += stride) { ph[p] = 0u; pl[p] = 0u; }
    for (size_t p = i; p < (size_t)HCNT; p += stride) g_c[p] = 0.0f;
    for (size_t p = i; p < (size_t)NROWS; p += stride) g_winner[p] = -1;
    if (i < 32) g_cnt[i] = 0;
}

// ---------------- pack input weights: g_W[k][j*4+g] ----------------
__global__ void k_pack_w(const float* __restrict__ W_iou, const float* __restrict__ b_iou,
                         const float* __restrict__ W_f,   const float* __restrict__ b_f) {
    int idx = blockIdx.x * blockDim.x + threadIdx.x;
    if (idx < NE * XN) {
        int k = idx >> 10, n = idx & 1023, j = n >> 2, g = n & 3;
        g_W[idx] = (g < 3) ? W_iou[k * 768 + g * 256 + j] : W_f[k * 256 + j];
    }
    if (idx < XN) {
        int j = idx >> 2, g = idx & 3;
        g_bias[idx] = (g < 3) ? b_iou[g * 256 + j] : b_f[j];
    }
}

// ---- pack U hi/lo bf16, mma-fragment-native layout (16 tiles of 80 cols) ----
__global__ void k_pack_ub(const float* __restrict__ Ul, const float* __restrict__ Ur,
                          const float* __restrict__ Fll, const float* __restrict__ Flr,
                          const float* __restrict__ Frl, const float* __restrict__ Frr) {
    int idx = blockIdx.x * blockDim.x + threadIdx.x;
    if (idx >= UB_TOTAL) return;
    int e = idx & 3, c = (idx >> 2) & 3;
    int n = (idx >> 4) % 80;
    int q = (idx >> 4) / 80;           // ntl*32 + kc*4 + s
    int s = q & 3, kc = (q >> 2) & 7, ntl = q >> 5;
    int kin = (e < 2) ? (2 * c + e) : (8 + 2 * c + (e - 2));
    int k = kc * 64 + s * 16 + kin;
    int ncol = ntl * 80 + n;
    int j = ncol / 5, g = ncol - 5 * j;
    float v;
    if (k < 256) {
        v = (g == 0) ? Ul[k * 768 + j]
          : (g == 1) ? Ul[k * 768 + 256 + j]
          : (g == 2) ? Ul[k * 768 + 512 + j]
          : (g == 3) ? Fll[k * 256 + j]
                     : Frl[k * 256 + j];
    } else {
        int kr = k - 256;
        v = (g == 0) ? Ur[kr * 768 + j]
          : (g == 1) ? Ur[kr * 768 + 256 + j]
          : (g == 2) ? Ur[kr * 768 + 512 + j]
          : (g == 3) ? Flr[kr * 256 + j]
                     : Frr[kr * 256 + j];
    }
    __nv_bfloat16 hi = __float2bfloat16(v);
    float lo = v - __bfloat162float(hi);
    g_UBH[idx] = hi;
    g_UBL[idx] = __float2bfloat16(lo);
}

// ---------------- input-projection GEMM (SIMT fp32, once) ----------------
__global__ __launch_bounds__(256) void k_xgemm(const float* __restrict__ X) {
    __shared__ float As[32][32];
    __shared__ __align__(16) float Bs[32][128];
    int tid = threadIdx.x;
    int m0 = blockIdx.x * 32;
    int j0 = blockIdx.y * 32;
    int w = tid >> 5, lane = tid & 31;

    float acc[4][4];
#pragma unroll
    for (int i = 0; i < 4; i++)
#pragma unroll
        for (int g = 0; g < 4; g++) acc[i][g] = 0.0f;

    for (int kc = 0; kc < 10; kc++) {
        int bk = kc * 32;
#pragma unroll
        for (int i = 0; i < 4; i++) {
            int r = w + i * 8;
            int k = bk + lane;
            As[r][lane] = (k < NE) ? X[(size_t)(m0 + r) * NE + k] : 0.0f;
        }
        {
            int kk = tid >> 3, grp = tid & 7;
            int k = bk + kk;
            float4* dst = (float4*)&Bs[kk][grp * 16];
            if (k < NE) {
                const float4* src = (const float4*)&g_W[(size_t)k * XN + j0 * 4 + grp * 16];
#pragma unroll
                for (int i = 0; i < 4; i++) dst[i] = src[i];
            } else {
                float4 z = make_float4(0.f, 0.f, 0.f, 0.f);
#pragma unroll
                for (int i = 0; i < 4; i++) dst[i] = z;
            }
        }
        __syncthreads();
#pragma unroll
        for (int kk = 0; kk < 32; kk++) {
            float4 b4 = *(const float4*)&Bs[kk][lane * 4];
#pragma unroll
            for (int i = 0; i < 4; i++) {
                float a = As[w + i * 8][kk];
                acc[i][0] += a * b4.x; acc[i][1] += a * b4.y;
                acc[i][2] += a * b4.z; acc[i][3] += a * b4.w;
            }
        }
        __syncthreads();
    }
    float4 bb = *(const float4*)&g_bias[(j0 + lane) * 4];
#pragma unroll
    for (int i = 0; i < 4; i++) {
        int row = m0 + w + i * 8;
        float4 o = make_float4(acc[i][0] + bb.x, acc[i][1] + bb.y,
                               acc[i][2] + bb.z, acc[i][3] + bb.w);
        *(float4*)&g_x[(size_t)row * XN + (j0 + lane) * 4] = o;
    }
}

// ---------------- winner / compact ----------------
__global__ void k_winner(int t, const int* __restrict__ td) {
    int idx = blockIdx.x * blockDim.x + threadIdx.x;
    if (idx >= NROWS) return;
    int b = idx >> 11, s = idx & 2047;
    int d = td[b * (NT * NS) + t * NS + s];
    atomicMax(&g_winner[(b << 11) + d], t * 2048 + s);
}

__global__ void k_compact(int t, const int* __restrict__ td) {
    int idx = blockIdx.x * blockDim.x + threadIdx.x;
    if (idx >= NROWS) return;
    int b = idx >> 11, s = idx & 2047;
    int d = td[b * (NT * NS) + t * NS + s];
    if (d != 0 && g_winner[(b << 11) + d] == t * 2048 + s) {
        int p = atomicAdd(&g_cnt[t], 1);
        g_work[p] = idx;
    }
}

// ---------------- mma.sync split-bf16 fused step kernel ----------------
// grid = (8 ntiles, 512 mtiles), 512 threads (16 warps: 4M x 4N)
__global__ __launch_bounds__(512, 1) void k_step_mma(
    int t, int final,
    const int* __restrict__ td, const int* __restrict__ tl, const int* __restrict__ tr,
    const __nv_bfloat16* __restrict__ hh, const __nv_bfloat16* __restrict__ hl,
    const float* __restrict__ ccur,
    __nv_bfloat16* __restrict__ hhn, __nv_bfloat16* __restrict__ hln,
    float* __restrict__ cnn, float* __restrict__ oh, float* __restrict__ oc)
{
    extern __shared__ char smem[];
    int count = g_cnt[t];
    int mt = blockIdx.y;
    if (mt * BM >= count) return;
    int nt = blockIdx.x;
    int tid = threadIdx.x;

    int* sL = (int*)(smem + OFF_IDX);
    int* sR = (int*)(smem + OFF_IDX + 512);
    int* sD = (int*)(smem + OFF_IDX + 1024);
    int* sRow = (int*)(smem + OFF_IDX + 1536);

    if (tid < BM) {
        int m = mt * BM + tid;
        if (m < count) {
            int idx = g_work[m];
            int b = idx >> 11, s = idx & 2047;
            int tb = b * (NT * NS) + t * NS + s;
            int brow = b << 11;
            sL[tid] = (brow + tl[tb]) << 8;
            sR[tid] = (brow + tr[tb]) << 8;
            sD[tid] = (brow + td[tb]) << 8;
            sRow[tid] = idx;
        } else {
            sL[tid] = 0; sR[tid] = 0; sD[tid] = -1; sRow[tid] = 0;
        }
    }
    __syncthreads();

    uint32_t sb = smem_u32(smem);
    // per-thread A-staging role: 4 threads per row, 16 k-elems per quarter
    int arow = tid >> 2, aq = tid & 3;
    int offL = sL[arow], offR = sR[arow];
    int b0 = arow * 128 + aq * 32;
    int b1 = b0 + 16;
    int s0 = b0 ^ ((b0 >> 3) & 0x70);
    int s1 = b1 ^ ((b1 >> 3) & 0x70);
    const uint32_t offAH[2] = {OFF_AH0, OFF_AH1};
    const uint32_t offAL[2] = {OFF_AL0, OFF_AL1};

    // stage chunk 0 (from h_l, k0=0)
    {
        const __nv_bfloat16* ph = hh + offL + aq * 16;
        const __nv_bfloat16* pl = hl + offL + aq * 16;
        cp16(sb + OFF_AH0 + s0, ph);  cp16(sb + OFF_AH0 + s1, ph + 8);
        cp16(sb + OFF_AL0 + s0, pl);  cp16(sb + OFF_AL0 + s1, pl + 8);
        CP_COMMIT;
    }

    int warp = tid >> 5, lane = tid & 31;
    int warpM = warp & 3, warpN = warp >> 2;     // 4 m-warps x 4 n-warps

    float acc[2][5][4];
#pragma unroll
    for (int m = 0; m < 2; m++)
#pragma unroll
        for (int f = 0; f < 5; f++)
#pragma unroll
            for (int i = 0; i < 4; i++) acc[m][f][i] = 0.0f;

    int r0 = warpM * 32 + (lane & 15);
    int r1 = r0 + 16;
    int segb = ((lane >> 4) & 1) * 16;

    int tilesel = nt * 2 + (warpN >> 1);
    const __nv_bfloat16* pbh = g_UBH + (size_t)tilesel * UB_NT_STRIDE;
    const __nv_bfloat16* pbl = g_UBL + (size_t)tilesel * UB_NT_STRIDE;
    int lanepart = (lane >> 2) * 16 + (lane & 3) * 4;
    int warppart = (warpN & 1) * 640;

    for (int kc = 0; kc < 8; kc++) {
        // prefetch next chunk into other buffer
        if (kc < 7) {
            int kcn = kc + 1;
            int nb = kcn & 1;
            int off = (kcn < 4) ? offL : offR;
            int k0 = (kcn & 3) * 64;
            const __nv_bfloat16* ph = hh + off + k0 + aq * 16;
            const __nv_bfloat16* pl = hl + off + k0 + aq * 16;
            cp16(sb + offAH[nb] + s0, ph);  cp16(sb + offAH[nb] + s1, ph + 8);
            cp16(sb + offAL[nb] + s0, pl);  cp16(sb + offAL[nb] + s1, pl + 8);
            CP_COMMIT;
            CP_WAIT1;      // chunk kc arrived
        } else {
            CP_WAIT0;
        }
        __syncthreads();

        uint32_t abh = sb + offAH[kc & 1];
        uint32_t abl = sb + offAL[kc & 1];
#pragma unroll
        for (int s = 0; s < 4; s++) {
            uint32_t ah0[4], ah1[4], al0[4], al1[4];
            {
                int o = r0 * 128 + s * 32 + segb; o ^= ((o >> 3) & 0x70);
                ldsm4(ah0, abh + o); ldsm4(al0, abl + o);
            }
            {
                int o = r1 * 128 + s * 32 + segb; o ^= ((o >> 3) & 0x70);
                ldsm4(ah1, abh + o); ldsm4(al1, abl + o);
            }
            int be = (kc * 4 + s) * 1280 + warppart + lanepart;
#pragma unroll
            for (int f = 0; f < 5; f++) {
                uint2 bh = *(const uint2*)(pbh + be + f * 128);
                uint2 bl = *(const uint2*)(pbl + be + f * 128);
                MMA(acc[0][f], ah0, bh.x, bh.y);
                MMA(acc[1][f], ah1, bh.x, bh.y);
                MMA(acc[0][f], al0, bh.x, bh.y);
                MMA(acc[1][f], al1, bh.x, bh.y);
                MMA(acc[0][f], ah0, bl.x, bl.y);
                MMA(acc[1][f], ah1, bl.x, bl.y);
            }
        }
        __syncthreads();    // all reads of buf[kc&1] done before re-stage at kc+2
    }

    // ---- epilogue: transpose acc through smem, fuse activations ----
    float* stg = (float*)(smem + OFF_STAGE);
    {
        int rg = lane >> 2, cl = 2 * (lane & 3);
#pragma unroll
        for (int m = 0; m < 2; m++) {
#pragma unroll
            for (int f = 0; f < 5; f++) {
                int row = warpM * 32 + m * 16 + rg;
                int col = warpN * 40 + f * 8 + cl;
                *(float2*)&stg[row * 164 + col] = make_float2(acc[m][f][0], acc[m][f][1]);
                *(float2*)&stg[(row + 8) * 164 + col] = make_float2(acc[m][f][2], acc[m][f][3]);
            }
        }
    }
    __syncthreads();

    {
        int row = arow, ug = aq;          // 4 threads per row, 8 units each
        int j0 = nt * 32;
        int od = sD[row];
        const float* xp = g_x + (size_t)sRow[row] * XN + (size_t)(j0 + ug * 8) * 4;
        const float* clp = ccur + offL + j0 + ug * 8;
        const float* crp = ccur + offR + j0 + ug * 8;
        float clv[8], crv[8], ho[8], co[8];
        *(float4*)&clv[0] = *(const float4*)clp;
        *(float4*)&clv[4] = *(const float4*)(clp + 4);
        *(float4*)&crv[0] = *(const float4*)crp;
        *(float4*)&crv[4] = *(const float4*)(crp + 4);
#pragma unroll
        for (int u = 0; u < 8; u++) {
            int col = (ug * 8 + u) * 5;
            float a_i  = stg[row * 164 + col + 0];
            float a_o  = stg[row * 164 + col + 1];
            float a_u  = stg[row * 164 + col + 2];
            float a_fl = stg[row * 164 + col + 3];
            float a_fr = stg[row * 164 + col + 4];
            float4 xv = ((const float4*)xp)[u];
            float gi = sigm(a_i + xv.x);
            float go = sigm(a_o + xv.y);
            float gu = tanhf(a_u + xv.z);
            float fl = sigm(a_fl + xv.w);
            float fr = sigm(a_fr + xv.w);
            float cnew = gi * gu + fl * clv[u] + fr * crv[u];
            ho[u] = go * tanhf(cnew);
            co[u] = cnew;
        }
        if (od >= 0) {
            uint32_t hw[4], lw[4];
#pragma unroll
            for (int p = 0; p < 4; p++) {
                float v0 = ho[2 * p], v1 = ho[2 * p + 1];
                __nv_bfloat16 a = __float2bfloat16(v0);
                __nv_bfloat16 b = __float2bfloat16(v1);
                hw[p] = pack_bf2(v0, v1);
                lw[p] = pack_bf2(v0 - __bfloat162float(a), v1 - __bfloat162float(b));
            }
            int eo = od + j0 + ug * 8;
            *(uint4*)(hhn + eo) = make_uint4(hw[0], hw[1], hw[2], hw[3]);
            *(uint4*)(hln + eo) = make_uint4(lw[0], lw[1], lw[2], lw[3]);
            *(float4*)(cnn + eo) = *(float4*)&co[0];
            *(float4*)(cnn + eo + 4) = *(float4*)&co[4];
            if (final) {
                *(float4*)(oh + eo) = *(float4*)&ho[0];
                *(float4*)(oh + eo + 4) = *(float4*)&ho[4];
                *(float4*)(oc + eo) = *(float4*)&co[0];
                *(float4*)(oc + eo + 4) = *(float4*)&co[4];
            }
        }
    }
}

// ---------------- copy non-winner rows; zero slot 0 ----------------
__global__ void k_copy(int t, int final,
                       const __nv_bfloat16* __restrict__ hhc, const __nv_bfloat16* __restrict__ hlc,
                       const float* __restrict__ ccc,
                       __nv_bfloat16* __restrict__ hhn, __nv_bfloat16* __restrict__ hln,
                       float* __restrict__ cnn, float* __restrict__ oh, float* __restrict__ oc) {
    int row = blockIdx.x;
    int j = threadIdx.x;
    int d = row & 2047;
    size_t o = ((size_t)row << 8) + j;
    if (d == 0) {
        hhn[o] = __float2bfloat16(0.0f);
        hln[o] = __float2bfloat16(0.0f);
        cnn[o] = 0.0f;
        if (final) { oh[o] = 0.0f; oc[o] = 0.0f; }
        return;
    }
    if (g_winner[row] >= t * 2048) return;   // winner wrote it in k_step
    __nv_bfloat16 a = hhc[o], b = hlc[o];
    float c = ccc[o];
    hhn[o] = a; hln[o] = b; cnn[o] = c;
    if (final) {
        oh[o] = __bfloat162float(a) + __bfloat162float(b);
        oc[o] = c;
    }
}

// ---------------- h_root ----------------
__global__ void k_root(const int* __restrict__ td, const float* __restrict__ out_h,
                       float* __restrict__ out_root) {
    __shared__ int red[256];
    int b = blockIdx.x, tid = threadIdx.x;
    int v = 0;
    for (int s = tid; s < NS; s += 256) v = max(v, td[b * (NT * NS) + (NT - 1) * NS + s]);
    red[tid] = v;
    __syncthreads();
    for (int off = 128; off > 0; off >>= 1) {
        if (tid < off) red[tid] = max(red[tid], red[tid + off]);
        __syncthreads();
    }
    int root = red[0];
    out_root[b * NH + tid] = out_h[(((size_t)(b << 11)) + root) * NH + tid];
}

// ---------------- host launcher (graph-capturable) ----------------
extern "C" void kernel_launch(void* const* d_in, const int* in_sizes, int n_in,
                              void* d_out, int out_size) {
    const float* X     = (const float*)d_in[0];
    const int*   td    = (const int*)d_in[1];
    const int*   tr    = (const int*)d_in[2];
    const int*   tl    = (const int*)d_in[3];
    const float* W_iou = (const float*)d_in[4];
    const float* b_iou = (const float*)d_in[5];
    const float* U_l   = (const float*)d_in[6];
    const float* U_r   = (const float*)d_in[7];
    const float* W_f   = (const float*)d_in[8];
    const float* b_f   = (const float*)d_in[9];
    const float* F_ll  = (const float*)d_in[10];
    const float* F_lr  = (const float*)d_in[11];
    const float* F_rl  = (const float*)d_in[12];
    const float* F_rr  = (const float*)d_in[13];

    float* out      = (float*)d_out;
    float* out_h    = out;
    float* out_c    = out + (size_t)HCNT;
    float* out_root = out + 2 * (size_t)HCNT;

    __nv_bfloat16 *hhb = nullptr, *hlb = nullptr;
    float* cb = nullptr;
    cudaGetSymbolAddress((void**)&hhb, g_hh);
    cudaGetSymbolAddress((void**)&hlb, g_hl);
    cudaGetSymbolAddress((void**)&cb, g_c);

    static int attr_done = 0;
    if (!attr_done) {
        cudaFuncSetAttribute(k_step_mma, cudaFuncAttributeMaxDynamicSharedMemorySize, SMEM_DYN);
        attr_done = 1;
    }

    k_init<<<4096, 256>>>();
    k_pack_w<<<(NE * XN + 255) / 256, 256>>>(W_iou, b_iou, W_f, b_f);
    k_pack_ub<<<(UB_TOTAL + 255) / 256, 256>>>(U_l, U_r, F_ll, F_lr, F_rl, F_rr);
    k_xgemm<<<dim3(NROWS / 32, 8), 256>>>(X);

    int cur = 0;
    for (int t = 0; t < NT; t++) {
        int fin = (t == NT - 1) ? 1 : 0;
        k_winner<<<NROWS / 256, 256>>>(t, td);
        k_compact<<<NROWS / 256, 256>>>(t, td);
        const __nv_bfloat16* hhc = hhb + (size_t)cur * HCNT;
        const __nv_bfloat16* hlc = hlb + (size_t)cur * HCNT;
        const float* ccc = cb + (size_t)cur * HCNT;
        __nv_bfloat16* hhn = hhb + (size_t)(1 - cur) * HCNT;
        __nv_bfloat16* hln = hlb + (size_t)(1 - cur) * HCNT;
        float* cnn = cb + (size_t)(1 - cur) * HCNT;
        k_step_mma<<<dim3(NTL, 512), 512, SMEM_DYN>>>(
            t, fin, td, tl, tr, hhc, hlc, ccc, hhn, hln, cnn, out_h, out_c);
        k_copy<<<NROWS, 256>>>(t, fin, hhc, hlc, ccc, hhn, hln, cnn, out_h, out_c);
        cur ^= 1;
    }
    k_root<<<NB, 256>>>(td, out_h, out_root);
}

// round 9
// speedup vs baseline: 3.8803x; 1.5715x over previous
#include <cuda_runtime.h>
#include <cuda_fp16.h>
#include <math.h>
#include <stdint.h>

// ---------------- problem constants ----------------
#define NB 32
#define NS 2048
#define NE 300
#define NH 256
#define NT 24
#define NROWS 65536            // NB*NS
#define XN 1024                 // x-gates per row: j*4 + {i,o,u,f}
#define HCNT 16777216           // NROWS*NH

// ---------------- step-GEMM tiling ----------------
#define BM 128                  // rows per CTA
#define NTL 8                   // 1280 / 160 n-tiles
#define UB_NT_STRIDE 40960      // fp16 elems per 80-col packed tile (8 kchunks)
#define UB_TOTAL (16 * UB_NT_STRIDE)
#define WP_TOTAL (20 * 16384)   // W pack: 20 kcs * 1024 cols * 16

// ---------------- k_step dynamic smem (bytes) ------
#define OFF_IDX   0             // sL/sR/sD/sRow: 4 * 512
#define OFF_AH0   2048          // 128 x 64 fp16 = 16384
#define OFF_AL0   18432
#define OFF_AH1   34816
#define OFF_AL1   51200
#define OFF_STAGE 2048          // 128 x 164 f32 (reuses A buffers)
#define SMEM_DYN  86016

// ---------------- device scratch -------------------
__device__ float g_x[(size_t)NROWS * XN];     // 256 MiB packed x-gates
__device__ __half g_Wp[WP_TOTAL];             // W fragment-native fp16 hi
__device__ float g_bias[XN];
__device__ __half g_UBH[UB_TOTAL];            // U fragment-native fp16 hi
__device__ __half g_hh[2 * (size_t)HCNT];     // h hi state (ping-pong)
__device__ __half g_hl[2 * (size_t)HCNT];     // h lo state
__device__ float g_c[2 * (size_t)HCNT];       // c state fp32
__device__ int      g_winner[NROWS];
__device__ uint32_t g_wmask[NROWS];           // bit t: row won at step t
__device__ int      g_work[NT * NROWS];       // per-step compacted winner lists
__device__ int      g_cnt[NT];

__device__ __forceinline__ float sigm(float x) { return 1.0f / (1.0f + __expf(-x)); }

__device__ __forceinline__ uint32_t smem_u32(const void* p) {
    uint32_t r;
    asm("{ .reg .u64 t; cvta.to.shared.u64 t, %1; cvt.u32.u64 %0, t; }" : "=r"(r) : "l"(p));
    return r;
}
__device__ __forceinline__ void ldsm4(uint32_t* r, uint32_t addr) {
    asm volatile("ldmatrix.sync.aligned.m8n8.x4.shared.b16 {%0,%1,%2,%3}, [%4];"
                 : "=r"(r[0]), "=r"(r[1]), "=r"(r[2]), "=r"(r[3]) : "r"(addr));
}
#define MMA(d, a, bx, by) asm volatile( \
    "mma.sync.aligned.m16n8k16.row.col.f32.f16.f16.f32 " \
    "{%0,%1,%2,%3},{%4,%5,%6,%7},{%8,%9},{%0,%1,%2,%3};" \
    : "+f"((d)[0]), "+f"((d)[1]), "+f"((d)[2]), "+f"((d)[3]) \
    : "r"((a)[0]), "r"((a)[1]), "r"((a)[2]), "r"((a)[3]), "r"(bx), "r"(by))

__device__ __forceinline__ void cp16(uint32_t dst, const void* src) {
    asm volatile("{\n\t.reg .u64 g;\n\tcvta.to.global.u64 g, %1;\n\t"
                 "cp.async.cg.shared.global [%0], [g], 16;\n\t}"
                 :: "r"(dst), "l"(src) : "memory");
}
#define CP_COMMIT asm volatile("cp.async.commit_group;" ::: "memory")
#define CP_WAIT1  asm volatile("cp.async.wait_group 1;" ::: "memory")
#define CP_WAIT0  asm volatile("cp.async.wait_group 0;" ::: "memory")

__device__ __forceinline__ uint32_t packh2(float a, float b) {
    __half2 v = __floats2half2_rn(a, b);
    return *(uint32_t*)&v;
}

// ---------------- init ----------------
__global__ void k_init() {
    size_t i = (size_t)blockIdx.x * blockDim.x + threadIdx.x;
    size_t stride = (size_t)gridDim.x * blockDim.x;
    uint32_t* ph = (uint32_t*)g_hh;
    uint32_t* pl = (uint32_t*)g_hl;
    for (size_t p = i; p < (size_t)(HCNT / 2); p += stride) { ph[p] = 0u; pl[p] = 0u; }
    for (size_t p = i; p < (size_t)HCNT; p += stride) g_c[p] = 0.0f;
    for (size_t p = i; p < (size_t)NROWS; p += stride) { g_winner[p] = -1; g_wmask[p] = 0u; }
    if (i < NT) g_cnt[i] = 0;
}

// ---- pack W: fragment-native fp16 hi; also bias ----
// elem = kcs*16384 + ncol*16 + c*4 + e ; k = (kcs>>2)*64 + (kcs&3)*16 + kin
__global__ void k_pack_wp(const float* __restrict__ W_iou, const float* __restrict__ b_iou,
                          const float* __restrict__ W_f,   const float* __restrict__ b_f) {
    int idx = blockIdx.x * blockDim.x + threadIdx.x;
    if (idx < WP_TOTAL) {
        int kcs = idx >> 14;
        int rem = idx & 16383;
        int ncol = rem >> 4, low = rem & 15;
        int c = low >> 2, e = low & 3;
        int kin = (e < 2) ? (2 * c + e) : (8 + 2 * c + (e - 2));
        int k = (kcs >> 2) * 64 + (kcs & 3) * 16 + kin;
        int j = ncol >> 2, g = ncol & 3;
        float v = 0.0f;
        if (k < NE) v = (g < 3) ? W_iou[k * 768 + g * 256 + j] : W_f[k * 256 + j];
        g_Wp[idx] = __float2half_rn(v);
    }
    if (idx < XN) {
        int j = idx >> 2, g = idx & 3;
        g_bias[idx] = (g < 3) ? b_iou[g * 256 + j] : b_f[j];
    }
}

// ---- pack U: fragment-native fp16 hi (16 tiles of 80 cols) ----
__global__ void k_pack_ub(const float* __restrict__ Ul, const float* __restrict__ Ur,
                          const float* __restrict__ Fll, const float* __restrict__ Flr,
                          const float* __restrict__ Frl, const float* __restrict__ Frr) {
    int idx = blockIdx.x * blockDim.x + threadIdx.x;
    if (idx >= UB_TOTAL) return;
    int e = idx & 3, c = (idx >> 2) & 3;
    int n = (idx >> 4) % 80;
    int q = (idx >> 4) / 80;           // ntl*32 + kc*4 + s
    int s = q & 3, kc = (q >> 2) & 7, ntl = q >> 5;
    int kin = (e < 2) ? (2 * c + e) : (8 + 2 * c + (e - 2));
    int k = kc * 64 + s * 16 + kin;
    int ncol = ntl * 80 + n;
    int j = ncol / 5, g = ncol - 5 * j;
    float v;
    if (k < 256) {
        v = (g == 0) ? Ul[k * 768 + j]
          : (g == 1) ? Ul[k * 768 + 256 + j]
          : (g == 2) ? Ul[k * 768 + 512 + j]
          : (g == 3) ? Fll[k * 256 + j]
                     : Frl[k * 256 + j];
    } else {
        int kr = k - 256;
        v = (g == 0) ? Ur[kr * 768 + j]
          : (g == 1) ? Ur[kr * 768 + 256 + j]
          : (g == 2) ? Ur[kr * 768 + 512 + j]
          : (g == 3) ? Flr[kr * 256 + j]
                     : Frr[kr * 256 + j];
    }
    g_UBH[idx] = __float2half_rn(v);
}

// ---------------- tensorized x-projection: g_x = X @ W + b ----------------
// grid (512 mtiles, 4 ntiles), 512 threads; tile 128 rows x 256 cols, K=320
__global__ __launch_bounds__(512, 1) void k_xgemm_mma(const float* __restrict__ X) {
    __shared__ __align__(16) char xs[32768];   // AH 16K | AL 16K
    int mt = blockIdx.x, nt = blockIdx.y;
    int tid = threadIdx.x;
    int warp = tid >> 5, lane = tid & 31;
    int warpM = warp & 3, warpN = warp >> 2;
    uint32_t sb = smem_u32(xs);

    int arow = tid >> 2, aq = tid & 3;
    int b0 = arow * 128 + aq * 32;
    int s0 = b0 ^ ((b0 >> 3) & 0x70);
    int s1 = (b0 + 16) ^ (((b0 + 16) >> 3) & 0x70);
    const float* xrow = X + (size_t)(mt * 128 + arow) * NE;

    float acc[2][8][4];
#pragma unroll
    for (int m = 0; m < 2; m++)
#pragma unroll
        for (int f = 0; f < 8; f++)
#pragma unroll
            for (int i = 0; i < 4; i++) acc[m][f][i] = 0.0f;

    int r0 = warpM * 32 + (lane & 15);
    int r1 = r0 + 16;
    int segb = ((lane >> 4) & 1) * 16;
    int lanepart = (lane >> 2) * 16 + (lane & 3) * 4;
    int nbase = (nt * 256 + warpN * 64) * 16 + lanepart;

    float v[16];
    // load chunk 0
    {
        int k0 = aq * 16;
#pragma unroll
        for (int i = 0; i < 4; i++) *(float4*)&v[i * 4] = *(const float4*)(xrow + k0 + i * 4);
    }

    for (int kc = 0; kc < 5; kc++) {
        __syncthreads();
        // store staged regs as hi/lo fp16
        {
            uint4 ph, pl;
            uint32_t* hp = (uint32_t*)&ph;
            uint32_t* lp = (uint32_t*)&pl;
#pragma unroll
            for (int p = 0; p < 4; p++) {
                float a = v[2 * p], b = v[2 * p + 1];
                __half ha = __float2half_rn(a), hb = __float2half_rn(b);
                hp[p] = packh2(a, b);
                lp[p] = packh2(a - __half2float(ha), b - __half2float(hb));
            }
            *(uint4*)(xs + s0) = ph;
            *(uint4*)(xs + 16384 + s0) = pl;
#pragma unroll
            for (int p = 0; p < 4; p++) {
                float a = v[8 + 2 * p], b = v[8 + 2 * p + 1];
                __half ha = __float2half_rn(a), hb = __float2half_rn(b);
                hp[p] = packh2(a, b);
                lp[p] = packh2(a - __half2float(ha), b - __half2float(hb));
            }
            *(uint4*)(xs + s1) = ph;
            *(uint4*)(xs + 16384 + s1) = pl;
        }
        __syncthreads();
        // prefetch next chunk into regs (overlaps MMA below)
        if (kc < 4) {
            int k0 = (kc + 1) * 64 + aq * 16;
            if (k0 + 15 < NE) {
#pragma unroll
                for (int i = 0; i < 4; i++) *(float4*)&v[i * 4] = *(const float4*)(xrow + k0 + i * 4);
            } else {
#pragma unroll
                for (int i = 0; i < 16; i++) v[i] = (k0 + i < NE) ? xrow[k0 + i] : 0.0f;
            }
        }
        // MMA over 4 k16 steps
#pragma unroll
        for (int s = 0; s < 4; s++) {
            uint32_t ah0[4], ah1[4], al0[4], al1[4];
            {
                int o = r0 * 128 + s * 32 + segb; o ^= ((o >> 3) & 0x70);
                ldsm4(ah0, sb + o); ldsm4(al0, sb + 16384 + o);
            }
            {
                int o = r1 * 128 + s * 32 + segb; o ^= ((o >> 3) & 0x70);
                ldsm4(ah1, sb + o); ldsm4(al1, sb + 16384 + o);
            }
            const __half* pb = g_Wp + (size_t)(kc * 4 + s) * 16384 + nbase;
#pragma unroll
            for (int f = 0; f < 8; f++) {
                uint2 bh = *(const uint2*)(pb + f * 128);
                MMA(acc[0][f], ah0, bh.x, bh.y);
                MMA(acc[1][f], ah1, bh.x, bh.y);
                MMA(acc[0][f], al0, bh.x, bh.y);
                MMA(acc[1][f], al1, bh.x, bh.y);
            }
        }
    }

    // epilogue: bias + direct float2 stores
    int rg = lane >> 2, c2 = (lane & 3) * 2;
#pragma unroll
    for (int f = 0; f < 8; f++) {
        int col = nt * 256 + warpN * 64 + f * 8 + c2;
        float2 bb = *(const float2*)&g_bias[col];
#pragma unroll
        for (int m = 0; m < 2; m++) {
            int row = mt * 128 + warpM * 32 + m * 16 + rg;
            *(float2*)&g_x[(size_t)row * XN + col] =
                make_float2(acc[m][f][0] + bb.x, acc[m][f][1] + bb.y);
            *(float2*)&g_x[(size_t)(row + 8) * XN + col] =
                make_float2(acc[m][f][2] + bb.x, acc[m][f][3] + bb.y);
        }
    }
}

// ---------------- winner / compact (precomputed for all steps) ----------------
__global__ void k_winner(int t, const int* __restrict__ td) {
    int idx = blockIdx.x * blockDim.x + threadIdx.x;
    if (idx >= NROWS) return;
    int b = idx >> 11, s = idx & 2047;
    int d = td[b * (NT * NS) + t * NS + s];
    atomicMax(&g_winner[(b << 11) + d], t * 2048 + s);
}

__global__ void k_compact(int t, const int* __restrict__ td) {
    __shared__ int scnt, sbase;
    int tid = threadIdx.x;
    if (tid == 0) scnt = 0;
    __syncthreads();
    int idx = blockIdx.x * blockDim.x + tid;
    int b = idx >> 11, s = idx & 2047;
    int d = td[b * (NT * NS) + t * NS + s];
    int dd = (b << 11) + d;
    bool win = (d != 0) && (g_winner[dd] == t * 2048 + s);
    int pos = 0;
    if (win) pos = atomicAdd(&scnt, 1);
    __syncthreads();
    if (tid == 0) sbase = atomicAdd(&g_cnt[t], scnt);
    __syncthreads();
    if (win) {
        g_work[t * NROWS + sbase + pos] = idx;
        atomicOr(&g_wmask[dd], 1u << t);
    }
}

// ---------------- fused step: fp16 2-pass mma GEMM + copy role ----------------
// grid = (8, 576): y<512 gemm tiles, y>=512 copy CTAs. 512 threads.
__global__ __launch_bounds__(512, 1) void k_step_mma(
    int t, int final,
    const int* __restrict__ td, const int* __restrict__ tl, const int* __restrict__ tr,
    const __half* __restrict__ hh, const __half* __restrict__ hl,
    const float* __restrict__ ccur,
    __half* __restrict__ hhn, __half* __restrict__ hln,
    float* __restrict__ cnn, float* __restrict__ oh, float* __restrict__ oc)
{
    extern __shared__ char smem[];
    int tid = threadIdx.x;

    if (blockIdx.y >= 512) {
        // ---------------- copy role ----------------
        int cid = (blockIdx.y - 512) * gridDim.x + blockIdx.x;   // 0..511
        int row = cid * 128 + (tid >> 2);
        int q = tid & 3;
        size_t ro = ((size_t)row << 8) + q * 64;
        int d = row & 2047;
        if (d == 0) {
            uint4 z = make_uint4(0, 0, 0, 0);
            uint4* dh = (uint4*)(hhn + ro);
            uint4* dl = (uint4*)(hln + ro);
            uint4* dc = (uint4*)(cnn + ro);
#pragma unroll
            for (int i = 0; i < 8; i++) { dh[i] = z; dl[i] = z; }
#pragma unroll
            for (int i = 0; i < 16; i++) dc[i] = z;
            if (final) {
                uint4* po = (uint4*)(oh + ro);
                uint4* pc = (uint4*)(oc + ro);
#pragma unroll
                for (int i = 0; i < 16; i++) { po[i] = z; pc[i] = z; }
            }
            return;
        }
        if ((g_wmask[row] >> t) & 1u) return;   // winner wrote it
        const uint4* sh = (const uint4*)(hh + ro);
        const uint4* sl = (const uint4*)(hl + ro);
        const uint4* sc = (const uint4*)(ccur + ro);
        uint4* dh = (uint4*)(hhn + ro);
        uint4* dl = (uint4*)(hln + ro);
        uint4* dc = (uint4*)(cnn + ro);
#pragma unroll
        for (int i = 0; i < 8; i++) { dh[i] = sh[i]; dl[i] = sl[i]; }
#pragma unroll
        for (int i = 0; i < 16; i++) dc[i] = sc[i];
        if (final) {
            const __half2* ph = (const __half2*)(hh + ro);
            const __half2* pl = (const __half2*)(hl + ro);
            float* po = oh + ro;
            float* pc = oc + ro;
#pragma unroll
            for (int i = 0; i < 32; i++) {
                float2 a = __half22float2(ph[i]);
                float2 b = __half22float2(pl[i]);
                *(float2*)(po + 2 * i) = make_float2(a.x + b.x, a.y + b.y);
            }
            const float4* cs = (const float4*)(ccur + ro);
#pragma unroll
            for (int i = 0; i < 16; i++) ((float4*)pc)[i] = cs[i];
        }
        return;
    }

    // ---------------- gemm role ----------------
    int count = g_cnt[t];
    int mt = blockIdx.y;
    if (mt * BM >= count) return;
    int nt = blockIdx.x;
    const int* work = g_work + t * NROWS;

    int* sL = (int*)(smem + OFF_IDX);
    int* sR = (int*)(smem + OFF_IDX + 512);
    int* sD = (int*)(smem + OFF_IDX + 1024);
    int* sRow = (int*)(smem + OFF_IDX + 1536);

    if (tid < BM) {
        int m = mt * BM + tid;
        if (m < count) {
            int idx = work[m];
            int b = idx >> 11, s = idx & 2047;
            int tb = b * (NT * NS) + t * NS + s;
            int brow = b << 11;
            sL[tid] = (brow + tl[tb]) << 8;
            sR[tid] = (brow + tr[tb]) << 8;
            sD[tid] = (brow + td[tb]) << 8;
            sRow[tid] = idx;
        } else {
            sL[tid] = 0; sR[tid] = 0; sD[tid] = -1; sRow[tid] = 0;
        }
    }
    __syncthreads();

    uint32_t sb = smem_u32(smem);
    int arow = tid >> 2, aq = tid & 3;
    int offL = sL[arow], offR = sR[arow];
    int b0 = arow * 128 + aq * 32;
    int b1 = b0 + 16;
    int s0 = b0 ^ ((b0 >> 3) & 0x70);
    int s1 = b1 ^ ((b1 >> 3) & 0x70);
    const uint32_t offAH[2] = {OFF_AH0, OFF_AH1};
    const uint32_t offAL[2] = {OFF_AL0, OFF_AL1};

    // stage chunk 0 (h_l, k0=0)
    {
        const __half* ph = hh + offL + aq * 16;
        const __half* pl = hl + offL + aq * 16;
        cp16(sb + OFF_AH0 + s0, ph);  cp16(sb + OFF_AH0 + s1, ph + 8);
        cp16(sb + OFF_AL0 + s0, pl);  cp16(sb + OFF_AL0 + s1, pl + 8);
        CP_COMMIT;
    }

    int warp = tid >> 5, lane = tid & 31;
    int warpM = warp & 3, warpN = warp >> 2;

    float acc[2][5][4];
#pragma unroll
    for (int m = 0; m < 2; m++)
#pragma unroll
        for (int f = 0; f < 5; f++)
#pragma unroll
            for (int i = 0; i < 4; i++) acc[m][f][i] = 0.0f;

    int r0 = warpM * 32 + (lane & 15);
    int r1 = r0 + 16;
    int segb = ((lane >> 4) & 1) * 16;

    int tilesel = nt * 2 + (warpN >> 1);
    const __half* pbh = g_UBH + (size_t)tilesel * UB_NT_STRIDE;
    int lanepart = (lane >> 2) * 16 + (lane & 3) * 4;
    int warppart = (warpN & 1) * 640;

    for (int kc = 0; kc < 8; kc++) {
        if (kc < 7) {
            int kcn = kc + 1;
            int nb = kcn & 1;
            int off = (kcn < 4) ? offL : offR;
            int k0 = (kcn & 3) * 64;
            const __half* ph = hh + off + k0 + aq * 16;
            const __half* pl = hl + off + k0 + aq * 16;
            cp16(sb + offAH[nb] + s0, ph);  cp16(sb + offAH[nb] + s1, ph + 8);
            cp16(sb + offAL[nb] + s0, pl);  cp16(sb + offAL[nb] + s1, pl + 8);
            CP_COMMIT;
            CP_WAIT1;
        } else {
            CP_WAIT0;
        }
        __syncthreads();

        uint32_t abh = sb + offAH[kc & 1];
        uint32_t abl = sb + offAL[kc & 1];
#pragma unroll
        for (int s = 0; s < 4; s++) {
            uint32_t ah0[4], ah1[4], al0[4], al1[4];
            {
                int o = r0 * 128 + s * 32 + segb; o ^= ((o >> 3) & 0x70);
                ldsm4(ah0, abh + o); ldsm4(al0, abl + o);
            }
            {
                int o = r1 * 128 + s * 32 + segb; o ^= ((o >> 3) & 0x70);
                ldsm4(ah1, abh + o); ldsm4(al1, abl + o);
            }
            int be = (kc * 4 + s) * 1280 + warppart + lanepart;
#pragma unroll
            for (int f = 0; f < 5; f++) {
                uint2 bh = *(const uint2*)(pbh + be + f * 128);
                MMA(acc[0][f], ah0, bh.x, bh.y);
                MMA(acc[1][f], ah1, bh.x, bh.y);
                MMA(acc[0][f], al0, bh.x, bh.y);
                MMA(acc[1][f], al1, bh.x, bh.y);
            }
        }
        __syncthreads();
    }

    // epilogue: transpose acc through smem, fuse activations
    float* stg = (float*)(smem + OFF_STAGE);
    {
        int rg = lane >> 2, cl = 2 * (lane & 3);
#pragma unroll
        for (int m = 0; m < 2; m++) {
#pragma unroll
            for (int f = 0; f < 5; f++) {
                int row = warpM * 32 + m * 16 + rg;
                int col = warpN * 40 + f * 8 + cl;
                *(float2*)&stg[row * 164 + col] = make_float2(acc[m][f][0], acc[m][f][1]);
                *(float2*)&stg[(row + 8) * 164 + col] = make_float2(acc[m][f][2], acc[m][f][3]);
            }
        }
    }
    __syncthreads();

    {
        int row = arow, ug = aq;
        int j0 = nt * 32;
        int od = sD[row];
        const float* xp = g_x + (size_t)sRow[row] * XN + (size_t)(j0 + ug * 8) * 4;
        const float* clp = ccur + offL + j0 + ug * 8;
        const float* crp = ccur + offR + j0 + ug * 8;
        float clv[8], crv[8], ho[8], co[8];
        *(float4*)&clv[0] = *(const float4*)clp;
        *(float4*)&clv[4] = *(const float4*)(clp + 4);
        *(float4*)&crv[0] = *(const float4*)crp;
        *(float4*)&crv[4] = *(const float4*)(crp + 4);
#pragma unroll
        for (int u = 0; u < 8; u++) {
            int col = (ug * 8 + u) * 5;
            float a_i  = stg[row * 164 + col + 0];
            float a_o  = stg[row * 164 + col + 1];
            float a_u  = stg[row * 164 + col + 2];
            float a_fl = stg[row * 164 + col + 3];
            float a_fr = stg[row * 164 + col + 4];
            float4 xv = ((const float4*)xp)[u];
            float gi = sigm(a_i + xv.x);
            float go = sigm(a_o + xv.y);
            float gu = tanhf(a_u + xv.z);
            float fl = sigm(a_fl + xv.w);
            float fr = sigm(a_fr + xv.w);
            float cnew = gi * gu + fl * clv[u] + fr * crv[u];
            ho[u] = go * tanhf(cnew);
            co[u] = cnew;
        }
        if (od >= 0) {
            uint32_t hw[4], lw[4];
#pragma unroll
            for (int p = 0; p < 4; p++) {
                float v0 = ho[2 * p], v1 = ho[2 * p + 1];
                __half a = __float2half_rn(v0);
                __half b = __float2half_rn(v1);
                hw[p] = packh2(v0, v1);
                lw[p] = packh2(v0 - __half2float(a), v1 - __half2float(b));
            }
            int eo = od + j0 + ug * 8;
            *(uint4*)(hhn + eo) = make_uint4(hw[0], hw[1], hw[2], hw[3]);
            *(uint4*)(hln + eo) = make_uint4(lw[0], lw[1], lw[2], lw[3]);
            *(float4*)(cnn + eo) = *(float4*)&co[0];
            *(float4*)(cnn + eo + 4) = *(float4*)&co[4];
            if (final) {
                *(float4*)(oh + eo) = *(float4*)&ho[0];
                *(float4*)(oh + eo + 4) = *(float4*)&ho[4];
                *(float4*)(oc + eo) = *(float4*)&co[0];
                *(float4*)(oc + eo + 4) = *(float4*)&co[4];
            }
        }
    }
}

// ---------------- h_root ----------------
__global__ void k_root(const int* __restrict__ td, const float* __restrict__ out_h,
                       float* __restrict__ out_root) {
    __shared__ int red[256];
    int b = blockIdx.x, tid = threadIdx.x;
    int v = 0;
    for (int s = tid; s < NS; s += 256) v = max(v, td[b * (NT * NS) + (NT - 1) * NS + s]);
    red[tid] = v;
    __syncthreads();
    for (int off = 128; off > 0; off >>= 1) {
        if (tid < off) red[tid] = max(red[tid], red[tid + off]);
        __syncthreads();
    }
    int root = red[0];
    out_root[b * NH + tid] = out_h[(((size_t)(b << 11)) + root) * NH + tid];
}

// ---------------- host launcher (graph-capturable) ----------------
extern "C" void kernel_launch(void* const* d_in, const int* in_sizes, int n_in,
                              void* d_out, int out_size) {
    const float* X     = (const float*)d_in[0];
    const int*   td    = (const int*)d_in[1];
    const int*   tr    = (const int*)d_in[2];
    const int*   tl    = (const int*)d_in[3];
    const float* W_iou = (const float*)d_in[4];
    const float* b_iou = (const float*)d_in[5];
    const float* U_l   = (const float*)d_in[6];
    const float* U_r   = (const float*)d_in[7];
    const float* W_f   = (const float*)d_in[8];
    const float* b_f   = (const float*)d_in[9];
    const float* F_ll  = (const float*)d_in[10];
    const float* F_lr  = (const float*)d_in[11];
    const float* F_rl  = (const float*)d_in[12];
    const float* F_rr  = (const float*)d_in[13];

    float* out      = (float*)d_out;
    float* out_h    = out;
    float* out_c    = out + (size_t)HCNT;
    float* out_root = out + 2 * (size_t)HCNT;

    __half *hhb = nullptr, *hlb = nullptr;
    float* cb = nullptr;
    cudaGetSymbolAddress((void**)&hhb, g_hh);
    cudaGetSymbolAddress((void**)&hlb, g_hl);
    cudaGetSymbolAddress((void**)&cb, g_c);

    static int attr_done = 0;
    if (!attr_done) {
        cudaFuncSetAttribute(k_step_mma, cudaFuncAttributeMaxDynamicSharedMemorySize, SMEM_DYN);
        attr_done = 1;
    }

    k_init<<<4096, 256>>>();
    k_pack_wp<<<(WP_TOTAL + 255) / 256, 256>>>(W_iou, b_iou, W_f, b_f);
    k_pack_ub<<<(UB_TOTAL + 255) / 256, 256>>>(U_l, U_r, F_ll, F_lr, F_rl, F_rr);
    k_xgemm_mma<<<dim3(512, 4), 512>>>(X);

    // precompute all winner/compact passes (sequential: winner(t) then compact(t))
    for (int t = 0; t < NT; t++) {
        k_winner<<<NROWS / 256, 256>>>(t, td);
        k_compact<<<NROWS / 256, 256>>>(t, td);
    }

    int cur = 0;
    for (int t = 0; t < NT; t++) {
        int fin = (t == NT - 1) ? 1 : 0;
        const __half* hhc = hhb + (size_t)cur * HCNT;
        const __half* hlc = hlb + (size_t)cur * HCNT;
        const float*  ccc = cb + (size_t)cur * HCNT;
        __half* hhn = hhb + (size_t)(1 - cur) * HCNT;
        __half* hln = hlb + (size_t)(1 - cur) * HCNT;
        float*  cnn = cb + (size_t)(1 - cur) * HCNT;
        k_step_mma<<<dim3(NTL, 576), 512, SMEM_DYN>>>(
            t, fin, td, tl, tr, hhc, hlc, ccc, hhn, hln, cnn, out_h, out_c);
        cur ^= 1;
    }
    k_root<<<NB, 256>>>(td, out_h, out_root);
}

// round 10
// speedup vs baseline: 5.0086x; 1.2908x over previous
#include <cuda_runtime.h>
#include <cuda_fp16.h>
#include <math.h>
#include <stdint.h>

// ---------------- problem constants ----------------
#define NB 32
#define NS 2048
#define NE 300
#define NH 256
#define NT 24
#define NROWS 65536            // NB*NS
#define XN 1024                 // x-gates per row: j*4 + {i,o,u,f}
#define HCNT 16777216           // NROWS*NH

// ---------------- step-GEMM tiling ----------------
#define BM 128                  // rows per CTA
#define NTL 8                   // 1280 / 160 n-tiles
#define UB_NT_STRIDE 40960      // fp16 elems per 80-col packed tile (8 kchunks)
#define UB_TOTAL (16 * UB_NT_STRIDE)
#define WP_TOTAL (20 * 16384)   // W pack: 20 kcs * 1024 cols * 16

// ---------------- k_step dynamic smem (bytes) ------
#define OFF_IDX   0             // sL/sR/sD/sRow: 4 * 512
#define OFF_AH0   2048          // 128 x 64 fp16 = 16384
#define OFF_AH1   18432
#define OFF_STAGE 2048          // 128 x 164 f32 (reuses A buffers)
#define SMEM_DYN  86016

// ---------------- device scratch -------------------
__device__ float g_x[(size_t)NROWS * XN];     // 256 MiB packed x-gates
__device__ __half g_Wp[WP_TOTAL];             // W fragment-native fp16 hi
__device__ float g_bias[XN];
__device__ __half g_UBH[UB_TOTAL];            // U fragment-native fp16 hi
__device__ __half g_hh[2 * (size_t)HCNT];     // h hi state (ping-pong)
__device__ __half g_hl[2 * (size_t)HCNT];     // h lo state
__device__ float g_c[2 * (size_t)HCNT];       // c state fp32
__device__ int      g_win[NT * NROWS];        // per-step winner s for each (b,d)
__device__ uint32_t g_wmask[NROWS];           // bit t: row won at step t
__device__ int      g_work[NT * NROWS];       // per-step compacted winner lists
__device__ int      g_cnt[NT];

__device__ __forceinline__ float sigm(float x) { return 1.0f / (1.0f + __expf(-x)); }

__device__ __forceinline__ uint32_t smem_u32(const void* p) {
    uint32_t r;
    asm("{ .reg .u64 t; cvta.to.shared.u64 t, %1; cvt.u32.u64 %0, t; }" : "=r"(r) : "l"(p));
    return r;
}
__device__ __forceinline__ void ldsm4(uint32_t* r, uint32_t addr) {
    asm volatile("ldmatrix.sync.aligned.m8n8.x4.shared.b16 {%0,%1,%2,%3}, [%4];"
                 : "=r"(r[0]), "=r"(r[1]), "=r"(r[2]), "=r"(r[3]) : "r"(addr));
}
#define MMA(d, a, bx, by) asm volatile( \
    "mma.sync.aligned.m16n8k16.row.col.f32.f16.f16.f32 " \
    "{%0,%1,%2,%3},{%4,%5,%6,%7},{%8,%9},{%0,%1,%2,%3};" \
    : "+f"((d)[0]), "+f"((d)[1]), "+f"((d)[2]), "+f"((d)[3]) \
    : "r"((a)[0]), "r"((a)[1]), "r"((a)[2]), "r"((a)[3]), "r"(bx), "r"(by))

__device__ __forceinline__ void cp16(uint32_t dst, const void* src) {
    asm volatile("{\n\t.reg .u64 g;\n\tcvta.to.global.u64 g, %1;\n\t"
                 "cp.async.cg.shared.global [%0], [g], 16;\n\t}"
                 :: "r"(dst), "l"(src) : "memory");
}
#define CP_COMMIT asm volatile("cp.async.commit_group;" ::: "memory")
#define CP_WAIT1  asm volatile("cp.async.wait_group 1;" ::: "memory")
#define CP_WAIT0  asm volatile("cp.async.wait_group 0;" ::: "memory")

__device__ __forceinline__ uint32_t packh2(float a, float b) {
    __half2 v = __floats2half2_rn(a, b);
    return *(uint32_t*)&v;
}

// ---------------- init ----------------
__global__ void k_init() {
    size_t i = (size_t)blockIdx.x * blockDim.x + threadIdx.x;
    size_t stride = (size_t)gridDim.x * blockDim.x;
    uint32_t* ph = (uint32_t*)g_hh;
    uint32_t* pl = (uint32_t*)g_hl;
    for (size_t p = i; p < (size_t)(HCNT / 2); p += stride) { ph[p] = 0u; pl[p] = 0u; }
    for (size_t p = i; p < (size_t)HCNT; p += stride) g_c[p] = 0.0f;
    for (size_t p = i; p < (size_t)(NT * NROWS); p += stride) g_win[p] = -1;
    for (size_t p = i; p < (size_t)NROWS; p += stride) g_wmask[p] = 0u;
    if (i < NT) g_cnt[i] = 0;
}

// ---- pack W: fragment-native fp16 hi; also bias ----
__global__ void k_pack_wp(const float* __restrict__ W_iou, const float* __restrict__ b_iou,
                          const float* __restrict__ W_f,   const float* __restrict__ b_f) {
    int idx = blockIdx.x * blockDim.x + threadIdx.x;
    if (idx < WP_TOTAL) {
        int kcs = idx >> 14;
        int rem = idx & 16383;
        int ncol = rem >> 4, low = rem & 15;
        int c = low >> 2, e = low & 3;
        int kin = (e < 2) ? (2 * c + e) : (8 + 2 * c + (e - 2));
        int k = (kcs >> 2) * 64 + (kcs & 3) * 16 + kin;
        int j = ncol >> 2, g = ncol & 3;
        float v = 0.0f;
        if (k < NE) v = (g < 3) ? W_iou[k * 768 + g * 256 + j] : W_f[k * 256 + j];
        g_Wp[idx] = __float2half_rn(v);
    }
    if (idx < XN) {
        int j = idx >> 2, g = idx & 3;
        g_bias[idx] = (g < 3) ? b_iou[g * 256 + j] : b_f[j];
    }
}

// ---- pack U: fragment-native fp16 hi (16 tiles of 80 cols) ----
__global__ void k_pack_ub(const float* __restrict__ Ul, const float* __restrict__ Ur,
                          const float* __restrict__ Fll, const float* __restrict__ Flr,
                          const float* __restrict__ Frl, const float* __restrict__ Frr) {
    int idx = blockIdx.x * blockDim.x + threadIdx.x;
    if (idx >= UB_TOTAL) return;
    int e = idx & 3, c = (idx >> 2) & 3;
    int n = (idx >> 4) % 80;
    int q = (idx >> 4) / 80;           // ntl*32 + kc*4 + s
    int s = q & 3, kc = (q >> 2) & 7, ntl = q >> 5;
    int kin = (e < 2) ? (2 * c + e) : (8 + 2 * c + (e - 2));
    int k = kc * 64 + s * 16 + kin;
    int ncol = ntl * 80 + n;
    int j = ncol / 5, g = ncol - 5 * j;
    float v;
    if (k < 256) {
        v = (g == 0) ? Ul[k * 768 + j]
          : (g == 1) ? Ul[k * 768 + 256 + j]
          : (g == 2) ? Ul[k * 768 + 512 + j]
          : (g == 3) ? Fll[k * 256 + j]
                     : Frl[k * 256 + j];
    } else {
        int kr = k - 256;
        v = (g == 0) ? Ur[kr * 768 + j]
          : (g == 1) ? Ur[kr * 768 + 256 + j]
          : (g == 2) ? Ur[kr * 768 + 512 + j]
          : (g == 3) ? Flr[kr * 256 + j]
                     : Frr[kr * 256 + j];
    }
    g_UBH[idx] = __float2half_rn(v);
}

// ---------------- tensorized x-projection: g_x = X @ W + b ----------------
__global__ __launch_bounds__(512, 1) void k_xgemm_mma(const float* __restrict__ X) {
    __shared__ __align__(16) char xs[32768];   // AH 16K | AL 16K
    int mt = blockIdx.x, nt = blockIdx.y;
    int tid = threadIdx.x;
    int warp = tid >> 5, lane = tid & 31;
    int warpM = warp & 3, warpN = warp >> 2;
    uint32_t sb = smem_u32(xs);

    int arow = tid >> 2, aq = tid & 3;
    int b0 = arow * 128 + aq * 32;
    int s0 = b0 ^ ((b0 >> 3) & 0x70);
    int s1 = (b0 + 16) ^ (((b0 + 16) >> 3) & 0x70);
    const float* xrow = X + (size_t)(mt * 128 + arow) * NE;

    float acc[2][8][4];
#pragma unroll
    for (int m = 0; m < 2; m++)
#pragma unroll
        for (int f = 0; f < 8; f++)
#pragma unroll
            for (int i = 0; i < 4; i++) acc[m][f][i] = 0.0f;

    int r0 = warpM * 32 + (lane & 15);
    int r1 = r0 + 16;
    int segb = ((lane >> 4) & 1) * 16;
    int lanepart = (lane >> 2) * 16 + (lane & 3) * 4;
    int nbase = (nt * 256 + warpN * 64) * 16 + lanepart;

    float v[16];
    {
        int k0 = aq * 16;
#pragma unroll
        for (int i = 0; i < 4; i++) *(float4*)&v[i * 4] = *(const float4*)(xrow + k0 + i * 4);
    }

    for (int kc = 0; kc < 5; kc++) {
        __syncthreads();
        {
            uint4 ph, pl;
            uint32_t* hp = (uint32_t*)&ph;
            uint32_t* lp = (uint32_t*)&pl;
#pragma unroll
            for (int p = 0; p < 4; p++) {
                float a = v[2 * p], b = v[2 * p + 1];
                __half ha = __float2half_rn(a), hb = __float2half_rn(b);
                hp[p] = packh2(a, b);
                lp[p] = packh2(a - __half2float(ha), b - __half2float(hb));
            }
            *(uint4*)(xs + s0) = ph;
            *(uint4*)(xs + 16384 + s0) = pl;
#pragma unroll
            for (int p = 0; p < 4; p++) {
                float a = v[8 + 2 * p], b = v[8 + 2 * p + 1];
                __half ha = __float2half_rn(a), hb = __float2half_rn(b);
                hp[p] = packh2(a, b);
                lp[p] = packh2(a - __half2float(ha), b - __half2float(hb));
            }
            *(uint4*)(xs + s1) = ph;
            *(uint4*)(xs + 16384 + s1) = pl;
        }
        __syncthreads();
        if (kc < 4) {
            int k0 = (kc + 1) * 64 + aq * 16;
            if (k0 + 15 < NE) {
#pragma unroll
                for (int i = 0; i < 4; i++) *(float4*)&v[i * 4] = *(const float4*)(xrow + k0 + i * 4);
            } else {
#pragma unroll
                for (int i = 0; i < 16; i++) v[i] = (k0 + i < NE) ? xrow[k0 + i] : 0.0f;
            }
        }
#pragma unroll
        for (int s = 0; s < 4; s++) {
            uint32_t ah0[4], ah1[4], al0[4], al1[4];
            {
                int o = r0 * 128 + s * 32 + segb; o ^= ((o >> 3) & 0x70);
                ldsm4(ah0, sb + o); ldsm4(al0, sb + 16384 + o);
            }
            {
                int o = r1 * 128 + s * 32 + segb; o ^= ((o >> 3) & 0x70);
                ldsm4(ah1, sb + o); ldsm4(al1, sb + 16384 + o);
            }
            const __half* pb = g_Wp + (size_t)(kc * 4 + s) * 16384 + nbase;
#pragma unroll
            for (int f = 0; f < 8; f++) {
                uint2 bh = *(const uint2*)(pb + f * 128);
                MMA(acc[0][f], ah0, bh.x, bh.y);
                MMA(acc[1][f], ah1, bh.x, bh.y);
                MMA(acc[0][f], al0, bh.x, bh.y);
                MMA(acc[1][f], al1, bh.x, bh.y);
            }
        }
    }

    int rg = lane >> 2, c2 = (lane & 3) * 2;
#pragma unroll
    for (int f = 0; f < 8; f++) {
        int col = nt * 256 + warpN * 64 + f * 8 + c2;
        float2 bb = *(const float2*)&g_bias[col];
#pragma unroll
        for (int m = 0; m < 2; m++) {
            int row = mt * 128 + warpM * 32 + m * 16 + rg;
            *(float2*)&g_x[(size_t)row * XN + col] =
                make_float2(acc[m][f][0] + bb.x, acc[m][f][1] + bb.y);
            *(float2*)&g_x[(size_t)(row + 8) * XN + col] =
                make_float2(acc[m][f][2] + bb.x, acc[m][f][3] + bb.y);
        }
    }
}

// ---------------- winner/compact: ALL steps in 2 launches ----------------
__global__ void k_winner_all(const int* __restrict__ td) {
    int t = blockIdx.y;
    int idx = blockIdx.x * blockDim.x + threadIdx.x;
    int b = idx >> 11, s = idx & 2047;
    int d = td[b * (NT * NS) + t * NS + s];
    atomicMax(&g_win[t * NROWS + (b << 11) + d], s);
}

__global__ void k_compact_all(const int* __restrict__ td) {
    __shared__ int scnt, sbase;
    int t = blockIdx.y;
    int tid = threadIdx.x;
    if (tid == 0) scnt = 0;
    __syncthreads();
    int idx = blockIdx.x * blockDim.x + tid;
    int b = idx >> 11, s = idx & 2047;
    int d = td[b * (NT * NS) + t * NS + s];
    int dd = (b << 11) + d;
    bool win = (d != 0) && (g_win[t * NROWS + dd] == s);
    int pos = 0;
    if (win) pos = atomicAdd(&scnt, 1);
    __syncthreads();
    if (tid == 0) sbase = atomicAdd(&g_cnt[t], scnt);
    __syncthreads();
    if (win) {
        g_work[t * NROWS + sbase + pos] = idx;
        atomicOr(&g_wmask[dd], 1u << t);
    }
}

// ---------------- fused step: single-pass fp16 mma GEMM + copy role ----------------
// grid = (8, 576): y<512 gemm tiles, y>=512 copy CTAs. 512 threads.
__global__ __launch_bounds__(512, 1) void k_step_mma(
    int t, int final,
    const int* __restrict__ td, const int* __restrict__ tl, const int* __restrict__ tr,
    const __half* __restrict__ hh, const __half* __restrict__ hl,
    const float* __restrict__ ccur,
    __half* __restrict__ hhn, __half* __restrict__ hln,
    float* __restrict__ cnn, float* __restrict__ oh, float* __restrict__ oc)
{
    extern __shared__ char smem[];
    int tid = threadIdx.x;

    if (blockIdx.y >= 512) {
        // ---------------- copy role ----------------
        int cid = (blockIdx.y - 512) * gridDim.x + blockIdx.x;   // 0..511
        int row = cid * 128 + (tid >> 2);
        int q = tid & 3;
        size_t ro = ((size_t)row << 8) + q * 64;
        int d = row & 2047;
        if (d == 0) {
            uint4 z = make_uint4(0, 0, 0, 0);
            uint4* dh = (uint4*)(hhn + ro);
            uint4* dl = (uint4*)(hln + ro);
            uint4* dc = (uint4*)(cnn + ro);
#pragma unroll
            for (int i = 0; i < 8; i++) { dh[i] = z; dl[i] = z; }
#pragma unroll
            for (int i = 0; i < 16; i++) dc[i] = z;
            if (final) {
                uint4* po = (uint4*)(oh + ro);
                uint4* pc = (uint4*)(oc + ro);
#pragma unroll
                for (int i = 0; i < 16; i++) { po[i] = z; pc[i] = z; }
            }
            return;
        }
        if ((g_wmask[row] >> t) & 1u) return;   // winner wrote it
        const uint4* sh = (const uint4*)(hh + ro);
        const uint4* sl = (const uint4*)(hl + ro);
        const uint4* sc = (const uint4*)(ccur + ro);
        uint4* dh = (uint4*)(hhn + ro);
        uint4* dl = (uint4*)(hln + ro);
        uint4* dc = (uint4*)(cnn + ro);
#pragma unroll
        for (int i = 0; i < 8; i++) { dh[i] = sh[i]; dl[i] = sl[i]; }
#pragma unroll
        for (int i = 0; i < 16; i++) dc[i] = sc[i];
        if (final) {
            const __half2* ph = (const __half2*)(hh + ro);
            const __half2* pl = (const __half2*)(hl + ro);
            float* po = oh + ro;
            float* pc = oc + ro;
#pragma unroll
            for (int i = 0; i < 32; i++) {
                float2 a = __half22float2(ph[i]);
                float2 b = __half22float2(pl[i]);
                *(float2*)(po + 2 * i) = make_float2(a.x + b.x, a.y + b.y);
            }
            const float4* cs = (const float4*)(ccur + ro);
#pragma unroll
            for (int i = 0; i < 16; i++) ((float4*)pc)[i] = cs[i];
        }
        return;
    }

    // ---------------- gemm role ----------------
    int count = g_cnt[t];
    int mt = blockIdx.y;
    if (mt * BM >= count) return;
    int nt = blockIdx.x;
    const int* work = g_work + t * NROWS;

    int* sL = (int*)(smem + OFF_IDX);
    int* sR = (int*)(smem + OFF_IDX + 512);
    int* sD = (int*)(smem + OFF_IDX + 1024);
    int* sRow = (int*)(smem + OFF_IDX + 1536);

    if (tid < BM) {
        int m = mt * BM + tid;
        if (m < count) {
            int idx = work[m];
            int b = idx >> 11, s = idx & 2047;
            int tb = b * (NT * NS) + t * NS + s;
            int brow = b << 11;
            sL[tid] = (brow + tl[tb]) << 8;
            sR[tid] = (brow + tr[tb]) << 8;
            sD[tid] = (brow + td[tb]) << 8;
            sRow[tid] = idx;
        } else {
            sL[tid] = 0; sR[tid] = 0; sD[tid] = -1; sRow[tid] = 0;
        }
    }
    __syncthreads();

    uint32_t sb = smem_u32(smem);
    int arow = tid >> 2, aq = tid & 3;
    int offL = sL[arow], offR = sR[arow];
    int b0 = arow * 128 + aq * 32;
    int b1 = b0 + 16;
    int s0 = b0 ^ ((b0 >> 3) & 0x70);
    int s1 = b1 ^ ((b1 >> 3) & 0x70);
    const uint32_t offAH[2] = {OFF_AH0, OFF_AH1};

    // stage chunk 0 (h_l, k0=0)
    {
        const __half* ph = hh + offL + aq * 16;
        cp16(sb + OFF_AH0 + s0, ph);  cp16(sb + OFF_AH0 + s1, ph + 8);
        CP_COMMIT;
    }

    int warp = tid >> 5, lane = tid & 31;
    int warpM = warp & 3, warpN = warp >> 2;

    float acc[2][5][4];
#pragma unroll
    for (int m = 0; m < 2; m++)
#pragma unroll
        for (int f = 0; f < 5; f++)
#pragma unroll
            for (int i = 0; i < 4; i++) acc[m][f][i] = 0.0f;

    int r0 = warpM * 32 + (lane & 15);
    int r1 = r0 + 16;
    int segb = ((lane >> 4) & 1) * 16;

    int tilesel = nt * 2 + (warpN >> 1);
    const __half* pbh = g_UBH + (size_t)tilesel * UB_NT_STRIDE;
    int lanepart = (lane >> 2) * 16 + (lane & 3) * 4;
    int warppart = (warpN & 1) * 640;

    for (int kc = 0; kc < 8; kc++) {
        if (kc < 7) {
            int kcn = kc + 1;
            int nb = kcn & 1;
            int off = (kcn < 4) ? offL : offR;
            int k0 = (kcn & 3) * 64;
            const __half* ph = hh + off + k0 + aq * 16;
            cp16(sb + offAH[nb] + s0, ph);  cp16(sb + offAH[nb] + s1, ph + 8);
            CP_COMMIT;
            CP_WAIT1;
        } else {
            CP_WAIT0;
        }
        __syncthreads();

        uint32_t abh = sb + offAH[kc & 1];
#pragma unroll
        for (int s = 0; s < 4; s++) {
            uint32_t ah0[4], ah1[4];
            {
                int o = r0 * 128 + s * 32 + segb; o ^= ((o >> 3) & 0x70);
                ldsm4(ah0, abh + o);
            }
            {
                int o = r1 * 128 + s * 32 + segb; o ^= ((o >> 3) & 0x70);
                ldsm4(ah1, abh + o);
            }
            int be = (kc * 4 + s) * 1280 + warppart + lanepart;
#pragma unroll
            for (int f = 0; f < 5; f++) {
                uint2 bh = *(const uint2*)(pbh + be + f * 128);
                MMA(acc[0][f], ah0, bh.x, bh.y);
                MMA(acc[1][f], ah1, bh.x, bh.y);
            }
        }
        __syncthreads();
    }

    // epilogue: transpose acc through smem, fuse activations
    float* stg = (float*)(smem + OFF_STAGE);
    {
        int rg = lane >> 2, cl = 2 * (lane & 3);
#pragma unroll
        for (int m = 0; m < 2; m++) {
#pragma unroll
            for (int f = 0; f < 5; f++) {
                int row = warpM * 32 + m * 16 + rg;
                int col = warpN * 40 + f * 8 + cl;
                *(float2*)&stg[row * 164 + col] = make_float2(acc[m][f][0], acc[m][f][1]);
                *(float2*)&stg[(row + 8) * 164 + col] = make_float2(acc[m][f][2], acc[m][f][3]);
            }
        }
    }
    __syncthreads();

    {
        int row = arow, ug = aq;
        int j0 = nt * 32;
        int od = sD[row];
        const float* xp = g_x + (size_t)sRow[row] * XN + (size_t)(j0 + ug * 8) * 4;
        const float* clp = ccur + offL + j0 + ug * 8;
        const float* crp = ccur + offR + j0 + ug * 8;
        float clv[8], crv[8], ho[8], co[8];
        *(float4*)&clv[0] = *(const float4*)clp;
        *(float4*)&clv[4] = *(const float4*)(clp + 4);
        *(float4*)&crv[0] = *(const float4*)crp;
        *(float4*)&crv[4] = *(const float4*)(crp + 4);
#pragma unroll
        for (int u = 0; u < 8; u++) {
            int col = (ug * 8 + u) * 5;
            float a_i  = stg[row * 164 + col + 0];
            float a_o  = stg[row * 164 + col + 1];
            float a_u  = stg[row * 164 + col + 2];
            float a_fl = stg[row * 164 + col + 3];
            float a_fr = stg[row * 164 + col + 4];
            float4 xv = ((const float4*)xp)[u];
            float gi = sigm(a_i + xv.x);
            float go = sigm(a_o + xv.y);
            float gu = tanhf(a_u + xv.z);
            float fl = sigm(a_fl + xv.w);
            float fr = sigm(a_fr + xv.w);
            float cnew = gi * gu + fl * clv[u] + fr * crv[u];
            ho[u] = go * tanhf(cnew);
            co[u] = cnew;
        }
        if (od >= 0) {
            uint32_t hw[4], lw[4];
#pragma unroll
            for (int p = 0; p < 4; p++) {
                float v0 = ho[2 * p], v1 = ho[2 * p + 1];
                __half a = __float2half_rn(v0);
                __half b = __float2half_rn(v1);
                hw[p] = packh2(v0, v1);
                lw[p] = packh2(v0 - __half2float(a), v1 - __half2float(b));
            }
            int eo = od + j0 + ug * 8;
            *(uint4*)(hhn + eo) = make_uint4(hw[0], hw[1], hw[2], hw[3]);
            *(uint4*)(hln + eo) = make_uint4(lw[0], lw[1], lw[2], lw[3]);
            *(float4*)(cnn + eo) = *(float4*)&co[0];
            *(float4*)(cnn + eo + 4) = *(float4*)&co[4];
            if (final) {
                *(float4*)(oh + eo) = *(float4*)&ho[0];
                *(float4*)(oh + eo + 4) = *(float4*)&ho[4];
                *(float4*)(oc + eo) = *(float4*)&co[0];
                *(float4*)(oc + eo + 4) = *(float4*)&co[4];
            }
        }
    }
}

// ---------------- h_root ----------------
__global__ void k_root(const int* __restrict__ td, const float* __restrict__ out_h,
                       float* __restrict__ out_root) {
    __shared__ int red[256];
    int b = blockIdx.x, tid = threadIdx.x;
    int v = 0;
    for (int s = tid; s < NS; s += 256) v = max(v, td[b * (NT * NS) + (NT - 1) * NS + s]);
    red[tid] = v;
    __syncthreads();
    for (int off = 128; off > 0; off >>= 1) {
        if (tid < off) red[tid] = max(red[tid], red[tid + off]);
        __syncthreads();
    }
    int root = red[0];
    out_root[b * NH + tid] = out_h[(((size_t)(b << 11)) + root) * NH + tid];
}

// ---------------- host launcher (graph-capturable) ----------------
extern "C" void kernel_launch(void* const* d_in, const int* in_sizes, int n_in,
                              void* d_out, int out_size) {
    const float* X     = (const float*)d_in[0];
    const int*   td    = (const int*)d_in[1];
    const int*   tr    = (const int*)d_in[2];
    const int*   tl    = (const int*)d_in[3];
    const float* W_iou = (const float*)d_in[4];
    const float* b_iou = (const float*)d_in[5];
    const float* U_l   = (const float*)d_in[6];
    const float* U_r   = (const float*)d_in[7];
    const float* W_f   = (const float*)d_in[8];
    const float* b_f   = (const float*)d_in[9];
    const float* F_ll  = (const float*)d_in[10];
    const float* F_lr  = (const float*)d_in[11];
    const float* F_rl  = (const float*)d_in[12];
    const float* F_rr  = (const float*)d_in[13];

    float* out      = (float*)d_out;
    float* out_h    = out;
    float* out_c    = out + (size_t)HCNT;
    float* out_root = out + 2 * (size_t)HCNT;

    __half *hhb = nullptr, *hlb = nullptr;
    float* cb = nullptr;
    cudaGetSymbolAddress((void**)&hhb, g_hh);
    cudaGetSymbolAddress((void**)&hlb, g_hl);
    cudaGetSymbolAddress((void**)&cb, g_c);

    static int attr_done = 0;
    if (!attr_done) {
        cudaFuncSetAttribute(k_step_mma, cudaFuncAttributeMaxDynamicSharedMemorySize, SMEM_DYN);
        attr_done = 1;
    }

    k_init<<<4096, 256>>>();
    k_pack_wp<<<(WP_TOTAL + 255) / 256, 256>>>(W_iou, b_iou, W_f, b_f);
    k_pack_ub<<<(UB_TOTAL + 255) / 256, 256>>>(U_l, U_r, F_ll, F_lr, F_rl, F_rr);
    k_winner_all<<<dim3(NROWS / 256, NT), 256>>>(td);
    k_compact_all<<<dim3(NROWS / 256, NT), 256>>>(td);
    k_xgemm_mma<<<dim3(512, 4), 512>>>(X);

    int cur = 0;
    for (int t = 0; t < NT; t++) {
        int fin = (t == NT - 1) ? 1 : 0;
        const __half* hhc = hhb + (size_t)cur * HCNT;
        const __half* hlc = hlb + (size_t)cur * HCNT;
        const float*  ccc = cb + (size_t)cur * HCNT;
        __half* hhn = hhb + (size_t)(1 - cur) * HCNT;
        __half* hln = hlb + (size_t)(1 - cur) * HCNT;
        float*  cnn = cb + (size_t)(1 - cur) * HCNT;
        k_step_mma<<<dim3(NTL, 576), 512, SMEM_DYN>>>(
            t, fin, td, tl, tr, hhc, hlc, ccc, hhn, hln, cnn, out_h, out_c);
        cur ^= 1;
    }
    k_root<<<NB, 256>>>(td, out_h, out_root);
}

// round 11
// speedup vs baseline: 5.6053x; 1.1191x over previous
#include <cuda_runtime.h>
#include <cuda_fp16.h>
#include <math.h>
#include <stdint.h>

// ---------------- problem constants ----------------
#define NB 32
#define NS 2048
#define NE 300
#define NH 256
#define NT 24
#define NROWS 65536            // NB*NS
#define XN 1024                 // x-gates per row: j*4 + {i,o,u,f}
#define HCNT 16777216           // NROWS*NH

// ---------------- step-GEMM tiling ----------------
#define BM 128                  // rows per CTA
#define NTL 8                   // 1280 / 160 n-tiles
#define UB_NT_STRIDE 40960      // fp16 elems per 80-col packed tile (8 kchunks)
#define UB_TOTAL (16 * UB_NT_STRIDE)
#define WP_TOTAL (20 * 16384)   // W pack: 20 kcs * 1024 cols * 16

// ---------------- k_step dynamic smem (bytes) ------
#define OFF_IDX   0             // sL/sR/sD/sRow: 4 * 512
#define OFF_AH0   2048          // 128 x 64 fp16 = 16384
#define OFF_AH1   18432
#define OFF_STAGE 2048          // 128 x 164 f32 (reuses A buffers)
#define SMEM_DYN  86016

// ---------------- device scratch -------------------
__device__ __half g_x[(size_t)NROWS * XN];    // 128 MiB packed x-gates (fp16)
__device__ __half g_Wp[WP_TOTAL];             // W fragment-native fp16 hi
__device__ float g_bias[XN];
__device__ __half g_UBH[UB_TOTAL];            // U fragment-native fp16 hi
__device__ __half g_hh[2 * (size_t)HCNT];     // h hi, 2 alternation buffers
__device__ __half g_hl[2 * (size_t)HCNT];     // h lo
__device__ float g_c[2 * (size_t)HCNT];       // c fp32
__device__ int      g_win[NT * NROWS];        // per-step winner s for each (b,d)
__device__ uint32_t g_wmask[NROWS];           // bit t: row won at step t
__device__ int      g_work[NT * NROWS];       // per-step compacted winner lists
__device__ int      g_cnt[NT];

__device__ __forceinline__ float sigm(float x) { return 1.0f / (1.0f + __expf(-x)); }

__device__ __forceinline__ uint32_t smem_u32(const void* p) {
    uint32_t r;
    asm("{ .reg .u64 t; cvta.to.shared.u64 t, %1; cvt.u32.u64 %0, t; }" : "=r"(r) : "l"(p));
    return r;
}
__device__ __forceinline__ void ldsm4(uint32_t* r, uint32_t addr) {
    asm volatile("ldmatrix.sync.aligned.m8n8.x4.shared.b16 {%0,%1,%2,%3}, [%4];"
                 : "=r"(r[0]), "=r"(r[1]), "=r"(r[2]), "=r"(r[3]) : "r"(addr));
}
#define MMA(d, a, bx, by) asm volatile( \
    "mma.sync.aligned.m16n8k16.row.col.f32.f16.f16.f32 " \
    "{%0,%1,%2,%3},{%4,%5,%6,%7},{%8,%9},{%0,%1,%2,%3};" \
    : "+f"((d)[0]), "+f"((d)[1]), "+f"((d)[2]), "+f"((d)[3]) \
    : "r"((a)[0]), "r"((a)[1]), "r"((a)[2]), "r"((a)[3]), "r"(bx), "r"(by))

__device__ __forceinline__ void cp16(uint32_t dst, const void* src) {
    asm volatile("{\n\t.reg .u64 g;\n\tcvta.to.global.u64 g, %1;\n\t"
                 "cp.async.cg.shared.global [%0], [g], 16;\n\t}"
                 :: "r"(dst), "l"(src) : "memory");
}
#define CP_COMMIT asm volatile("cp.async.commit_group;" ::: "memory")
#define CP_WAIT1  asm volatile("cp.async.wait_group 1;" ::: "memory")
#define CP_WAIT0  asm volatile("cp.async.wait_group 0;" ::: "memory")

__device__ __forceinline__ uint32_t packh2(float a, float b) {
    __half2 v = __floats2half2_rn(a, b);
    return *(uint32_t*)&v;
}

// ---------------- init: zero BOTH state buffers ----------------
__global__ void k_init() {
    size_t i = (size_t)blockIdx.x * blockDim.x + threadIdx.x;
    size_t stride = (size_t)gridDim.x * blockDim.x;
    uint32_t* ph = (uint32_t*)g_hh;   // 2*HCNT halves = HCNT u32
    uint32_t* pl = (uint32_t*)g_hl;
    for (size_t p = i; p < (size_t)HCNT; p += stride) { ph[p] = 0u; pl[p] = 0u; }
    for (size_t p = i; p < 2 * (size_t)HCNT; p += stride) g_c[p] = 0.0f;
    for (size_t p = i; p < (size_t)(NT * NROWS); p += stride) g_win[p] = -1;
    for (size_t p = i; p < (size_t)NROWS; p += stride) g_wmask[p] = 0u;
    if (i < NT) g_cnt[i] = 0;
}

// ---- pack W: fragment-native fp16 hi; also bias ----
__global__ void k_pack_wp(const float* __restrict__ W_iou, const float* __restrict__ b_iou,
                          const float* __restrict__ W_f,   const float* __restrict__ b_f) {
    int idx = blockIdx.x * blockDim.x + threadIdx.x;
    if (idx < WP_TOTAL) {
        int kcs = idx >> 14;
        int rem = idx & 16383;
        int ncol = rem >> 4, low = rem & 15;
        int c = low >> 2, e = low & 3;
        int kin = (e < 2) ? (2 * c + e) : (8 + 2 * c + (e - 2));
        int k = (kcs >> 2) * 64 + (kcs & 3) * 16 + kin;
        int j = ncol >> 2, g = ncol & 3;
        float v = 0.0f;
        if (k < NE) v = (g < 3) ? W_iou[k * 768 + g * 256 + j] : W_f[k * 256 + j];
        g_Wp[idx] = __float2half_rn(v);
    }
    if (idx < XN) {
        int j = idx >> 2, g = idx & 3;
        g_bias[idx] = (g < 3) ? b_iou[g * 256 + j] : b_f[j];
    }
}

// ---- pack U: fragment-native fp16 hi (16 tiles of 80 cols) ----
__global__ void k_pack_ub(const float* __restrict__ Ul, const float* __restrict__ Ur,
                          const float* __restrict__ Fll, const float* __restrict__ Flr,
                          const float* __restrict__ Frl, const float* __restrict__ Frr) {
    int idx = blockIdx.x * blockDim.x + threadIdx.x;
    if (idx >= UB_TOTAL) return;
    int e = idx & 3, c = (idx >> 2) & 3;
    int n = (idx >> 4) % 80;
    int q = (idx >> 4) / 80;           // ntl*32 + kc*4 + s
    int s = q & 3, kc = (q >> 2) & 7, ntl = q >> 5;
    int kin = (e < 2) ? (2 * c + e) : (8 + 2 * c + (e - 2));
    int k = kc * 64 + s * 16 + kin;
    int ncol = ntl * 80 + n;
    int j = ncol / 5, g = ncol - 5 * j;
    float v;
    if (k < 256) {
        v = (g == 0) ? Ul[k * 768 + j]
          : (g == 1) ? Ul[k * 768 + 256 + j]
          : (g == 2) ? Ul[k * 768 + 512 + j]
          : (g == 3) ? Fll[k * 256 + j]
                     : Frl[k * 256 + j];
    } else {
        int kr = k - 256;
        v = (g == 0) ? Ur[kr * 768 + j]
          : (g == 1) ? Ur[kr * 768 + 256 + j]
          : (g == 2) ? Ur[kr * 768 + 512 + j]
          : (g == 3) ? Flr[kr * 256 + j]
                     : Frr[kr * 256 + j];
    }
    g_UBH[idx] = __float2half_rn(v);
}

// ---------------- tensorized x-projection: g_x = fp16(X @ W + b) ----------------
__global__ __launch_bounds__(512, 1) void k_xgemm_mma(const float* __restrict__ X) {
    __shared__ __align__(16) char xs[32768];   // AH 16K | AL 16K
    int mt = blockIdx.x, nt = blockIdx.y;
    int tid = threadIdx.x;
    int warp = tid >> 5, lane = tid & 31;
    int warpM = warp & 3, warpN = warp >> 2;
    uint32_t sb = smem_u32(xs);

    int arow = tid >> 2, aq = tid & 3;
    int b0 = arow * 128 + aq * 32;
    int s0 = b0 ^ ((b0 >> 3) & 0x70);
    int s1 = (b0 + 16) ^ (((b0 + 16) >> 3) & 0x70);
    const float* xrow = X + (size_t)(mt * 128 + arow) * NE;

    float acc[2][8][4];
#pragma unroll
    for (int m = 0; m < 2; m++)
#pragma unroll
        for (int f = 0; f < 8; f++)
#pragma unroll
            for (int i = 0; i < 4; i++) acc[m][f][i] = 0.0f;

    int r0 = warpM * 32 + (lane & 15);
    int r1 = r0 + 16;
    int segb = ((lane >> 4) & 1) * 16;
    int lanepart = (lane >> 2) * 16 + (lane & 3) * 4;
    int nbase = (nt * 256 + warpN * 64) * 16 + lanepart;

    float v[16];
    {
        int k0 = aq * 16;
#pragma unroll
        for (int i = 0; i < 4; i++) *(float4*)&v[i * 4] = *(const float4*)(xrow + k0 + i * 4);
    }

    for (int kc = 0; kc < 5; kc++) {
        __syncthreads();
        {
            uint4 ph, pl;
            uint32_t* hp = (uint32_t*)&ph;
            uint32_t* lp = (uint32_t*)&pl;
#pragma unroll
            for (int p = 0; p < 4; p++) {
                float a = v[2 * p], b = v[2 * p + 1];
                __half ha = __float2half_rn(a), hb = __float2half_rn(b);
                hp[p] = packh2(a, b);
                lp[p] = packh2(a - __half2float(ha), b - __half2float(hb));
            }
            *(uint4*)(xs + s0) = ph;
            *(uint4*)(xs + 16384 + s0) = pl;
#pragma unroll
            for (int p = 0; p < 4; p++) {
                float a = v[8 + 2 * p], b = v[8 + 2 * p + 1];
                __half ha = __float2half_rn(a), hb = __float2half_rn(b);
                hp[p] = packh2(a, b);
                lp[p] = packh2(a - __half2float(ha), b - __half2float(hb));
            }
            *(uint4*)(xs + s1) = ph;
            *(uint4*)(xs + 16384 + s1) = pl;
        }
        __syncthreads();
        if (kc < 4) {
            int k0 = (kc + 1) * 64 + aq * 16;
            if (k0 + 15 < NE) {
#pragma unroll
                for (int i = 0; i < 4; i++) *(float4*)&v[i * 4] = *(const float4*)(xrow + k0 + i * 4);
            } else {
#pragma unroll
                for (int i = 0; i < 16; i++) v[i] = (k0 + i < NE) ? xrow[k0 + i] : 0.0f;
            }
        }
#pragma unroll
        for (int s = 0; s < 4; s++) {
            uint32_t ah0[4], ah1[4], al0[4], al1[4];
            {
                int o = r0 * 128 + s * 32 + segb; o ^= ((o >> 3) & 0x70);
                ldsm4(ah0, sb + o); ldsm4(al0, sb + 16384 + o);
            }
            {
                int o = r1 * 128 + s * 32 + segb; o ^= ((o >> 3) & 0x70);
                ldsm4(ah1, sb + o); ldsm4(al1, sb + 16384 + o);
            }
            const __half* pb = g_Wp + (size_t)(kc * 4 + s) * 16384 + nbase;
#pragma unroll
            for (int f = 0; f < 8; f++) {
                uint2 bh = *(const uint2*)(pb + f * 128);
                MMA(acc[0][f], ah0, bh.x, bh.y);
                MMA(acc[1][f], ah1, bh.x, bh.y);
                MMA(acc[0][f], al0, bh.x, bh.y);
                MMA(acc[1][f], al1, bh.x, bh.y);
            }
        }
    }

    int rg = lane >> 2, c2 = (lane & 3) * 2;
#pragma unroll
    for (int f = 0; f < 8; f++) {
        int col = nt * 256 + warpN * 64 + f * 8 + c2;
        float2 bb = *(const float2*)&g_bias[col];
#pragma unroll
        for (int m = 0; m < 2; m++) {
            int row = mt * 128 + warpM * 32 + m * 16 + rg;
            *(uint32_t*)&g_x[(size_t)row * XN + col] =
                packh2(acc[m][f][0] + bb.x, acc[m][f][1] + bb.y);
            *(uint32_t*)&g_x[(size_t)(row + 8) * XN + col] =
                packh2(acc[m][f][2] + bb.x, acc[m][f][3] + bb.y);
        }
    }
}

// ---------------- winner/compact: ALL steps in 2 launches ----------------
__global__ void k_winner_all(const int* __restrict__ td) {
    int t = blockIdx.y;
    int idx = blockIdx.x * blockDim.x + threadIdx.x;
    int b = idx >> 11, s = idx & 2047;
    int d = td[b * (NT * NS) + t * NS + s];
    atomicMax(&g_win[t * NROWS + (b << 11) + d], s);
}

__global__ void k_compact_all(const int* __restrict__ td) {
    __shared__ int scnt, sbase;
    int t = blockIdx.y;
    int tid = threadIdx.x;
    if (tid == 0) scnt = 0;
    __syncthreads();
    int idx = blockIdx.x * blockDim.x + tid;
    int b = idx >> 11, s = idx & 2047;
    int d = td[b * (NT * NS) + t * NS + s];
    int dd = (b << 11) + d;
    bool win = (d != 0) && (g_win[t * NROWS + dd] == s);
    int pos = 0;
    if (win) pos = atomicAdd(&scnt, 1);
    __syncthreads();
    if (tid == 0) sbase = atomicAdd(&g_cnt[t], scnt);
    __syncthreads();
    if (win) {
        g_work[t * NROWS + sbase + pos] = idx;
        atomicOr(&g_wmask[dd], 1u << t);
    }
}

// ---------------- fused step: single-pass fp16 mma, buffer-alternating state ----
// grid = (8, 512), 512 threads (16 warps: 4M x 4N)
__global__ __launch_bounds__(512, 1) void k_step_mma(
    int t,
    const int* __restrict__ td, const int* __restrict__ tl, const int* __restrict__ tr,
    const __half* __restrict__ hh, const __half* __restrict__ hl,
    const float* __restrict__ cc,
    __half* __restrict__ hhw, __half* __restrict__ hlw, float* __restrict__ ccw)
{
    extern __shared__ char smem[];
    int tid = threadIdx.x;
    int count = g_cnt[t];
    int mt = blockIdx.y;
    if (mt * BM >= count) return;
    int nt = blockIdx.x;
    const int* work = g_work + t * NROWS;

    int* sL = (int*)(smem + OFF_IDX);
    int* sR = (int*)(smem + OFF_IDX + 512);
    int* sD = (int*)(smem + OFF_IDX + 1024);
    int* sRow = (int*)(smem + OFF_IDX + 1536);

    if (tid < BM) {
        int m = mt * BM + tid;
        if (m < count) {
            int idx = work[m];
            int b = idx >> 11, s = idx & 2047;
            int tb = b * (NT * NS) + t * NS + s;
            int brow = b << 11;
            int rl = brow + tl[tb];
            int rr = brow + tr[tb];
            int rd = brow + td[tb];
            uint32_t below = (1u << t) - 1u;
            int nl = __popc(g_wmask[rl] & below);
            int nr = __popc(g_wmask[rr] & below);
            int nd = __popc(g_wmask[rd] & below);
            // readers use buf[(n+1)&1]; writer uses buf[n&1] -> never collide
            sL[tid] = ((nl + 1) & 1) * HCNT + (rl << 8);
            sR[tid] = ((nr + 1) & 1) * HCNT + (rr << 8);
            sD[tid] = (nd & 1) * HCNT + (rd << 8);
            sRow[tid] = idx;
        } else {
            sL[tid] = 0; sR[tid] = 0; sD[tid] = -1; sRow[tid] = 0;
        }
    }
    __syncthreads();

    uint32_t sb = smem_u32(smem);
    int arow = tid >> 2, aq = tid & 3;
    int offL = sL[arow], offR = sR[arow];
    int b0 = arow * 128 + aq * 32;
    int b1 = b0 + 16;
    int s0 = b0 ^ ((b0 >> 3) & 0x70);
    int s1 = b1 ^ ((b1 >> 3) & 0x70);
    const uint32_t offAH[2] = {OFF_AH0, OFF_AH1};

    // stage chunk 0 (h_l, k0=0)
    {
        const __half* ph = hh + offL + aq * 16;
        cp16(sb + OFF_AH0 + s0, ph);  cp16(sb + OFF_AH0 + s1, ph + 8);
        CP_COMMIT;
    }

    int warp = tid >> 5, lane = tid & 31;
    int warpM = warp & 3, warpN = warp >> 2;

    float acc[2][5][4];
#pragma unroll
    for (int m = 0; m < 2; m++)
#pragma unroll
        for (int f = 0; f < 5; f++)
#pragma unroll
            for (int i = 0; i < 4; i++) acc[m][f][i] = 0.0f;

    int r0 = warpM * 32 + (lane & 15);
    int r1 = r0 + 16;
    int segb = ((lane >> 4) & 1) * 16;

    int tilesel = nt * 2 + (warpN >> 1);
    const __half* pbh = g_UBH + (size_t)tilesel * UB_NT_STRIDE;
    int lanepart = (lane >> 2) * 16 + (lane & 3) * 4;
    int warppart = (warpN & 1) * 640;

    for (int kc = 0; kc < 8; kc++) {
        if (kc < 7) {
            int kcn = kc + 1;
            int nb = kcn & 1;
            int off = (kcn < 4) ? offL : offR;
            int k0 = (kcn & 3) * 64;
            const __half* ph = hh + off + k0 + aq * 16;
            cp16(sb + offAH[nb] + s0, ph);  cp16(sb + offAH[nb] + s1, ph + 8);
            CP_COMMIT;
            CP_WAIT1;
        } else {
            CP_WAIT0;
        }
        __syncthreads();

        uint32_t abh = sb + offAH[kc & 1];
#pragma unroll
        for (int s = 0; s < 4; s++) {
            uint32_t ah0[4], ah1[4];
            {
                int o = r0 * 128 + s * 32 + segb; o ^= ((o >> 3) & 0x70);
                ldsm4(ah0, abh + o);
            }
            {
                int o = r1 * 128 + s * 32 + segb; o ^= ((o >> 3) & 0x70);
                ldsm4(ah1, abh + o);
            }
            int be = (kc * 4 + s) * 1280 + warppart + lanepart;
#pragma unroll
            for (int f = 0; f < 5; f++) {
                uint2 bh = *(const uint2*)(pbh + be + f * 128);
                MMA(acc[0][f], ah0, bh.x, bh.y);
                MMA(acc[1][f], ah1, bh.x, bh.y);
            }
        }
        __syncthreads();
    }

    // epilogue: transpose acc through smem, fuse activations
    float* stg = (float*)(smem + OFF_STAGE);
    {
        int rg = lane >> 2, cl = 2 * (lane & 3);
#pragma unroll
        for (int m = 0; m < 2; m++) {
#pragma unroll
            for (int f = 0; f < 5; f++) {
                int row = warpM * 32 + m * 16 + rg;
                int col = warpN * 40 + f * 8 + cl;
                *(float2*)&stg[row * 164 + col] = make_float2(acc[m][f][0], acc[m][f][1]);
                *(float2*)&stg[(row + 8) * 164 + col] = make_float2(acc[m][f][2], acc[m][f][3]);
            }
        }
    }
    __syncthreads();

    {
        int row = arow, ug = aq;
        int j0 = nt * 32;
        int od = sD[row];
        const __half* xp = g_x + (size_t)sRow[row] * XN + (size_t)(j0 + ug * 8) * 4;
        const float* clp = cc + offL + j0 + ug * 8;
        const float* crp = cc + offR + j0 + ug * 8;
        uint4 xr[4];
#pragma unroll
        for (int i = 0; i < 4; i++) xr[i] = ((const uint4*)xp)[i];
        const __half2* xh = (const __half2*)xr;
        float clv[8], crv[8], ho[8], co[8];
        *(float4*)&clv[0] = *(const float4*)clp;
        *(float4*)&clv[4] = *(const float4*)(clp + 4);
        *(float4*)&crv[0] = *(const float4*)crp;
        *(float4*)&crv[4] = *(const float4*)(crp + 4);
#pragma unroll
        for (int u = 0; u < 8; u++) {
            int col = (ug * 8 + u) * 5;
            float a_i  = stg[row * 164 + col + 0];
            float a_o  = stg[row * 164 + col + 1];
            float a_u  = stg[row * 164 + col + 2];
            float a_fl = stg[row * 164 + col + 3];
            float a_fr = stg[row * 164 + col + 4];
            float2 p0 = __half22float2(xh[2 * u]);
            float2 p1 = __half22float2(xh[2 * u + 1]);
            float gi = sigm(a_i + p0.x);
            float go = sigm(a_o + p0.y);
            float gu = tanhf(a_u + p1.x);
            float fl = sigm(a_fl + p1.y);
            float fr = sigm(a_fr + p1.y);
            float cnew = gi * gu + fl * clv[u] + fr * crv[u];
            ho[u] = go * tanhf(cnew);
            co[u] = cnew;
        }
        if (od >= 0) {
            uint32_t hw[4], lw[4];
#pragma unroll
            for (int p = 0; p < 4; p++) {
                float v0 = ho[2 * p], v1 = ho[2 * p + 1];
                __half a = __float2half_rn(v0);
                __half b = __float2half_rn(v1);
                hw[p] = packh2(v0, v1);
                lw[p] = packh2(v0 - __half2float(a), v1 - __half2float(b));
            }
            int eo = od + j0 + ug * 8;
            *(uint4*)(hhw + eo) = make_uint4(hw[0], hw[1], hw[2], hw[3]);
            *(uint4*)(hlw + eo) = make_uint4(lw[0], lw[1], lw[2], lw[3]);
            *(float4*)(ccw + eo) = *(float4*)&co[0];
            *(float4*)(ccw + eo + 4) = *(float4*)&co[4];
        }
    }
}

// ---------------- final output assembly ----------------
// grid 4096 x 512 threads; each thread: one row-slice of 8 cols
__global__ void k_output(const __half* __restrict__ hh, const __half* __restrict__ hl,
                         const float* __restrict__ cc,
                         float* __restrict__ oh, float* __restrict__ oc) {
    int tid = threadIdx.x;
    int row = blockIdx.x * 16 + (tid >> 5);
    int cg = (tid & 31) * 8;
    size_t oo = ((size_t)row << 8) + cg;
    uint32_t m = g_wmask[row];
    if (m == 0u) {
        float4 z = make_float4(0.f, 0.f, 0.f, 0.f);
        *(float4*)(oh + oo) = z; *(float4*)(oh + oo + 4) = z;
        *(float4*)(oc + oo) = z; *(float4*)(oc + oo + 4) = z;
        return;
    }
    int nw = __popc(m);
    size_t so = (size_t)(((nw - 1) & 1)) * HCNT + oo;
    uint4 rh = *(const uint4*)(hh + so);
    uint4 rl = *(const uint4*)(hl + so);
    const __half2* ph = (const __half2*)&rh;
    const __half2* pl = (const __half2*)&rl;
#pragma unroll
    for (int i = 0; i < 4; i++) {
        float2 a = __half22float2(ph[i]);
        float2 b = __half22float2(pl[i]);
        *(float2*)(oh + oo + 2 * i) = make_float2(a.x + b.x, a.y + b.y);
    }
    *(float4*)(oc + oo) = *(const float4*)(cc + so);
    *(float4*)(oc + oo + 4) = *(const float4*)(cc + so + 4);
}

// ---------------- h_root ----------------
__global__ void k_root(const int* __restrict__ td, const float* __restrict__ out_h,
                       float* __restrict__ out_root) {
    __shared__ int red[256];
    int b = blockIdx.x, tid = threadIdx.x;
    int v = 0;
    for (int s = tid; s < NS; s += 256) v = max(v, td[b * (NT * NS) + (NT - 1) * NS + s]);
    red[tid] = v;
    __syncthreads();
    for (int off = 128; off > 0; off >>= 1) {
        if (tid < off) red[tid] = max(red[tid], red[tid + off]);
        __syncthreads();
    }
    int root = red[0];
    out_root[b * NH + tid] = out_h[(((size_t)(b << 11)) + root) * NH + tid];
}

// ---------------- host launcher (graph-capturable) ----------------
extern "C" void kernel_launch(void* const* d_in, const int* in_sizes, int n_in,
                              void* d_out, int out_size) {
    const float* X     = (const float*)d_in[0];
    const int*   td    = (const int*)d_in[1];
    const int*   tr    = (const int*)d_in[2];
    const int*   tl    = (const int*)d_in[3];
    const float* W_iou = (const float*)d_in[4];
    const float* b_iou = (const float*)d_in[5];
    const float* U_l   = (const float*)d_in[6];
    const float* U_r   = (const float*)d_in[7];
    const float* W_f   = (const float*)d_in[8];
    const float* b_f   = (const float*)d_in[9];
    const float* F_ll  = (const float*)d_in[10];
    const float* F_lr  = (const float*)d_in[11];
    const float* F_rl  = (const float*)d_in[12];
    const float* F_rr  = (const float*)d_in[13];

    float* out      = (float*)d_out;
    float* out_h    = out;
    float* out_c    = out + (size_t)HCNT;
    float* out_root = out + 2 * (size_t)HCNT;

    __half *hhb = nullptr, *hlb = nullptr;
    float* cb = nullptr;
    cudaGetSymbolAddress((void**)&hhb, g_hh);
    cudaGetSymbolAddress((void**)&hlb, g_hl);
    cudaGetSymbolAddress((void**)&cb, g_c);

    static int attr_done = 0;
    if (!attr_done) {
        cudaFuncSetAttribute(k_step_mma, cudaFuncAttributeMaxDynamicSharedMemorySize, SMEM_DYN);
        attr_done = 1;
    }

    k_init<<<4096, 256>>>();
    k_pack_wp<<<(WP_TOTAL + 255) / 256, 256>>>(W_iou, b_iou, W_f, b_f);
    k_pack_ub<<<(UB_TOTAL + 255) / 256, 256>>>(U_l, U_r, F_ll, F_lr, F_rl, F_rr);
    k_winner_all<<<dim3(NROWS / 256, NT), 256>>>(td);
    k_compact_all<<<dim3(NROWS / 256, NT), 256>>>(td);
    k_xgemm_mma<<<dim3(512, 4), 512>>>(X);

    for (int t = 0; t < NT; t++) {
        k_step_mma<<<dim3(NTL, 512), 512, SMEM_DYN>>>(
            t, td, tl, tr, hhb, hlb, cb, hhb, hlb, cb);
    }
    k_output<<<4096, 512>>>(hhb, hlb, cb, out_h, out_c);
    k_root<<<NB, 256>>>(td, out_h, out_root);
}

// round 13
// speedup vs baseline: 5.6268x; 1.0038x over previous
#include <cuda_runtime.h>
#include <cuda_fp16.h>
#include <math.h>
#include <stdint.h>

// ---------------- problem constants ----------------
#define NB 32
#define NS 2048
#define NE 300
#define NH 256
#define NT 24
#define NROWS 65536            // NB*NS
#define XN 1024                 // x-gates per row: j*4 + {i,o,u,f}
#define HCNT 16777216           // NROWS*NH

// ---------------- step-GEMM tiling ----------------
#define BM 128                  // rows per CTA
#define NTL 8                   // 1280 / 160 n-tiles
#define UB_NT_STRIDE 40960      // fp16 elems per 80-col packed tile (8 kchunks)
#define UB_TOTAL (16 * UB_NT_STRIDE)
#define WP_TOTAL (20 * 16384)   // W pack: 20 kcs * 1024 cols * 16

// ---------------- k_step dynamic smem (bytes) ------
#define OFF_IDX   0             // sL/sR/sD/sRow: 4 * 512
#define OFF_A0    2048          // 3 x (128 x 64 fp16 = 16384)
#define OFF_A1    18432
#define OFF_A2    34816
#define OFF_STAGE 2048          // 128 x 164 f32 = 83968 (reuses A bufs) -> 86016
#define OFF_XST   86016         // 128 rows x 272 B (256 + 16 pad) = 34816
#define OFF_CL    120832        // 128 rows x 144 B = 18432
#define OFF_CR    139264        // 128 rows x 144 B = 18432
#define SMEM_DYN  157696

// ---------------- device scratch -------------------
__device__ __half g_x[(size_t)NROWS * XN];    // 128 MiB packed x-gates (fp16)
__device__ __half g_Wp[WP_TOTAL];             // W fragment-native fp16 hi
__device__ float g_bias[XN];
__device__ __half g_UBH[UB_TOTAL];            // U fragment-native fp16 hi
__device__ __half g_hh[2 * (size_t)HCNT];     // h hi, 2 alternation buffers
__device__ __half g_hl[2 * (size_t)HCNT];     // h lo
__device__ float g_c[2 * (size_t)HCNT];       // c fp32
__device__ int      g_win[NT * NROWS];        // per-step winner s for each (b,d)
__device__ uint32_t g_wmask[NROWS];           // bit t: row won at step t
__device__ int      g_work[NT * NROWS];       // per-step compacted winner lists
__device__ int      g_cnt[NT];

__device__ __forceinline__ float sigm(float x) { return 1.0f / (1.0f + __expf(-x)); }

__device__ __forceinline__ uint32_t smem_u32(const void* p) {
    uint32_t r;
    asm("{ .reg .u64 t; cvta.to.shared.u64 t, %1; cvt.u32.u64 %0, t; }" : "=r"(r) : "l"(p));
    return r;
}
__device__ __forceinline__ void ldsm4(uint32_t* r, uint32_t addr) {
    asm volatile("ldmatrix.sync.aligned.m8n8.x4.shared.b16 {%0,%1,%2,%3}, [%4];"
                 : "=r"(r[0]), "=r"(r[1]), "=r"(r[2]), "=r"(r[3]) : "r"(addr));
}
#define MMA(d, a, bx, by) asm volatile( \
    "mma.sync.aligned.m16n8k16.row.col.f32.f16.f16.f32 " \
    "{%0,%1,%2,%3},{%4,%5,%6,%7},{%8,%9},{%0,%1,%2,%3};" \
    : "+f"((d)[0]), "+f"((d)[1]), "+f"((d)[2]), "+f"((d)[3]) \
    : "r"((a)[0]), "r"((a)[1]), "r"((a)[2]), "r"((a)[3]), "r"(bx), "r"(by))

__device__ __forceinline__ void cp16(uint32_t dst, const void* src) {
    asm volatile("{\n\t.reg .u64 g;\n\tcvta.to.global.u64 g, %1;\n\t"
                 "cp.async.cg.shared.global [%0], [g], 16;\n\t}"
                 :: "r"(dst), "l"(src) : "memory");
}
#define CP_COMMIT asm volatile("cp.async.commit_group;" ::: "memory")
#define CP_WAIT1  asm volatile("cp.async.wait_group 1;" ::: "memory")
#define CP_WAIT0  asm volatile("cp.async.wait_group 0;" ::: "memory")

__device__ __forceinline__ uint32_t packh2(float a, float b) {
    __half2 v = __floats2half2_rn(a, b);
    return *(uint32_t*)&v;
}

// ---------------- init: zero ONLY buffer 1 of state (buf0 always written
// before first read: readers with n prior writes read buf[(n+1)&1]) ----------
__global__ void k_init() {
    size_t i = (size_t)blockIdx.x * blockDim.x + threadIdx.x;
    size_t stride = (size_t)gridDim.x * blockDim.x;
    uint32_t* ph = (uint32_t*)g_hh;   // u32 p covers halves 2p,2p+1
    uint32_t* pl = (uint32_t*)g_hl;
    for (size_t p = (size_t)(HCNT / 2) + i; p < (size_t)HCNT; p += stride) {
        ph[p] = 0u; pl[p] = 0u;
    }
    for (size_t p = (size_t)HCNT + i; p < 2 * (size_t)HCNT; p += stride) g_c[p] = 0.0f;
    for (size_t p = i; p < (size_t)(NT * NROWS); p += stride) g_win[p] = -1;
    for (size_t p = i; p < (size_t)NROWS; p += stride) g_wmask[p] = 0u;
    if (i < NT) g_cnt[i] = 0;
}

// ---- pack W: fragment-native fp16 hi; also bias ----
__global__ void k_pack_wp(const float* __restrict__ W_iou, const float* __restrict__ b_iou,
                          const float* __restrict__ W_f,   const float* __restrict__ b_f) {
    int idx = blockIdx.x * blockDim.x + threadIdx.x;
    if (idx < WP_TOTAL) {
        int kcs = idx >> 14;
        int rem = idx & 16383;
        int ncol = rem >> 4, low = rem & 15;
        int c = low >> 2, e = low & 3;
        int kin = (e < 2) ? (2 * c + e) : (8 + 2 * c + (e - 2));
        int k = (kcs >> 2) * 64 + (kcs & 3) * 16 + kin;
        int j = ncol >> 2, g = ncol & 3;
        float v = 0.0f;
        if (k < NE) v = (g < 3) ? W_iou[k * 768 + g * 256 + j] : W_f[k * 256 + j];
        g_Wp[idx] = __float2half_rn(v);
    }
    if (idx < XN) {
        int j = idx >> 2, g = idx & 3;
        g_bias[idx] = (g < 3) ? b_iou[g * 256 + j] : b_f[j];
    }
}

// ---- pack U: fragment-native fp16 hi (16 tiles of 80 cols) ----
__global__ void k_pack_ub(const float* __restrict__ Ul, const float* __restrict__ Ur,
                          const float* __restrict__ Fll, const float* __restrict__ Flr,
                          const float* __restrict__ Frl, const float* __restrict__ Frr) {
    int idx = blockIdx.x * blockDim.x + threadIdx.x;
    if (idx >= UB_TOTAL) return;
    int e = idx & 3, c = (idx >> 2) & 3;
    int n = (idx >> 4) % 80;
    int q = (idx >> 4) / 80;           // ntl*32 + kc*4 + s
    int s = q & 3, kc = (q >> 2) & 7, ntl = q >> 5;
    int kin = (e < 2) ? (2 * c + e) : (8 + 2 * c + (e - 2));
    int k = kc * 64 + s * 16 + kin;
    int ncol = ntl * 80 + n;
    int j = ncol / 5, g = ncol - 5 * j;
    float v;
    if (k < 256) {
        v = (g == 0) ? Ul[k * 768 + j]
          : (g == 1) ? Ul[k * 768 + 256 + j]
          : (g == 2) ? Ul[k * 768 + 512 + j]
          : (g == 3) ? Fll[k * 256 + j]
                     : Frl[k * 256 + j];
    } else {
        int kr = k - 256;
        v = (g == 0) ? Ur[kr * 768 + j]
          : (g == 1) ? Ur[kr * 768 + 256 + j]
          : (g == 2) ? Ur[kr * 768 + 512 + j]
          : (g == 3) ? Flr[kr * 256 + j]
                     : Frr[kr * 256 + j];
    }
    g_UBH[idx] = __float2half_rn(v);
}

// ---------------- tensorized x-projection: g_x = fp16(X @ W + b) ----------------
__global__ __launch_bounds__(512, 1) void k_xgemm_mma(const float* __restrict__ X) {
    __shared__ __align__(16) char xs[32768];   // AH 16K | AL 16K
    int mt = blockIdx.x, nt = blockIdx.y;
    int tid = threadIdx.x;
    int warp = tid >> 5, lane = tid & 31;
    int warpM = warp & 3, warpN = warp >> 2;
    uint32_t sb = smem_u32(xs);

    int arow = tid >> 2, aq = tid & 3;
    int b0 = arow * 128 + aq * 32;
    int s0 = b0 ^ ((b0 >> 3) & 0x70);
    int s1 = (b0 + 16) ^ (((b0 + 16) >> 3) & 0x70);
    const float* xrow = X + (size_t)(mt * 128 + arow) * NE;

    float acc[2][8][4];
#pragma unroll
    for (int m = 0; m < 2; m++)
#pragma unroll
        for (int f = 0; f < 8; f++)
#pragma unroll
            for (int i = 0; i < 4; i++) acc[m][f][i] = 0.0f;

    int r0 = warpM * 32 + (lane & 15);
    int r1 = r0 + 16;
    int segb = ((lane >> 4) & 1) * 16;
    int lanepart = (lane >> 2) * 16 + (lane & 3) * 4;
    int nbase = (nt * 256 + warpN * 64) * 16 + lanepart;

    float v[16];
    {
        int k0 = aq * 16;
#pragma unroll
        for (int i = 0; i < 4; i++) *(float4*)&v[i * 4] = *(const float4*)(xrow + k0 + i * 4);
    }

    for (int kc = 0; kc < 5; kc++) {
        __syncthreads();
        {
            uint4 ph, pl;
            uint32_t* hp = (uint32_t*)&ph;
            uint32_t* lp = (uint32_t*)&pl;
#pragma unroll
            for (int p = 0; p < 4; p++) {
                float a = v[2 * p], b = v[2 * p + 1];
                __half ha = __float2half_rn(a), hb = __float2half_rn(b);
                hp[p] = packh2(a, b);
                lp[p] = packh2(a - __half2float(ha), b - __half2float(hb));
            }
            *(uint4*)(xs + s0) = ph;
            *(uint4*)(xs + 16384 + s0) = pl;
#pragma unroll
            for (int p = 0; p < 4; p++) {
                float a = v[8 + 2 * p], b = v[8 + 2 * p + 1];
                __half ha = __float2half_rn(a), hb = __float2half_rn(b);
                hp[p] = packh2(a, b);
                lp[p] = packh2(a - __half2float(ha), b - __half2float(hb));
            }
            *(uint4*)(xs + s1) = ph;
            *(uint4*)(xs + 16384 + s1) = pl;
        }
        __syncthreads();
        if (kc < 4) {
            int k0 = (kc + 1) * 64 + aq * 16;
            if (k0 + 15 < NE) {
#pragma unroll
                for (int i = 0; i < 4; i++) *(float4*)&v[i * 4] = *(const float4*)(xrow + k0 + i * 4);
            } else {
#pragma unroll
                for (int i = 0; i < 16; i++) v[i] = (k0 + i < NE) ? xrow[k0 + i] : 0.0f;
            }
        }
#pragma unroll
        for (int s = 0; s < 4; s++) {
            uint32_t ah0[4], ah1[4], al0[4], al1[4];
            {
                int o = r0 * 128 + s * 32 + segb; o ^= ((o >> 3) & 0x70);
                ldsm4(ah0, sb + o); ldsm4(al0, sb + 16384 + o);
            }
            {
                int o = r1 * 128 + s * 32 + segb; o ^= ((o >> 3) & 0x70);
                ldsm4(ah1, sb + o); ldsm4(al1, sb + 16384 + o);
            }
            const __half* pb = g_Wp + (size_t)(kc * 4 + s) * 16384 + nbase;
#pragma unroll
            for (int f = 0; f < 8; f++) {
                uint2 bh = *(const uint2*)(pb + f * 128);
                MMA(acc[0][f], ah0, bh.x, bh.y);
                MMA(acc[1][f], ah1, bh.x, bh.y);
                MMA(acc[0][f], al0, bh.x, bh.y);
                MMA(acc[1][f], al1, bh.x, bh.y);
            }
        }
    }

    int rg = lane >> 2, c2 = (lane & 3) * 2;
#pragma unroll
    for (int f = 0; f < 8; f++) {
        int col = nt * 256 + warpN * 64 + f * 8 + c2;
        float2 bb = *(const float2*)&g_bias[col];
#pragma unroll
        for (int m = 0; m < 2; m++) {
            int row = mt * 128 + warpM * 32 + m * 16 + rg;
            *(uint32_t*)&g_x[(size_t)row * XN + col] =
                packh2(acc[m][f][0] + bb.x, acc[m][f][1] + bb.y);
            *(uint32_t*)&g_x[(size_t)(row + 8) * XN + col] =
                packh2(acc[m][f][2] + bb.x, acc[m][f][3] + bb.y);
        }
    }
}

// ---------------- winner/compact: ALL steps in 2 launches ----------------
__global__ void k_winner_all(const int* __restrict__ td) {
    int t = blockIdx.y;
    int idx = blockIdx.x * blockDim.x + threadIdx.x;
    int b = idx >> 11, s = idx & 2047;
    int d = td[b * (NT * NS) + t * NS + s];
    atomicMax(&g_win[t * NROWS + (b << 11) + d], s);
}

__global__ void k_compact_all(const int* __restrict__ td) {
    __shared__ int scnt, sbase;
    int t = blockIdx.y;
    int tid = threadIdx.x;
    if (tid == 0) scnt = 0;
    __syncthreads();
    int idx = blockIdx.x * blockDim.x + tid;
    int b = idx >> 11, s = idx & 2047;
    int d = td[b * (NT * NS) + t * NS + s];
    int dd = (b << 11) + d;
    bool win = (d != 0) && (g_win[t * NROWS + dd] == s);
    int pos = 0;
    if (win) pos = atomicAdd(&scnt, 1);
    __syncthreads();
    if (tid == 0) sbase = atomicAdd(&g_cnt[t], scnt);
    __syncthreads();
    if (win) {
        g_work[t * NROWS + sbase + pos] = idx;
        atomicOr(&g_wmask[dd], 1u << t);
    }
}

// ---------------- step 0: h==0 -> pure elementwise from x ----------------
// grid 8192 x 256: 8 winner rows per CTA, 32 threads/row, 8 units/thread
__global__ void k_step0(const int* __restrict__ td,
                        __half* __restrict__ hhw, __half* __restrict__ hlw,
                        float* __restrict__ ccw) {
    int count = g_cnt[0];
    int tid = threadIdx.x;
    int m = blockIdx.x * 8 + (tid >> 5);
    if (m >= count) return;
    int lane = tid & 31;
    int idx = g_work[m];
    int b = idx >> 11, s = idx & 2047;
    int d = td[b * (NT * NS) + s];
    int eo = (((b << 11) + d) << 8) + lane * 8;    // buffer 0 (first write)
    // this thread's 8 units need 32 halves (64 bytes) of x = 4 uint4
    const uint4* xp = (const uint4*)(g_x + (size_t)idx * XN + (size_t)lane * 32);
    uint4 xr[4];
#pragma unroll
    for (int i = 0; i < 4; i++) xr[i] = xp[i];
    const __half2* xh = (const __half2*)xr;
    float ho[8], co[8];
#pragma unroll
    for (int u = 0; u < 8; u++) {
        float2 p0 = __half22float2(xh[2 * u]);      // x_i, x_o
        float2 p1 = __half22float2(xh[2 * u + 1]);  // x_u, x_f
        float gi = sigm(p0.x);
        float go = sigm(p0.y);
        float gu = tanhf(p1.x);
        float cn = gi * gu;                          // c_l = c_r = 0
        ho[u] = go * tanhf(cn);
        co[u] = cn;
    }
    uint32_t hw[4], lw[4];
#pragma unroll
    for (int p = 0; p < 4; p++) {
        float v0 = ho[2 * p], v1 = ho[2 * p + 1];
        __half a = __float2half_rn(v0);
        __half bb = __float2half_rn(v1);
        hw[p] = packh2(v0, v1);
        lw[p] = packh2(v0 - __half2float(a), v1 - __half2float(bb));
    }
    *(uint4*)(hhw + eo) = make_uint4(hw[0], hw[1], hw[2], hw[3]);
    *(uint4*)(hlw + eo) = make_uint4(lw[0], lw[1], lw[2], lw[3]);
    *(float4*)(ccw + eo) = *(float4*)&co[0];
    *(float4*)(ccw + eo + 4) = *(float4*)&co[4];
}

// ---------------- fused step: fp16 mma, 3-buf pipeline, smem-prefetched epilogue ----
// grid = (8, 512), 512 threads (16 warps: 4M x 4N)
__global__ __launch_bounds__(512, 1) void k_step_mma(
    int t,
    const int* __restrict__ td, const int* __restrict__ tl, const int* __restrict__ tr,
    const __half* __restrict__ hh, const __half* __restrict__ hl,
    const float* __restrict__ cc,
    __half* __restrict__ hhw, __half* __restrict__ hlw, float* __restrict__ ccw)
{
    extern __shared__ char smem[];
    int tid = threadIdx.x;
    int count = g_cnt[t];
    int mt = blockIdx.y;
    if (mt * BM >= count) return;
    int nt = blockIdx.x;
    const int* work = g_work + t * NROWS;

    int* sL = (int*)(smem + OFF_IDX);
    int* sR = (int*)(smem + OFF_IDX + 512);
    int* sD = (int*)(smem + OFF_IDX + 1024);
    int* sRow = (int*)(smem + OFF_IDX + 1536);

    if (tid < BM) {
        int m = mt * BM + tid;
        if (m < count) {
            int idx = work[m];
            int b = idx >> 11, s = idx & 2047;
            int tb = b * (NT * NS) + t * NS + s;
            int brow = b << 11;
            int rl = brow + tl[tb];
            int rr = brow + tr[tb];
            int rd = brow + td[tb];
            uint32_t below = (1u << t) - 1u;
            int nl = __popc(g_wmask[rl] & below);
            int nr = __popc(g_wmask[rr] & below);
            int nd = __popc(g_wmask[rd] & below);
            sL[tid] = ((nl + 1) & 1) * HCNT + (rl << 8);
            sR[tid] = ((nr + 1) & 1) * HCNT + (rr << 8);
            sD[tid] = (nd & 1) * HCNT + (rd << 8);
            sRow[tid] = idx;
        } else {
            sL[tid] = 0; sR[tid] = 0; sD[tid] = -1; sRow[tid] = 0;
        }
    }
    __syncthreads();

    uint32_t sb = smem_u32(smem);
    int arow = tid >> 2, aq = tid & 3;
    int offL = sL[arow], offR = sR[arow];
    int srow = sRow[arow];
    int j0 = nt * 32;
    int b0 = arow * 128 + aq * 32;
    int b1 = b0 + 16;
    int s0 = b0 ^ ((b0 >> 3) & 0x70);
    int s1 = b1 ^ ((b1 >> 3) & 0x70);
    const uint32_t offA[3] = {OFF_A0, OFF_A1, OFF_A2};

    // prologue group 0: chunk 0 + x/c prefetch
    {
        const __half* ph = hh + offL + aq * 16;
        cp16(sb + OFF_A0 + s0, ph);  cp16(sb + OFF_A0 + s1, ph + 8);
        const __half* xp = g_x + (size_t)srow * XN + j0 * 4 + aq * 32;
        uint32_t xd = sb + OFF_XST + arow * 272 + aq * 64;
        cp16(xd, xp); cp16(xd + 16, xp + 8); cp16(xd + 32, xp + 16); cp16(xd + 48, xp + 24);
        const float* clp = cc + offL + j0 + aq * 8;
        const float* crp = cc + offR + j0 + aq * 8;
        uint32_t cld = sb + OFF_CL + arow * 144 + aq * 32;
        uint32_t crd = sb + OFF_CR + arow * 144 + aq * 32;
        cp16(cld, clp); cp16(cld + 16, clp + 4);
        cp16(crd, crp); cp16(crd + 16, crp + 4);
        CP_COMMIT;
        // prologue group 1: chunk 1
        const __half* p1 = hh + offL + 64 + aq * 16;
        cp16(sb + OFF_A1 + s0, p1);  cp16(sb + OFF_A1 + s1, p1 + 8);
        CP_COMMIT;
    }

    int warp = tid >> 5, lane = tid & 31;
    int warpM = warp & 3, warpN = warp >> 2;

    float acc[2][5][4];
#pragma unroll
    for (int m = 0; m < 2; m++)
#pragma unroll
        for (int f = 0; f < 5; f++)
#pragma unroll
            for (int i = 0; i < 4; i++) acc[m][f][i] = 0.0f;

    int r0 = warpM * 32 + (lane & 15);
    int r1 = r0 + 16;
    int segb = ((lane >> 4) & 1) * 16;

    int tilesel = nt * 2 + (warpN >> 1);
    const __half* pbh = g_UBH + (size_t)tilesel * UB_NT_STRIDE;
    int lanepart = (lane >> 2) * 16 + (lane & 3) * 4;
    int warppart = (warpN & 1) * 640;

    for (int kc = 0; kc < 8; kc++) {
        if (kc < 7) { CP_WAIT1; } else { CP_WAIT0; }
        __syncthreads();          // chunk kc visible; all warps done with buf[(kc+2)%3]
        if (kc < 6) {
            int kcn = kc + 2;
            int off = (kcn < 4) ? offL : offR;
            int k0 = (kcn & 3) * 64;
            const __half* ph = hh + off + k0 + aq * 16;
            uint32_t ab = sb + offA[kcn % 3];
            cp16(ab + s0, ph);  cp16(ab + s1, ph + 8);
            CP_COMMIT;
        }
        uint32_t abh = sb + offA[kc % 3];
#pragma unroll
        for (int s = 0; s < 4; s++) {
            uint32_t ah0[4], ah1[4];
            {
                int o = r0 * 128 + s * 32 + segb; o ^= ((o >> 3) & 0x70);
                ldsm4(ah0, abh + o);
            }
            {
                int o = r1 * 128 + s * 32 + segb; o ^= ((o >> 3) & 0x70);
                ldsm4(ah1, abh + o);
            }
            int be = (kc * 4 + s) * 1280 + warppart + lanepart;
#pragma unroll
            for (int f = 0; f < 5; f++) {
                uint2 bh = *(const uint2*)(pbh + be + f * 128);
                MMA(acc[0][f], ah0, bh.x, bh.y);
                MMA(acc[1][f], ah1, bh.x, bh.y);
            }
        }
    }
    __syncthreads();    // all MMA reads done before stage-region overwrite

    // epilogue: transpose acc through smem, fuse activations
    float* stg = (float*)(smem + OFF_STAGE);
    {
        int rg = lane >> 2, cl = 2 * (lane & 3);
#pragma unroll
        for (int m = 0; m < 2; m++) {
#pragma unroll
            for (int f = 0; f < 5; f++) {
                int row = warpM * 32 + m * 16 + rg;
                int col = warpN * 40 + f * 8 + cl;
                *(float2*)&stg[row * 164 + col] = make_float2(acc[m][f][0], acc[m][f][1]);
                *(float2*)&stg[(row + 8) * 164 + col] = make_float2(acc[m][f][2], acc[m][f][3]);
            }
        }
    }
    __syncthreads();

    {
        int row = arow, ug = aq;
        int od = sD[row];
        const __half2* xh = (const __half2*)(smem + OFF_XST + row * 272 + ug * 64);
        const float* clp = (const float*)(smem + OFF_CL + row * 144 + ug * 32);
        const float* crp = (const float*)(smem + OFF_CR + row * 144 + ug * 32);
        float clv[8], crv[8], ho[8], co[8];
        *(float4*)&clv[0] = *(const float4*)clp;
        *(float4*)&clv[4] = *(const float4*)(clp + 4);
        *(float4*)&crv[0] = *(const float4*)crp;
        *(float4*)&crv[4] = *(const float4*)(crp + 4);
#pragma unroll
        for (int u = 0; u < 8; u++) {
            int col = (ug * 8 + u) * 5;
            float a_i  = stg[row * 164 + col + 0];
            float a_o  = stg[row * 164 + col + 1];
            float a_u  = stg[row * 164 + col + 2];
            float a_fl = stg[row * 164 + col + 3];
            float a_fr = stg[row * 164 + col + 4];
            float2 p0 = __half22float2(xh[2 * u]);
            float2 p1 = __half22float2(xh[2 * u + 1]);
            float gi = sigm(a_i + p0.x);
            float go = sigm(a_o + p0.y);
            float gu = tanhf(a_u + p1.x);
            float fl = sigm(a_fl + p1.y);
            float fr = sigm(a_fr + p1.y);
            float cnew = gi * gu + fl * clv[u] + fr * crv[u];
            ho[u] = go * tanhf(cnew);
            co[u] = cnew;
        }
        if (od >= 0) {
            uint32_t hw[4], lw[4];
#pragma unroll
            for (int p = 0; p < 4; p++) {
                float v0 = ho[2 * p], v1 = ho[2 * p + 1];
                __half a = __float2half_rn(v0);
                __half b = __float2half_rn(v1);
                hw[p] = packh2(v0, v1);
                lw[p] = packh2(v0 - __half2float(a), v1 - __half2float(b));
            }
            int eo = od + j0 + ug * 8;
            *(uint4*)(hhw + eo) = make_uint4(hw[0], hw[1], hw[2], hw[3]);
            *(uint4*)(hlw + eo) = make_uint4(lw[0], lw[1], lw[2], lw[3]);
            *(float4*)(ccw + eo) = *(float4*)&co[0];
            *(float4*)(ccw + eo + 4) = *(float4*)&co[4];
        }
    }
}

// ---------------- final output assembly ----------------
__global__ void k_output(const __half* __restrict__ hh, const __half* __restrict__ hl,
                         const float* __restrict__ cc,
                         float* __restrict__ oh, float* __restrict__ oc) {
    int tid = threadIdx.x;
    int row = blockIdx.x * 16 + (tid >> 5);
    int cg = (tid & 31) * 8;
    size_t oo = ((size_t)row << 8) + cg;
    uint32_t m = g_wmask[row];
    if (m == 0u) {
        float4 z = make_float4(0.f, 0.f, 0.f, 0.f);
        *(float4*)(oh + oo) = z; *(float4*)(oh + oo + 4) = z;
        *(float4*)(oc + oo) = z; *(float4*)(oc + oo + 4) = z;
        return;
    }
    int nw = __popc(m);
    size_t so = (size_t)(((nw - 1) & 1)) * HCNT + oo;
    uint4 rh = *(const uint4*)(hh + so);
    uint4 rl = *(const uint4*)(hl + so);
    const __half2* ph = (const __half2*)&rh;
    const __half2* pl = (const __half2*)&rl;
#pragma unroll
    for (int i = 0; i < 4; i++) {
        float2 a = __half22float2(ph[i]);
        float2 b = __half22float2(pl[i]);
        *(float2*)(oh + oo + 2 * i) = make_float2(a.x + b.x, a.y + b.y);
    }
    *(float4*)(oc + oo) = *(const float4*)(cc + so);
    *(float4*)(oc + oo + 4) = *(const float4*)(cc + so + 4);
}

// ---------------- h_root ----------------
__global__ void k_root(const int* __restrict__ td, const float* __restrict__ out_h,
                       float* __restrict__ out_root) {
    __shared__ int red[256];
    int b = blockIdx.x, tid = threadIdx.x;
    int v = 0;
    for (int s = tid; s < NS; s += 256) v = max(v, td[b * (NT * NS) + (NT - 1) * NS + s]);
    red[tid] = v;
    __syncthreads();
    for (int off = 128; off > 0; off >>= 1) {
        if (tid < off) red[tid] = max(red[tid], red[tid + off]);
        __syncthreads();
    }
    int root = red[0];
    out_root[b * NH + tid] = out_h[(((size_t)(b << 11)) + root) * NH + tid];
}

// ---------------- host launcher (graph-capturable) ----------------
extern "C" void kernel_launch(void* const* d_in, const int* in_sizes, int n_in,
                              void* d_out, int out_size) {
    const float* X     = (const float*)d_in[0];
    const int*   td    = (const int*)d_in[1];
    const int*   tr    = (const int*)d_in[2];
    const int*   tl    = (const int*)d_in[3];
    const float* W_iou = (const float*)d_in[4];
    const float* b_iou = (const float*)d_in[5];
    const float* U_l   = (const float*)d_in[6];
    const float* U_r   = (const float*)d_in[7];
    const float* W_f   = (const float*)d_in[8];
    const float* b_f   = (const float*)d_in[9];
    const float* F_ll  = (const float*)d_in[10];
    const float* F_lr  = (const float*)d_in[11];
    const float* F_rl  = (const float*)d_in[12];
    const float* F_rr  = (const float*)d_in[13];

    float* out      = (float*)d_out;
    float* out_h    = out;
    float* out_c    = out + (size_t)HCNT;
    float* out_root = out + 2 * (size_t)HCNT;

    __half *hhb = nullptr, *hlb = nullptr;
    float* cb = nullptr;
    cudaGetSymbolAddress((void**)&hhb, g_hh);
    cudaGetSymbolAddress((void**)&hlb, g_hl);
    cudaGetSymbolAddress((void**)&cb, g_c);

    static int attr_done = 0;
    if (!attr_done) {
        cudaFuncSetAttribute(k_step_mma, cudaFuncAttributeMaxDynamicSharedMemorySize, SMEM_DYN);
        attr_done = 1;
    }

    k_init<<<4096, 256>>>();
    k_pack_wp<<<(WP_TOTAL + 255) / 256, 256>>>(W_iou, b_iou, W_f, b_f);
    k_pack_ub<<<(UB_TOTAL + 255) / 256, 256>>>(U_l, U_r, F_ll, F_lr, F_rl, F_rr);
    k_winner_all<<<dim3(NROWS / 256, NT), 256>>>(td);
    k_compact_all<<<dim3(NROWS / 256, NT), 256>>>(td);
    k_xgemm_mma<<<dim3(512, 4), 512>>>(X);

    k_step0<<<NROWS / 8, 256>>>(td, hhb, hlb, cb);
    for (int t = 1; t < NT; t++) {
        k_step_mma<<<dim3(NTL, 512), 512, SMEM_DYN>>>(
            t, td, tl, tr, hhb, hlb, cb, hhb, hlb, cb);
    }
    k_output<<<4096, 512>>>(hhb, hlb, cb, out_h, out_c);
    k_root<<<NB, 256>>>(td, out_h, out_root);
}

// round 14
// speedup vs baseline: 5.8799x; 1.0450x over previous
#include <cuda_runtime.h>
#include <cuda_fp16.h>
#include <math.h>
#include <stdint.h>

// ---------------- problem constants ----------------
#define NB 32
#define NS 2048
#define NE 300
#define NH 256
#define NT 24
#define NROWS 65536            // NB*NS
#define XN 1024                 // x-gates per row: j*4 + {i,o,u,f}
#define HCNT 16777216           // NROWS*NH

// ---------------- step-GEMM tiling ----------------
#define BM 128                  // rows per CTA
#define NTL 8                   // 1280 / 160 n-tiles
#define UB_NT_STRIDE 40960      // fp16 elems per 80-col packed tile (8 kchunks)
#define UB_TOTAL (16 * UB_NT_STRIDE)
#define WP_TOTAL (20 * 16384)   // W pack: 20 kcs * 1024 cols * 16

// ---------------- k_step dynamic smem (bytes) ------
#define OFF_IDX   0             // sL/sR/sD/sRow: 4 * 512
#define OFF_A0    2048          // 3 x (128 x 64 fp16 = 16384)
#define OFF_A1    18432
#define OFF_A2    34816
#define OFF_STAGE 2048          // 128 x 164 f32 = 83968 (reuses A bufs) -> 86016
#define OFF_XST   86016         // 128 rows x 272 B (256 + 16 pad) = 34816
#define OFF_CL    120832        // 128 rows x 144 B = 18432
#define OFF_CR    139264        // 128 rows x 144 B = 18432
#define SMEM_DYN  157696

// ---------------- device scratch -------------------
__device__ __half g_x[(size_t)NROWS * XN];    // 128 MiB packed x-gates (fp16)
__device__ __half g_Wp[WP_TOTAL];             // W fragment-native fp16 hi
__device__ float g_bias[XN];
__device__ __half g_UBH[UB_TOTAL];            // U fragment-native fp16 hi
__device__ __half g_hh[2 * (size_t)HCNT];     // h hi, 2 alternation buffers
__device__ __half g_hl[2 * (size_t)HCNT];     // h lo
__device__ float g_c[2 * (size_t)HCNT];       // c fp32
__device__ int      g_win[NT * NROWS];        // per-step winner s for each (b,d)
__device__ uint32_t g_wmask[NROWS];           // bit t: row won at step t
__device__ int      g_work[NT * NROWS];       // per-step compacted winner lists
__device__ int4     g_meta[NT * NROWS];       // per-step {offL, offR, offD, row}
__device__ int      g_cnt[NT];

__device__ __forceinline__ float sigm(float x) { return 1.0f / (1.0f + __expf(-x)); }

__device__ __forceinline__ uint32_t smem_u32(const void* p) {
    uint32_t r;
    asm("{ .reg .u64 t; cvta.to.shared.u64 t, %1; cvt.u32.u64 %0, t; }" : "=r"(r) : "l"(p));
    return r;
}
__device__ __forceinline__ void ldsm4(uint32_t* r, uint32_t addr) {
    asm volatile("ldmatrix.sync.aligned.m8n8.x4.shared.b16 {%0,%1,%2,%3}, [%4];"
                 : "=r"(r[0]), "=r"(r[1]), "=r"(r[2]), "=r"(r[3]) : "r"(addr));
}
#define MMA(d, a, bx, by) asm volatile( \
    "mma.sync.aligned.m16n8k16.row.col.f32.f16.f16.f32 " \
    "{%0,%1,%2,%3},{%4,%5,%6,%7},{%8,%9},{%0,%1,%2,%3};" \
    : "+f"((d)[0]), "+f"((d)[1]), "+f"((d)[2]), "+f"((d)[3]) \
    : "r"((a)[0]), "r"((a)[1]), "r"((a)[2]), "r"((a)[3]), "r"(bx), "r"(by))

__device__ __forceinline__ void cp16(uint32_t dst, const void* src) {
    asm volatile("{\n\t.reg .u64 g;\n\tcvta.to.global.u64 g, %1;\n\t"
                 "cp.async.cg.shared.global [%0], [g], 16;\n\t}"
                 :: "r"(dst), "l"(src) : "memory");
}
#define CP_COMMIT asm volatile("cp.async.commit_group;" ::: "memory")
#define CP_WAIT1  asm volatile("cp.async.wait_group 1;" ::: "memory")
#define CP_WAIT0  asm volatile("cp.async.wait_group 0;" ::: "memory")

__device__ __forceinline__ uint32_t packh2(float a, float b) {
    __half2 v = __floats2half2_rn(a, b);
    return *(uint32_t*)&v;
}

// ---------------- init: zero ONLY buffer 1 of state (buf0 always written
// before first read: readers with n prior writes read buf[(n+1)&1]) ----------
__global__ void k_init() {
    size_t i = (size_t)blockIdx.x * blockDim.x + threadIdx.x;
    size_t stride = (size_t)gridDim.x * blockDim.x;
    uint32_t* ph = (uint32_t*)g_hh;   // u32 p covers halves 2p,2p+1
    uint32_t* pl = (uint32_t*)g_hl;
    for (size_t p = (size_t)(HCNT / 2) + i; p < (size_t)HCNT; p += stride) {
        ph[p] = 0u; pl[p] = 0u;
    }
    for (size_t p = (size_t)HCNT + i; p < 2 * (size_t)HCNT; p += stride) g_c[p] = 0.0f;
    for (size_t p = i; p < (size_t)(NT * NROWS); p += stride) g_win[p] = -1;
    for (size_t p = i; p < (size_t)NROWS; p += stride) g_wmask[p] = 0u;
    if (i < NT) g_cnt[i] = 0;
}

// ---- pack W: fragment-native fp16 hi; also bias ----
__global__ void k_pack_wp(const float* __restrict__ W_iou, const float* __restrict__ b_iou,
                          const float* __restrict__ W_f,   const float* __restrict__ b_f) {
    int idx = blockIdx.x * blockDim.x + threadIdx.x;
    if (idx < WP_TOTAL) {
        int kcs = idx >> 14;
        int rem = idx & 16383;
        int ncol = rem >> 4, low = rem & 15;
        int c = low >> 2, e = low & 3;
        int kin = (e < 2) ? (2 * c + e) : (8 + 2 * c + (e - 2));
        int k = (kcs >> 2) * 64 + (kcs & 3) * 16 + kin;
        int j = ncol >> 2, g = ncol & 3;
        float v = 0.0f;
        if (k < NE) v = (g < 3) ? W_iou[k * 768 + g * 256 + j] : W_f[k * 256 + j];
        g_Wp[idx] = __float2half_rn(v);
    }
    if (idx < XN) {
        int j = idx >> 2, g = idx & 3;
        g_bias[idx] = (g < 3) ? b_iou[g * 256 + j] : b_f[j];
    }
}

// ---- pack U: fragment-native fp16 hi (16 tiles of 80 cols) ----
__global__ void k_pack_ub(const float* __restrict__ Ul, const float* __restrict__ Ur,
                          const float* __restrict__ Fll, const float* __restrict__ Flr,
                          const float* __restrict__ Frl, const float* __restrict__ Frr) {
    int idx = blockIdx.x * blockDim.x + threadIdx.x;
    if (idx >= UB_TOTAL) return;
    int e = idx & 3, c = (idx >> 2) & 3;
    int n = (idx >> 4) % 80;
    int q = (idx >> 4) / 80;           // ntl*32 + kc*4 + s
    int s = q & 3, kc = (q >> 2) & 7, ntl = q >> 5;
    int kin = (e < 2) ? (2 * c + e) : (8 + 2 * c + (e - 2));
    int k = kc * 64 + s * 16 + kin;
    int ncol = ntl * 80 + n;
    int j = ncol / 5, g = ncol - 5 * j;
    float v;
    if (k < 256) {
        v = (g == 0) ? Ul[k * 768 + j]
          : (g == 1) ? Ul[k * 768 + 256 + j]
          : (g == 2) ? Ul[k * 768 + 512 + j]
          : (g == 3) ? Fll[k * 256 + j]
                     : Frl[k * 256 + j];
    } else {
        int kr = k - 256;
        v = (g == 0) ? Ur[kr * 768 + j]
          : (g == 1) ? Ur[kr * 768 + 256 + j]
          : (g == 2) ? Ur[kr * 768 + 512 + j]
          : (g == 3) ? Flr[kr * 256 + j]
                     : Frr[kr * 256 + j];
    }
    g_UBH[idx] = __float2half_rn(v);
}

// ---------------- tensorized x-projection: g_x = fp16(X @ W + b) ----------------
__global__ __launch_bounds__(512, 1) void k_xgemm_mma(const float* __restrict__ X) {
    __shared__ __align__(16) char xs[32768];   // AH 16K | AL 16K
    int mt = blockIdx.x, nt = blockIdx.y;
    int tid = threadIdx.x;
    int warp = tid >> 5, lane = tid & 31;
    int warpM = warp & 3, warpN = warp >> 2;
    uint32_t sb = smem_u32(xs);

    int arow = tid >> 2, aq = tid & 3;
    int b0 = arow * 128 + aq * 32;
    int s0 = b0 ^ ((b0 >> 3) & 0x70);
    int s1 = (b0 + 16) ^ (((b0 + 16) >> 3) & 0x70);
    const float* xrow = X + (size_t)(mt * 128 + arow) * NE;

    float acc[2][8][4];
#pragma unroll
    for (int m = 0; m < 2; m++)
#pragma unroll
        for (int f = 0; f < 8; f++)
#pragma unroll
            for (int i = 0; i < 4; i++) acc[m][f][i] = 0.0f;

    int r0 = warpM * 32 + (lane & 15);
    int r1 = r0 + 16;
    int segb = ((lane >> 4) & 1) * 16;
    int lanepart = (lane >> 2) * 16 + (lane & 3) * 4;
    int nbase = (nt * 256 + warpN * 64) * 16 + lanepart;

    float v[16];
    {
        int k0 = aq * 16;
#pragma unroll
        for (int i = 0; i < 4; i++) *(float4*)&v[i * 4] = *(const float4*)(xrow + k0 + i * 4);
    }

    for (int kc = 0; kc < 5; kc++) {
        __syncthreads();
        {
            uint4 ph, pl;
            uint32_t* hp = (uint32_t*)&ph;
            uint32_t* lp = (uint32_t*)&pl;
#pragma unroll
            for (int p = 0; p < 4; p++) {
                float a = v[2 * p], b = v[2 * p + 1];
                __half ha = __float2half_rn(a), hb = __float2half_rn(b);
                hp[p] = packh2(a, b);
                lp[p] = packh2(a - __half2float(ha), b - __half2float(hb));
            }
            *(uint4*)(xs + s0) = ph;
            *(uint4*)(xs + 16384 + s0) = pl;
#pragma unroll
            for (int p = 0; p < 4; p++) {
                float a = v[8 + 2 * p], b = v[8 + 2 * p + 1];
                __half ha = __float2half_rn(a), hb = __float2half_rn(b);
                hp[p] = packh2(a, b);
                lp[p] = packh2(a - __half2float(ha), b - __half2float(hb));
            }
            *(uint4*)(xs + s1) = ph;
            *(uint4*)(xs + 16384 + s1) = pl;
        }
        __syncthreads();
        if (kc < 4) {
            int k0 = (kc + 1) * 64 + aq * 16;
            if (k0 + 15 < NE) {
#pragma unroll
                for (int i = 0; i < 4; i++) *(float4*)&v[i * 4] = *(const float4*)(xrow + k0 + i * 4);
            } else {
#pragma unroll
                for (int i = 0; i < 16; i++) v[i] = (k0 + i < NE) ? xrow[k0 + i] : 0.0f;
            }
        }
#pragma unroll
        for (int s = 0; s < 4; s++) {
            uint32_t ah0[4], ah1[4], al0[4], al1[4];
            {
                int o = r0 * 128 + s * 32 + segb; o ^= ((o >> 3) & 0x70);
                ldsm4(ah0, sb + o); ldsm4(al0, sb + 16384 + o);
            }
            {
                int o = r1 * 128 + s * 32 + segb; o ^= ((o >> 3) & 0x70);
                ldsm4(ah1, sb + o); ldsm4(al1, sb + 16384 + o);
            }
            const __half* pb = g_Wp + (size_t)(kc * 4 + s) * 16384 + nbase;
#pragma unroll
            for (int f = 0; f < 8; f++) {
                uint2 bh = *(const uint2*)(pb + f * 128);
                MMA(acc[0][f], ah0, bh.x, bh.y);
                MMA(acc[1][f], ah1, bh.x, bh.y);
                MMA(acc[0][f], al0, bh.x, bh.y);
                MMA(acc[1][f], al1, bh.x, bh.y);
            }
        }
    }

    int rg = lane >> 2, c2 = (lane & 3) * 2;
#pragma unroll
    for (int f = 0; f < 8; f++) {
        int col = nt * 256 + warpN * 64 + f * 8 + c2;
        float2 bb = *(const float2*)&g_bias[col];
#pragma unroll
        for (int m = 0; m < 2; m++) {
            int row = mt * 128 + warpM * 32 + m * 16 + rg;
            *(uint32_t*)&g_x[(size_t)row * XN + col] =
                packh2(acc[m][f][0] + bb.x, acc[m][f][1] + bb.y);
            *(uint32_t*)&g_x[(size_t)(row + 8) * XN + col] =
                packh2(acc[m][f][2] + bb.x, acc[m][f][3] + bb.y);
        }
    }
}

// ---------------- winner/compact/prep: ALL steps in 3 launches ----------------
__global__ void k_winner_all(const int* __restrict__ td) {
    int t = blockIdx.y;
    int idx = blockIdx.x * blockDim.x + threadIdx.x;
    int b = idx >> 11, s = idx & 2047;
    int d = td[b * (NT * NS) + t * NS + s];
    atomicMax(&g_win[t * NROWS + (b << 11) + d], s);
}

__global__ void k_compact_all(const int* __restrict__ td) {
    __shared__ int scnt, sbase;
    int t = blockIdx.y;
    int tid = threadIdx.x;
    if (tid == 0) scnt = 0;
    __syncthreads();
    int idx = blockIdx.x * blockDim.x + tid;
    int b = idx >> 11, s = idx & 2047;
    int d = td[b * (NT * NS) + t * NS + s];
    int dd = (b << 11) + d;
    bool win = (d != 0) && (g_win[t * NROWS + dd] == s);
    int pos = 0;
    if (win) pos = atomicAdd(&scnt, 1);
    __syncthreads();
    if (tid == 0) sbase = atomicAdd(&g_cnt[t], scnt);
    __syncthreads();
    if (win) {
        g_work[t * NROWS + sbase + pos] = idx;
        atomicOr(&g_wmask[dd], 1u << t);
    }
}

// after wmask is complete: resolve all per-row offsets once
__global__ void k_prep_all(const int* __restrict__ td, const int* __restrict__ tl,
                           const int* __restrict__ tr) {
    int t = blockIdx.y;
    int i = blockIdx.x * blockDim.x + threadIdx.x;
    if (i >= g_cnt[t]) return;
    int idx = g_work[t * NROWS + i];
    int b = idx >> 11, s = idx & 2047;
    int tb = b * (NT * NS) + t * NS + s;
    int brow = b << 11;
    int rl = brow + tl[tb];
    int rr = brow + tr[tb];
    int rd = brow + td[tb];
    uint32_t below = (1u << t) - 1u;
    int nl = __popc(g_wmask[rl] & below);
    int nr = __popc(g_wmask[rr] & below);
    int nd = __popc(g_wmask[rd] & below);
    // readers use buf[(n+1)&1]; writer uses buf[n&1] -> never collide
    g_meta[t * NROWS + i] = make_int4(
        ((nl + 1) & 1) * HCNT + (rl << 8),
        ((nr + 1) & 1) * HCNT + (rr << 8),
        (nd & 1) * HCNT + (rd << 8),
        idx);
}

// ---------------- step 0: h==0 -> pure elementwise from x ----------------
// grid 8192 x 256: 8 winner rows per CTA, 32 threads/row, 8 units/thread
__global__ void k_step0(__half* __restrict__ hhw, __half* __restrict__ hlw,
                        float* __restrict__ ccw) {
    int count = g_cnt[0];
    int tid = threadIdx.x;
    int m = blockIdx.x * 8 + (tid >> 5);
    if (m >= count) return;
    int lane = tid & 31;
    int4 v = g_meta[m];          // t = 0
    int eo = v.z + lane * 8;     // offD (buffer 0 at t=0)
    // this thread's 8 units need 32 halves (64 bytes) of x = 4 uint4
    const uint4* xp = (const uint4*)(g_x + (size_t)v.w * XN + (size_t)lane * 32);
    uint4 xr[4];
#pragma unroll
    for (int i = 0; i < 4; i++) xr[i] = xp[i];
    const __half2* xh = (const __half2*)xr;
    float ho[8], co[8];
#pragma unroll
    for (int u = 0; u < 8; u++) {
        float2 p0 = __half22float2(xh[2 * u]);      // x_i, x_o
        float2 p1 = __half22float2(xh[2 * u + 1]);  // x_u, x_f
        float gi = sigm(p0.x);
        float go = sigm(p0.y);
        float gu = tanhf(p1.x);
        float cn = gi * gu;                          // c_l = c_r = 0
        ho[u] = go * tanhf(cn);
        co[u] = cn;
    }
    uint32_t hw[4], lw[4];
#pragma unroll
    for (int p = 0; p < 4; p++) {
        float v0 = ho[2 * p], v1 = ho[2 * p + 1];
        __half a = __float2half_rn(v0);
        __half bb = __float2half_rn(v1);
        hw[p] = packh2(v0, v1);
        lw[p] = packh2(v0 - __half2float(a), v1 - __half2float(bb));
    }
    *(uint4*)(hhw + eo) = make_uint4(hw[0], hw[1], hw[2], hw[3]);
    *(uint4*)(hlw + eo) = make_uint4(lw[0], lw[1], lw[2], lw[3]);
    *(float4*)(ccw + eo) = *(float4*)&co[0];
    *(float4*)(ccw + eo + 4) = *(float4*)&co[4];
}

// ---------------- fused step: fp16 mma, 3-buf pipeline, mid-loop x/c prefetch ----
// grid = (8, 512), 512 threads (16 warps: 4M x 4N)
__global__ __launch_bounds__(512, 1) void k_step_mma(
    int t,
    const __half* __restrict__ hh, const __half* __restrict__ hl,
    const float* __restrict__ cc,
    __half* __restrict__ hhw, __half* __restrict__ hlw, float* __restrict__ ccw)
{
    extern __shared__ char smem[];
    int tid = threadIdx.x;
    int count = g_cnt[t];
    int mt = blockIdx.y;
    if (mt * BM >= count) return;
    int nt = blockIdx.x;

    int* sL = (int*)(smem + OFF_IDX);
    int* sR = (int*)(smem + OFF_IDX + 512);
    int* sD = (int*)(smem + OFF_IDX + 1024);
    int* sRow = (int*)(smem + OFF_IDX + 1536);

    if (tid < BM) {
        int m = mt * BM + tid;
        int4 v = (m < count) ? g_meta[t * NROWS + m] : make_int4(0, 0, -1, 0);
        sL[tid] = v.x; sR[tid] = v.y; sD[tid] = v.z; sRow[tid] = v.w;
    }
    __syncthreads();

    uint32_t sb = smem_u32(smem);
    int arow = tid >> 2, aq = tid & 3;
    int offL = sL[arow], offR = sR[arow];
    int srow = sRow[arow];
    int j0 = nt * 32;
    int b0 = arow * 128 + aq * 32;
    int b1 = b0 + 16;
    int s0 = b0 ^ ((b0 >> 3) & 0x70);
    int s1 = b1 ^ ((b1 >> 3) & 0x70);
    const uint32_t offA[3] = {OFF_A0, OFF_A1, OFF_A2};

    // prologue: group 0 = chunk 0 only (minimal critical path); group 1 = chunk 1
    {
        const __half* ph = hh + offL + aq * 16;
        cp16(sb + OFF_A0 + s0, ph);  cp16(sb + OFF_A0 + s1, ph + 8);
        CP_COMMIT;
        const __half* p1 = hh + offL + 64 + aq * 16;
        cp16(sb + OFF_A1 + s0, p1);  cp16(sb + OFF_A1 + s1, p1 + 8);
        CP_COMMIT;
    }

    int warp = tid >> 5, lane = tid & 31;
    int warpM = warp & 3, warpN = warp >> 2;

    float acc[2][5][4];
#pragma unroll
    for (int m = 0; m < 2; m++)
#pragma unroll
        for (int f = 0; f < 5; f++)
#pragma unroll
            for (int i = 0; i < 4; i++) acc[m][f][i] = 0.0f;

    int r0 = warpM * 32 + (lane & 15);
    int r1 = r0 + 16;
    int segb = ((lane >> 4) & 1) * 16;

    int tilesel = nt * 2 + (warpN >> 1);
    const __half* pbh = g_UBH + (size_t)tilesel * UB_NT_STRIDE;
    int lanepart = (lane >> 2) * 16 + (lane & 3) * 4;
    int warppart = (warpN & 1) * 640;

    for (int kc = 0; kc < 8; kc++) {
        if (kc < 7) { CP_WAIT1; } else { CP_WAIT0; }
        __syncthreads();          // chunk kc visible to ALL warps; buf[(kc+2)%3] free
        if (kc < 6) {
            int kcn = kc + 2;
            int off = (kcn < 4) ? offL : offR;
            int k0 = (kcn & 3) * 64;
            const __half* ph = hh + off + k0 + aq * 16;
            uint32_t ab = sb + offA[kcn % 3];
            cp16(ab + s0, ph);  cp16(ab + s1, ph + 8);
            if (kc == 3) {
                // x/c epilogue prefetch rides in this group (chunk 5's):
                // overlaps chunks 3..7 MMA, drained by the kc==5 wait.
                const __half* xp = g_x + (size_t)srow * XN + j0 * 4 + aq * 32;
                uint32_t xd = sb + OFF_XST + arow * 272 + aq * 64;
                cp16(xd, xp); cp16(xd + 16, xp + 8);
                cp16(xd + 32, xp + 16); cp16(xd + 48, xp + 24);
                const float* clp = cc + offL + j0 + aq * 8;
                const float* crp = cc + offR + j0 + aq * 8;
                uint32_t cld = sb + OFF_CL + arow * 144 + aq * 32;
                uint32_t crd = sb + OFF_CR + arow * 144 + aq * 32;
                cp16(cld, clp); cp16(cld + 16, clp + 4);
                cp16(crd, crp); cp16(crd + 16, crp + 4);
            }
            CP_COMMIT;
        }
        uint32_t abh = sb + offA[kc % 3];
#pragma unroll
        for (int s = 0; s < 4; s++) {
            uint32_t ah0[4], ah1[4];
            {
                int o = r0 * 128 + s * 32 + segb; o ^= ((o >> 3) & 0x70);
                ldsm4(ah0, abh + o);
            }
            {
                int o = r1 * 128 + s * 32 + segb; o ^= ((o >> 3) & 0x70);
                ldsm4(ah1, abh + o);
            }
            int be = (kc * 4 + s) * 1280 + warppart + lanepart;
#pragma unroll
            for (int f = 0; f < 5; f++) {
                uint2 bh = *(const uint2*)(pbh + be + f * 128);
                MMA(acc[0][f], ah0, bh.x, bh.y);
                MMA(acc[1][f], ah1, bh.x, bh.y);
            }
        }
    }
    __syncthreads();    // all MMA reads done before stage-region overwrite

    // epilogue: transpose acc through smem, fuse activations
    float* stg = (float*)(smem + OFF_STAGE);
    {
        int rg = lane >> 2, cl = 2 * (lane & 3);
#pragma unroll
        for (int m = 0; m < 2; m++) {
#pragma unroll
            for (int f = 0; f < 5; f++) {
                int row = warpM * 32 + m * 16 + rg;
                int col = warpN * 40 + f * 8 + cl;
                *(float2*)&stg[row * 164 + col] = make_float2(acc[m][f][0], acc[m][f][1]);
                *(float2*)&stg[(row + 8) * 164 + col] = make_float2(acc[m][f][2], acc[m][f][3]);
            }
        }
    }
    __syncthreads();

    {
        int row = arow, ug = aq;
        int od = sD[row];
        const __half2* xh = (const __half2*)(smem + OFF_XST + row * 272 + ug * 64);
        const float* clp = (const float*)(smem + OFF_CL + row * 144 + ug * 32);
        const float* crp = (const float*)(smem + OFF_CR + row * 144 + ug * 32);
        float clv[8], crv[8], ho[8], co[8];
        *(float4*)&clv[0] = *(const float4*)clp;
        *(float4*)&clv[4] = *(const float4*)(clp + 4);
        *(float4*)&crv[0] = *(const float4*)crp;
        *(float4*)&crv[4] = *(const float4*)(crp + 4);
#pragma unroll
        for (int u = 0; u < 8; u++) {
            int col = (ug * 8 + u) * 5;
            float a_i  = stg[row * 164 + col + 0];
            float a_o  = stg[row * 164 + col + 1];
            float a_u  = stg[row * 164 + col + 2];
            float a_fl = stg[row * 164 + col + 3];
            float a_fr = stg[row * 164 + col + 4];
            float2 p0 = __half22float2(xh[2 * u]);
            float2 p1 = __half22float2(xh[2 * u + 1]);
            float gi = sigm(a_i + p0.x);
            float go = sigm(a_o + p0.y);
            float gu = tanhf(a_u + p1.x);
            float fl = sigm(a_fl + p1.y);
            float fr = sigm(a_fr + p1.y);
            float cnew = gi * gu + fl * clv[u] + fr * crv[u];
            ho[u] = go * tanhf(cnew);
            co[u] = cnew;
        }
        if (od >= 0) {
            uint32_t hw[4], lw[4];
#pragma unroll
            for (int p = 0; p < 4; p++) {
                float v0 = ho[2 * p], v1 = ho[2 * p + 1];
                __half a = __float2half_rn(v0);
                __half b = __float2half_rn(v1);
                hw[p] = packh2(v0, v1);
                lw[p] = packh2(v0 - __half2float(a), v1 - __half2float(b));
            }
            int eo = od + j0 + ug * 8;
            *(uint4*)(hhw + eo) = make_uint4(hw[0], hw[1], hw[2], hw[3]);
            *(uint4*)(hlw + eo) = make_uint4(lw[0], lw[1], lw[2], lw[3]);
            *(float4*)(ccw + eo) = *(float4*)&co[0];
            *(float4*)(ccw + eo + 4) = *(float4*)&co[4];
        }
    }
}

// ---------------- final output assembly ----------------
__global__ void k_output(const __half* __restrict__ hh, const __half* __restrict__ hl,
                         const float* __restrict__ cc,
                         float* __restrict__ oh, float* __restrict__ oc) {
    int tid = threadIdx.x;
    int row = blockIdx.x * 16 + (tid >> 5);
    int cg = (tid & 31) * 8;
    size_t oo = ((size_t)row << 8) + cg;
    uint32_t m = g_wmask[row];
    if (m == 0u) {
        float4 z = make_float4(0.f, 0.f, 0.f, 0.f);
        *(float4*)(oh + oo) = z; *(float4*)(oh + oo + 4) = z;
        *(float4*)(oc + oo) = z; *(float4*)(oc + oo + 4) = z;
        return;
    }
    int nw = __popc(m);
    size_t so = (size_t)(((nw - 1) & 1)) * HCNT + oo;
    uint4 rh = *(const uint4*)(hh + so);
    uint4 rl = *(const uint4*)(hl + so);
    const __half2* ph = (const __half2*)&rh;
    const __half2* pl = (const __half2*)&rl;
#pragma unroll
    for (int i = 0; i < 4; i++) {
        float2 a = __half22float2(ph[i]);
        float2 b = __half22float2(pl[i]);
        *(float2*)(oh + oo + 2 * i) = make_float2(a.x + b.x, a.y + b.y);
    }
    *(float4*)(oc + oo) = *(const float4*)(cc + so);
    *(float4*)(oc + oo + 4) = *(const float4*)(cc + so + 4);
}

// ---------------- h_root ----------------
__global__ void k_root(const int* __restrict__ td, const float* __restrict__ out_h,
                       float* __restrict__ out_root) {
    __shared__ int red[256];
    int b = blockIdx.x, tid = threadIdx.x;
    int v = 0;
    for (int s = tid; s < NS; s += 256) v = max(v, td[b * (NT * NS) + (NT - 1) * NS + s]);
    red[tid] = v;
    __syncthreads();
    for (int off = 128; off > 0; off >>= 1) {
        if (tid < off) red[tid] = max(red[tid], red[tid + off]);
        __syncthreads();
    }
    int root = red[0];
    out_root[b * NH + tid] = out_h[(((size_t)(b << 11)) + root) * NH + tid];
}

// ---------------- host launcher (graph-capturable) ----------------
extern "C" void kernel_launch(void* const* d_in, const int* in_sizes, int n_in,
                              void* d_out, int out_size) {
    const float* X     = (const float*)d_in[0];
    const int*   td    = (const int*)d_in[1];
    const int*   tr    = (const int*)d_in[2];
    const int*   tl    = (const int*)d_in[3];
    const float* W_iou = (const float*)d_in[4];
    const float* b_iou = (const float*)d_in[5];
    const float* U_l   = (const float*)d_in[6];
    const float* U_r   = (const float*)d_in[7];
    const float* W_f   = (const float*)d_in[8];
    const float* b_f   = (const float*)d_in[9];
    const float* F_ll  = (const float*)d_in[10];
    const float* F_lr  = (const float*)d_in[11];
    const float* F_rl  = (const float*)d_in[12];
    const float* F_rr  = (const float*)d_in[13];

    float* out      = (float*)d_out;
    float* out_h    = out;
    float* out_c    = out + (size_t)HCNT;
    float* out_root = out + 2 * (size_t)HCNT;

    __half *hhb = nullptr, *hlb = nullptr;
    float* cb = nullptr;
    cudaGetSymbolAddress((void**)&hhb, g_hh);
    cudaGetSymbolAddress((void**)&hlb, g_hl);
    cudaGetSymbolAddress((void**)&cb, g_c);

    static int attr_done = 0;
    if (!attr_done) {
        cudaFuncSetAttribute(k_step_mma, cudaFuncAttributeMaxDynamicSharedMemorySize, SMEM_DYN);
        attr_done = 1;
    }

    k_init<<<4096, 256>>>();
    k_pack_wp<<<(WP_TOTAL + 255) / 256, 256>>>(W_iou, b_iou, W_f, b_f);
    k_pack_ub<<<(UB_TOTAL + 255) / 256, 256>>>(U_l, U_r, F_ll, F_lr, F_rl, F_rr);
    k_winner_all<<<dim3(NROWS / 256, NT), 256>>>(td);
    k_compact_all<<<dim3(NROWS / 256, NT), 256>>>(td);
    k_prep_all<<<dim3(NROWS / 256, NT), 256>>>(td, tl, tr);
    k_xgemm_mma<<<dim3(512, 4), 512>>>(X);

    k_step0<<<NROWS / 8, 256>>>(hhb, hlb, cb);
    for (int t = 1; t < NT; t++) {
        k_step_mma<<<dim3(NTL, 512), 512, SMEM_DYN>>>(
            t, hhb, hlb, cb, hhb, hlb, cb);
    }
    k_output<<<4096, 512>>>(hhb, hlb, cb, out_h, out_c);
    k_root<<<NB, 256>>>(td, out_h, out_root);
}

// round 15
// speedup vs baseline: 6.5188x; 1.1087x over previous
#include <cuda_runtime.h>
#include <cuda_fp16.h>
#include <math.h>
#include <stdint.h>

// ---------------- problem constants ----------------
#define NB 32
#define NS 2048
#define NE 300
#define NH 256
#define NT 24
#define NROWS 65536            // NB*NS
#define XN 1024                 // x-gates per row: j*4 + {i,o,u,f}
#define HCNT 16777216           // NROWS*NH

// ---------------- step-GEMM tiling ----------------
#define BM 128                  // rows per CTA
#define NTL 8                   // 1280 / 160 n-tiles
#define UB_NT_STRIDE 40960      // fp16 elems per 80-col packed tile (8 kchunks)
#define UB_TOTAL (16 * UB_NT_STRIDE)
#define WP_TOTAL (20 * 16384)   // W pack: 20 kcs * 1024 cols * 16

// ---------------- k_step dynamic smem (bytes) ------
// occupancy-2 layout: 86016 B/CTA -> 2 CTAs/SM (172 KB of 228 KB)
#define OFF_IDX   0             // sL/sR/sD/sRow: 4 * 512
#define OFF_A0    2048          // 3 x (128 x 64 fp16 = 16384)
#define OFF_A1    18432
#define OFF_A2    34816
#define OFF_STAGE 2048          // 128 x 164 f32 = 83968 (reuses A bufs)
#define SMEM_DYN  86016

// ---------------- device scratch -------------------
__device__ __half g_x[(size_t)NROWS * XN];    // 128 MiB packed x-gates (fp16)
__device__ __half g_Wp[WP_TOTAL];             // W fragment-native fp16 hi
__device__ float g_bias[XN];
__device__ __half g_UBH[UB_TOTAL];            // U fragment-native fp16 hi
__device__ __half g_hh[2 * (size_t)HCNT];     // h hi, 2 alternation buffers
__device__ __half g_hl[2 * (size_t)HCNT];     // h lo
__device__ float g_c[2 * (size_t)HCNT];       // c fp32
__device__ int      g_win[NT * NROWS];        // per-step winner s for each (b,d)
__device__ uint32_t g_wmask[NROWS];           // bit t: row won at step t
__device__ int      g_work[NT * NROWS];       // per-step compacted winner lists
__device__ int4     g_meta[NT * NROWS];       // per-step {offL, offR, offD, row}
__device__ int      g_cnt[NT];

__device__ __forceinline__ float sigm(float x) { return 1.0f / (1.0f + __expf(-x)); }

__device__ __forceinline__ uint32_t smem_u32(const void* p) {
    uint32_t r;
    asm("{ .reg .u64 t; cvta.to.shared.u64 t, %1; cvt.u32.u64 %0, t; }" : "=r"(r) : "l"(p));
    return r;
}
__device__ __forceinline__ void ldsm4(uint32_t* r, uint32_t addr) {
    asm volatile("ldmatrix.sync.aligned.m8n8.x4.shared.b16 {%0,%1,%2,%3}, [%4];"
                 : "=r"(r[0]), "=r"(r[1]), "=r"(r[2]), "=r"(r[3]) : "r"(addr));
}
#define MMA(d, a, bx, by) asm volatile( \
    "mma.sync.aligned.m16n8k16.row.col.f32.f16.f16.f32 " \
    "{%0,%1,%2,%3},{%4,%5,%6,%7},{%8,%9},{%0,%1,%2,%3};" \
    : "+f"((d)[0]), "+f"((d)[1]), "+f"((d)[2]), "+f"((d)[3]) \
    : "r"((a)[0]), "r"((a)[1]), "r"((a)[2]), "r"((a)[3]), "r"(bx), "r"(by))

__device__ __forceinline__ void cp16(uint32_t dst, const void* src) {
    asm volatile("{\n\t.reg .u64 g;\n\tcvta.to.global.u64 g, %1;\n\t"
                 "cp.async.cg.shared.global [%0], [g], 16;\n\t}"
                 :: "r"(dst), "l"(src) : "memory");
}
#define CP_COMMIT asm volatile("cp.async.commit_group;" ::: "memory")
#define CP_WAIT1  asm volatile("cp.async.wait_group 1;" ::: "memory")
#define CP_WAIT0  asm volatile("cp.async.wait_group 0;" ::: "memory")

__device__ __forceinline__ uint32_t packh2(float a, float b) {
    __half2 v = __floats2half2_rn(a, b);
    return *(uint32_t*)&v;
}

// ---------------- init: zero ONLY buffer 1 of state (buf0 always written
// before first read: readers with n prior writes read buf[(n+1)&1]) ----------
__global__ void k_init() {
    size_t i = (size_t)blockIdx.x * blockDim.x + threadIdx.x;
    size_t stride = (size_t)gridDim.x * blockDim.x;
    uint32_t* ph = (uint32_t*)g_hh;   // u32 p covers halves 2p,2p+1
    uint32_t* pl = (uint32_t*)g_hl;
    for (size_t p = (size_t)(HCNT / 2) + i; p < (size_t)HCNT; p += stride) {
        ph[p] = 0u; pl[p] = 0u;
    }
    for (size_t p = (size_t)HCNT + i; p < 2 * (size_t)HCNT; p += stride) g_c[p] = 0.0f;
    for (size_t p = i; p < (size_t)(NT * NROWS); p += stride) g_win[p] = -1;
    for (size_t p = i; p < (size_t)NROWS; p += stride) g_wmask[p] = 0u;
    if (i < NT) g_cnt[i] = 0;
}

// ---- pack W: fragment-native fp16 hi; also bias ----
__global__ void k_pack_wp(const float* __restrict__ W_iou, const float* __restrict__ b_iou,
                          const float* __restrict__ W_f,   const float* __restrict__ b_f) {
    int idx = blockIdx.x * blockDim.x + threadIdx.x;
    if (idx < WP_TOTAL) {
        int kcs = idx >> 14;
        int rem = idx & 16383;
        int ncol = rem >> 4, low = rem & 15;
        int c = low >> 2, e = low & 3;
        int kin = (e < 2) ? (2 * c + e) : (8 + 2 * c + (e - 2));
        int k = (kcs >> 2) * 64 + (kcs & 3) * 16 + kin;
        int j = ncol >> 2, g = ncol & 3;
        float v = 0.0f;
        if (k < NE) v = (g < 3) ? W_iou[k * 768 + g * 256 + j] : W_f[k * 256 + j];
        g_Wp[idx] = __float2half_rn(v);
    }
    if (idx < XN) {
        int j = idx >> 2, g = idx & 3;
        g_bias[idx] = (g < 3) ? b_iou[g * 256 + j] : b_f[j];
    }
}

// ---- pack U: fragment-native fp16 hi (16 tiles of 80 cols) ----
__global__ void k_pack_ub(const float* __restrict__ Ul, const float* __restrict__ Ur,
                          const float* __restrict__ Fll, const float* __restrict__ Flr,
                          const float* __restrict__ Frl, const float* __restrict__ Frr) {
    int idx = blockIdx.x * blockDim.x + threadIdx.x;
    if (idx >= UB_TOTAL) return;
    int e = idx & 3, c = (idx >> 2) & 3;
    int n = (idx >> 4) % 80;
    int q = (idx >> 4) / 80;           // ntl*32 + kc*4 + s
    int s = q & 3, kc = (q >> 2) & 7, ntl = q >> 5;
    int kin = (e < 2) ? (2 * c + e) : (8 + 2 * c + (e - 2));
    int k = kc * 64 + s * 16 + kin;
    int ncol = ntl * 80 + n;
    int j = ncol / 5, g = ncol - 5 * j;
    float v;
    if (k < 256) {
        v = (g == 0) ? Ul[k * 768 + j]
          : (g == 1) ? Ul[k * 768 + 256 + j]
          : (g == 2) ? Ul[k * 768 + 512 + j]
          : (g == 3) ? Fll[k * 256 + j]
                     : Frl[k * 256 + j];
    } else {
        int kr = k - 256;
        v = (g == 0) ? Ur[kr * 768 + j]
          : (g == 1) ? Ur[kr * 768 + 256 + j]
          : (g == 2) ? Ur[kr * 768 + 512 + j]
          : (g == 3) ? Flr[kr * 256 + j]
                     : Frr[kr * 256 + j];
    }
    g_UBH[idx] = __float2half_rn(v);
}

// ---------------- tensorized x-projection: g_x = fp16(X @ W + b) ----------------
__global__ __launch_bounds__(512, 1) void k_xgemm_mma(const float* __restrict__ X) {
    __shared__ __align__(16) char xs[32768];   // AH 16K | AL 16K
    int mt = blockIdx.x, nt = blockIdx.y;
    int tid = threadIdx.x;
    int warp = tid >> 5, lane = tid & 31;
    int warpM = warp & 3, warpN = warp >> 2;
    uint32_t sb = smem_u32(xs);

    int arow = tid >> 2, aq = tid & 3;
    int b0 = arow * 128 + aq * 32;
    int s0 = b0 ^ ((b0 >> 3) & 0x70);
    int s1 = (b0 + 16) ^ (((b0 + 16) >> 3) & 0x70);
    const float* xrow = X + (size_t)(mt * 128 + arow) * NE;

    float acc[2][8][4];
#pragma unroll
    for (int m = 0; m < 2; m++)
#pragma unroll
        for (int f = 0; f < 8; f++)
#pragma unroll
            for (int i = 0; i < 4; i++) acc[m][f][i] = 0.0f;

    int r0 = warpM * 32 + (lane & 15);
    int r1 = r0 + 16;
    int segb = ((lane >> 4) & 1) * 16;
    int lanepart = (lane >> 2) * 16 + (lane & 3) * 4;
    int nbase = (nt * 256 + warpN * 64) * 16 + lanepart;

    float v[16];
    {
        int k0 = aq * 16;
#pragma unroll
        for (int i = 0; i < 4; i++) *(float4*)&v[i * 4] = *(const float4*)(xrow + k0 + i * 4);
    }

    for (int kc = 0; kc < 5; kc++) {
        __syncthreads();
        {
            uint4 ph, pl;
            uint32_t* hp = (uint32_t*)&ph;
            uint32_t* lp = (uint32_t*)&pl;
#pragma unroll
            for (int p = 0; p < 4; p++) {
                float a = v[2 * p], b = v[2 * p + 1];
                __half ha = __float2half_rn(a), hb = __float2half_rn(b);
                hp[p] = packh2(a, b);
                lp[p] = packh2(a - __half2float(ha), b - __half2float(hb));
            }
            *(uint4*)(xs + s0) = ph;
            *(uint4*)(xs + 16384 + s0) = pl;
#pragma unroll
            for (int p = 0; p < 4; p++) {
                float a = v[8 + 2 * p], b = v[8 + 2 * p + 1];
                __half ha = __float2half_rn(a), hb = __float2half_rn(b);
                hp[p] = packh2(a, b);
                lp[p] = packh2(a - __half2float(ha), b - __half2float(hb));
            }
            *(uint4*)(xs + s1) = ph;
            *(uint4*)(xs + 16384 + s1) = pl;
        }
        __syncthreads();
        if (kc < 4) {
            int k0 = (kc + 1) * 64 + aq * 16;
            if (k0 + 15 < NE) {
#pragma unroll
                for (int i = 0; i < 4; i++) *(float4*)&v[i * 4] = *(const float4*)(xrow + k0 + i * 4);
            } else {
#pragma unroll
                for (int i = 0; i < 16; i++) v[i] = (k0 + i < NE) ? xrow[k0 + i] : 0.0f;
            }
        }
#pragma unroll
        for (int s = 0; s < 4; s++) {
            uint32_t ah0[4], ah1[4], al0[4], al1[4];
            {
                int o = r0 * 128 + s * 32 + segb; o ^= ((o >> 3) & 0x70);
                ldsm4(ah0, sb + o); ldsm4(al0, sb + 16384 + o);
            }
            {
                int o = r1 * 128 + s * 32 + segb; o ^= ((o >> 3) & 0x70);
                ldsm4(ah1, sb + o); ldsm4(al1, sb + 16384 + o);
            }
            const __half* pb = g_Wp + (size_t)(kc * 4 + s) * 16384 + nbase;
#pragma unroll
            for (int f = 0; f < 8; f++) {
                uint2 bh = *(const uint2*)(pb + f * 128);
                MMA(acc[0][f], ah0, bh.x, bh.y);
                MMA(acc[1][f], ah1, bh.x, bh.y);
                MMA(acc[0][f], al0, bh.x, bh.y);
                MMA(acc[1][f], al1, bh.x, bh.y);
            }
        }
    }

    int rg = lane >> 2, c2 = (lane & 3) * 2;
#pragma unroll
    for (int f = 0; f < 8; f++) {
        int col = nt * 256 + warpN * 64 + f * 8 + c2;
        float2 bb = *(const float2*)&g_bias[col];
#pragma unroll
        for (int m = 0; m < 2; m++) {
            int row = mt * 128 + warpM * 32 + m * 16 + rg;
            *(uint32_t*)&g_x[(size_t)row * XN + col] =
                packh2(acc[m][f][0] + bb.x, acc[m][f][1] + bb.y);
            *(uint32_t*)&g_x[(size_t)(row + 8) * XN + col] =
                packh2(acc[m][f][2] + bb.x, acc[m][f][3] + bb.y);
        }
    }
}

// ---------------- winner/compact/prep: ALL steps in 3 launches ----------------
__global__ void k_winner_all(const int* __restrict__ td) {
    int t = blockIdx.y;
    int idx = blockIdx.x * blockDim.x + threadIdx.x;
    int b = idx >> 11, s = idx & 2047;
    int d = td[b * (NT * NS) + t * NS + s];
    atomicMax(&g_win[t * NROWS + (b << 11) + d], s);
}

__global__ void k_compact_all(const int* __restrict__ td) {
    __shared__ int scnt, sbase;
    int t = blockIdx.y;
    int tid = threadIdx.x;
    if (tid == 0) scnt = 0;
    __syncthreads();
    int idx = blockIdx.x * blockDim.x + tid;
    int b = idx >> 11, s = idx & 2047;
    int d = td[b * (NT * NS) + t * NS + s];
    int dd = (b << 11) + d;
    bool win = (d != 0) && (g_win[t * NROWS + dd] == s);
    int pos = 0;
    if (win) pos = atomicAdd(&scnt, 1);
    __syncthreads();
    if (tid == 0) sbase = atomicAdd(&g_cnt[t], scnt);
    __syncthreads();
    if (win) {
        g_work[t * NROWS + sbase + pos] = idx;
        atomicOr(&g_wmask[dd], 1u << t);
    }
}

// after wmask is complete: resolve all per-row offsets once
__global__ void k_prep_all(const int* __restrict__ td, const int* __restrict__ tl,
                           const int* __restrict__ tr) {
    int t = blockIdx.y;
    int i = blockIdx.x * blockDim.x + threadIdx.x;
    if (i >= g_cnt[t]) return;
    int idx = g_work[t * NROWS + i];
    int b = idx >> 11, s = idx & 2047;
    int tb = b * (NT * NS) + t * NS + s;
    int brow = b << 11;
    int rl = brow + tl[tb];
    int rr = brow + tr[tb];
    int rd = brow + td[tb];
    uint32_t below = (1u << t) - 1u;
    int nl = __popc(g_wmask[rl] & below);
    int nr = __popc(g_wmask[rr] & below);
    int nd = __popc(g_wmask[rd] & below);
    // readers use buf[(n+1)&1]; writer uses buf[n&1] -> never collide
    g_meta[t * NROWS + i] = make_int4(
        ((nl + 1) & 1) * HCNT + (rl << 8),
        ((nr + 1) & 1) * HCNT + (rr << 8),
        (nd & 1) * HCNT + (rd << 8),
        idx);
}

// ---------------- step 0: h==0 -> pure elementwise from x ----------------
__global__ void k_step0(__half* __restrict__ hhw, __half* __restrict__ hlw,
                        float* __restrict__ ccw) {
    int count = g_cnt[0];
    int tid = threadIdx.x;
    int m = blockIdx.x * 8 + (tid >> 5);
    if (m >= count) return;
    int lane = tid & 31;
    int4 v = g_meta[m];          // t = 0
    int eo = v.z + lane * 8;     // offD (buffer 0 at t=0)
    const uint4* xp = (const uint4*)(g_x + (size_t)v.w * XN + (size_t)lane * 32);
    uint4 xr[4];
#pragma unroll
    for (int i = 0; i < 4; i++) xr[i] = xp[i];
    const __half2* xh = (const __half2*)xr;
    float ho[8], co[8];
#pragma unroll
    for (int u = 0; u < 8; u++) {
        float2 p0 = __half22float2(xh[2 * u]);      // x_i, x_o
        float2 p1 = __half22float2(xh[2 * u + 1]);  // x_u, x_f
        float gi = sigm(p0.x);
        float go = sigm(p0.y);
        float gu = tanhf(p1.x);
        float cn = gi * gu;                          // c_l = c_r = 0
        ho[u] = go * tanhf(cn);
        co[u] = cn;
    }
    uint32_t hw[4], lw[4];
#pragma unroll
    for (int p = 0; p < 4; p++) {
        float v0 = ho[2 * p], v1 = ho[2 * p + 1];
        __half a = __float2half_rn(v0);
        __half bb = __float2half_rn(v1);
        hw[p] = packh2(v0, v1);
        lw[p] = packh2(v0 - __half2float(a), v1 - __half2float(bb));
    }
    *(uint4*)(hhw + eo) = make_uint4(hw[0], hw[1], hw[2], hw[3]);
    *(uint4*)(hlw + eo) = make_uint4(lw[0], lw[1], lw[2], lw[3]);
    *(float4*)(ccw + eo) = *(float4*)&co[0];
    *(float4*)(ccw + eo + 4) = *(float4*)&co[4];
}

// ---------------- fused step: fp16 mma, 3-buf pipeline, occupancy 2 ----------
// grid = (8, 512), 512 threads (16 warps: 4M x 4N), 2 CTAs/SM
__global__ __launch_bounds__(512, 2) void k_step_mma(
    int t,
    const __half* __restrict__ hh, const __half* __restrict__ hl,
    const float* __restrict__ cc,
    __half* __restrict__ hhw, __half* __restrict__ hlw, float* __restrict__ ccw)
{
    extern __shared__ char smem[];
    int tid = threadIdx.x;
    int count = g_cnt[t];
    int mt = blockIdx.y;
    if (mt * BM >= count) return;
    int nt = blockIdx.x;

    int* sL = (int*)(smem + OFF_IDX);
    int* sR = (int*)(smem + OFF_IDX + 512);
    int* sD = (int*)(smem + OFF_IDX + 1024);
    int* sRow = (int*)(smem + OFF_IDX + 1536);

    if (tid < BM) {
        int m = mt * BM + tid;
        int4 v = (m < count) ? g_meta[t * NROWS + m] : make_int4(0, 0, -1, 0);
        sL[tid] = v.x; sR[tid] = v.y; sD[tid] = v.z; sRow[tid] = v.w;
    }
    __syncthreads();

    uint32_t sb = smem_u32(smem);
    int arow = tid >> 2, aq = tid & 3;
    int offL = sL[arow], offR = sR[arow];
    int b0 = arow * 128 + aq * 32;
    int b1 = b0 + 16;
    int s0 = b0 ^ ((b0 >> 3) & 0x70);
    int s1 = b1 ^ ((b1 >> 3) & 0x70);
    const uint32_t offA[3] = {OFF_A0, OFF_A1, OFF_A2};

    // prologue: group 0 = chunk 0; group 1 = chunk 1
    {
        const __half* ph = hh + offL + aq * 16;
        cp16(sb + OFF_A0 + s0, ph);  cp16(sb + OFF_A0 + s1, ph + 8);
        CP_COMMIT;
        const __half* p1 = hh + offL + 64 + aq * 16;
        cp16(sb + OFF_A1 + s0, p1);  cp16(sb + OFF_A1 + s1, p1 + 8);
        CP_COMMIT;
    }

    int warp = tid >> 5, lane = tid & 31;
    int warpM = warp & 3, warpN = warp >> 2;

    float acc[2][5][4];
#pragma unroll
    for (int m = 0; m < 2; m++)
#pragma unroll
        for (int f = 0; f < 5; f++)
#pragma unroll
            for (int i = 0; i < 4; i++) acc[m][f][i] = 0.0f;

    int r0 = warpM * 32 + (lane & 15);
    int r1 = r0 + 16;
    int segb = ((lane >> 4) & 1) * 16;

    int tilesel = nt * 2 + (warpN >> 1);
    const __half* pbh = g_UBH + (size_t)tilesel * UB_NT_STRIDE;
    int lanepart = (lane >> 2) * 16 + (lane & 3) * 4;
    int warppart = (warpN & 1) * 640;

    for (int kc = 0; kc < 8; kc++) {
        if (kc < 7) { CP_WAIT1; } else { CP_WAIT0; }
        __syncthreads();          // chunk kc visible to ALL warps; buf[(kc+2)%3] free
        if (kc < 6) {
            int kcn = kc + 2;
            int off = (kcn < 4) ? offL : offR;
            int k0 = (kcn & 3) * 64;
            const __half* ph = hh + off + k0 + aq * 16;
            uint32_t ab = sb + offA[kcn % 3];
            cp16(ab + s0, ph);  cp16(ab + s1, ph + 8);
            CP_COMMIT;
        }
        uint32_t abh = sb + offA[kc % 3];
#pragma unroll
        for (int s = 0; s < 4; s++) {
            uint32_t ah0[4], ah1[4];
            {
                int o = r0 * 128 + s * 32 + segb; o ^= ((o >> 3) & 0x70);
                ldsm4(ah0, abh + o);
            }
            {
                int o = r1 * 128 + s * 32 + segb; o ^= ((o >> 3) & 0x70);
                ldsm4(ah1, abh + o);
            }
            int be = (kc * 4 + s) * 1280 + warppart + lanepart;
#pragma unroll
            for (int f = 0; f < 5; f++) {
                uint2 bh = *(const uint2*)(pbh + be + f * 128);
                MMA(acc[0][f], ah0, bh.x, bh.y);
                MMA(acc[1][f], ah1, bh.x, bh.y);
            }
        }
    }
    __syncthreads();    // all MMA reads done before stage-region overwrite

    // epilogue: transpose acc through smem, fuse activations (direct LDG x/c)
    float* stg = (float*)(smem + OFF_STAGE);
    {
        int rg = lane >> 2, cl = 2 * (lane & 3);
#pragma unroll
        for (int m = 0; m < 2; m++) {
#pragma unroll
            for (int f = 0; f < 5; f++) {
                int row = warpM * 32 + m * 16 + rg;
                int col = warpN * 40 + f * 8 + cl;
                *(float2*)&stg[row * 164 + col] = make_float2(acc[m][f][0], acc[m][f][1]);
                *(float2*)&stg[(row + 8) * 164 + col] = make_float2(acc[m][f][2], acc[m][f][3]);
            }
        }
    }
    __syncthreads();

    {
        int row = arow, ug = aq;
        int j0 = nt * 32;
        int od = sD[row];
        const uint4* xp = (const uint4*)(g_x + (size_t)sRow[row] * XN + (size_t)(j0 + ug * 8) * 4);
        const float* clp = cc + offL + j0 + ug * 8;
        const float* crp = cc + offR + j0 + ug * 8;
        uint4 xr[4];
#pragma unroll
        for (int i = 0; i < 4; i++) xr[i] = xp[i];
        const __half2* xh = (const __half2*)xr;
        float clv[8], crv[8], ho[8], co[8];
        *(float4*)&clv[0] = *(const float4*)clp;
        *(float4*)&clv[4] = *(const float4*)(clp + 4);
        *(float4*)&crv[0] = *(const float4*)crp;
        *(float4*)&crv[4] = *(const float4*)(crp + 4);
#pragma unroll
        for (int u = 0; u < 8; u++) {
            int col = (ug * 8 + u) * 5;
            float a_i  = stg[row * 164 + col + 0];
            float a_o  = stg[row * 164 + col + 1];
            float a_u  = stg[row * 164 + col + 2];
            float a_fl = stg[row * 164 + col + 3];
            float a_fr = stg[row * 164 + col + 4];
            float2 p0 = __half22float2(xh[2 * u]);
            float2 p1 = __half22float2(xh[2 * u + 1]);
            float gi = sigm(a_i + p0.x);
            float go = sigm(a_o + p0.y);
            float gu = tanhf(a_u + p1.x);
            float fl = sigm(a_fl + p1.y);
            float fr = sigm(a_fr + p1.y);
            float cnew = gi * gu + fl * clv[u] + fr * crv[u];
            ho[u] = go * tanhf(cnew);
            co[u] = cnew;
        }
        if (od >= 0) {
            uint32_t hw[4], lw[4];
#pragma unroll
            for (int p = 0; p < 4; p++) {
                float v0 = ho[2 * p], v1 = ho[2 * p + 1];
                __half a = __float2half_rn(v0);
                __half b = __float2half_rn(v1);
                hw[p] = packh2(v0, v1);
                lw[p] = packh2(v0 - __half2float(a), v1 - __half2float(b));
            }
            int eo = od + j0 + ug * 8;
            *(uint4*)(hhw + eo) = make_uint4(hw[0], hw[1], hw[2], hw[3]);
            *(uint4*)(hlw + eo) = make_uint4(lw[0], lw[1], lw[2], lw[3]);
            *(float4*)(ccw + eo) = *(float4*)&co[0];
            *(float4*)(ccw + eo + 4) = *(float4*)&co[4];
        }
    }
}

// ---------------- final output assembly ----------------
__global__ void k_output(const __half* __restrict__ hh, const __half* __restrict__ hl,
                         const float* __restrict__ cc,
                         float* __restrict__ oh, float* __restrict__ oc) {
    int tid = threadIdx.x;
    int row = blockIdx.x * 16 + (tid >> 5);
    int cg = (tid & 31) * 8;
    size_t oo = ((size_t)row << 8) + cg;
    uint32_t m = g_wmask[row];
    if (m == 0u) {
        float4 z = make_float4(0.f, 0.f, 0.f, 0.f);
        *(float4*)(oh + oo) = z; *(float4*)(oh + oo + 4) = z;
        *(float4*)(oc + oo) = z; *(float4*)(oc + oo + 4) = z;
        return;
    }
    int nw = __popc(m);
    size_t so = (size_t)(((nw - 1) & 1)) * HCNT + oo;
    uint4 rh = *(const uint4*)(hh + so);
    uint4 rl = *(const uint4*)(hl + so);
    const __half2* ph = (const __half2*)&rh;
    const __half2* pl = (const __half2*)&rl;
#pragma unroll
    for (int i = 0; i < 4; i++) {
        float2 a = __half22float2(ph[i]);
        float2 b = __half22float2(pl[i]);
        *(float2*)(oh + oo + 2 * i) = make_float2(a.x + b.x, a.y + b.y);
    }
    *(float4*)(oc + oo) = *(const float4*)(cc + so);
    *(float4*)(oc + oo + 4) = *(const float4*)(cc + so + 4);
}

// ---------------- h_root ----------------
__global__ void k_root(const int* __restrict__ td, const float* __restrict__ out_h,
                       float* __restrict__ out_root) {
    __shared__ int red[256];
    int b = blockIdx.x, tid = threadIdx.x;
    int v = 0;
    for (int s = tid; s < NS; s += 256) v = max(v, td[b * (NT * NS) + (NT - 1) * NS + s]);
    red[tid] = v;
    __syncthreads();
    for (int off = 128; off > 0; off >>= 1) {
        if (tid < off) red[tid] = max(red[tid], red[tid + off]);
        __syncthreads();
    }
    int root = red[0];
    out_root[b * NH + tid] = out_h[(((size_t)(b << 11)) + root) * NH + tid];
}

// ---------------- host launcher (graph-capturable) ----------------
extern "C" void kernel_launch(void* const* d_in, const int* in_sizes, int n_in,
                              void* d_out, int out_size) {
    const float* X     = (const float*)d_in[0];
    const int*   td    = (const int*)d_in[1];
    const int*   tr    = (const int*)d_in[2];
    const int*   tl    = (const int*)d_in[3];
    const float* W_iou = (const float*)d_in[4];
    const float* b_iou = (const float*)d_in[5];
    const float* U_l   = (const float*)d_in[6];
    const float* U_r   = (const float*)d_in[7];
    const float* W_f   = (const float*)d_in[8];
    const float* b_f   = (const float*)d_in[9];
    const float* F_ll  = (const float*)d_in[10];
    const float* F_lr  = (const float*)d_in[11];
    const float* F_rl  = (const float*)d_in[12];
    const float* F_rr  = (const float*)d_in[13];

    float* out      = (float*)d_out;
    float* out_h    = out;
    float* out_c    = out + (size_t)HCNT;
    float* out_root = out + 2 * (size_t)HCNT;

    __half *hhb = nullptr, *hlb = nullptr;
    float* cb = nullptr;
    cudaGetSymbolAddress((void**)&hhb, g_hh);
    cudaGetSymbolAddress((void**)&hlb, g_hl);
    cudaGetSymbolAddress((void**)&cb, g_c);

    static int attr_done = 0;
    if (!attr_done) {
        cudaFuncSetAttribute(k_step_mma, cudaFuncAttributeMaxDynamicSharedMemorySize, SMEM_DYN);
        attr_done = 1;
    }

    k_init<<<4096, 256>>>();
    k_pack_wp<<<(WP_TOTAL + 255) / 256, 256>>>(W_iou, b_iou, W_f, b_f);
    k_pack_ub<<<(UB_TOTAL + 255) / 256, 256>>>(U_l, U_r, F_ll, F_lr, F_rl, F_rr);
    k_winner_all<<<dim3(NROWS / 256, NT), 256>>>(td);
    k_compact_all<<<dim3(NROWS / 256, NT), 256>>>(td);
    k_prep_all<<<dim3(NROWS / 256, NT), 256>>>(td, tl, tr);
    k_xgemm_mma<<<dim3(512, 4), 512>>>(X);

    k_step0<<<NROWS / 8, 256>>>(hhb, hlb, cb);
    for (int t = 1; t < NT; t++) {
        k_step_mma<<<dim3(NTL, 512), 512, SMEM_DYN>>>(
            t, hhb, hlb, cb, hhb, hlb, cb);
    }
    k_output<<<4096, 512>>>(hhb, hlb, cb, out_h, out_c);
    k_root<<<NB, 256>>>(td, out_h, out_root);
}